// round 5
// baseline (speedup 1.0000x reference)
#include <cuda_runtime.h>
#include <cstdint>

#define BB 2
#define SS 2048
#define DD 1024
#define HH 16
#define HDD 64

// ---------------- scratch (allocation-free: __device__ globals) ----------------
__device__ float g_q[BB * SS * HH * HDD];      // 16 MB
__device__ float g_k[BB * SS * HH * HDD];      // 16 MB
__device__ float g_v[BB * SS * HH * HDD];      // 16 MB
__device__ float g_ctx[BB * SS * HH * HDD];    // 16 MB
__device__ float g_bias[HH * SS * SS];         // 256 MB

// ---------------- generic fp32 GEMM: C[M,N] = A[M,K] * B[K,N] + bias[N] --------
// BM=128, BN=64, BK=16, 256 threads, 8x4 per-thread microtile
#define BM 128
#define BN 64
#define BK 16

__global__ void __launch_bounds__(256)
gemm_bias_kernel(const float* __restrict__ A, const float* __restrict__ Bm,
                 const float* __restrict__ bias, float* __restrict__ C,
                 int M, int N, int K)
{
    __shared__ float AsT[BK][BM + 4];   // [k][m]
    __shared__ float Bs[BK][BN];        // [k][n]

    const int tid = threadIdx.x;
    const int tx = tid & 15;            // n group (4 cols)
    const int ty = tid >> 4;            // m group (8 rows)
    const int m0 = blockIdx.y * BM;
    const int n0 = blockIdx.x * BN;

    float acc[8][4];
#pragma unroll
    for (int i = 0; i < 8; ++i)
#pragma unroll
        for (int j = 0; j < 4; ++j) acc[i][j] = 0.f;

    for (int k0 = 0; k0 < K; k0 += BK) {
        // load A tile (128 x 16) as float4, store transposed
#pragma unroll
        for (int it = 0; it < 2; ++it) {
            int idx = tid + it * 256;          // 512 float4s
            int r   = idx >> 2;                // 0..127
            int kk  = (idx & 3) * 4;
            float4 v = *(const float4*)(A + (size_t)(m0 + r) * K + k0 + kk);
            AsT[kk + 0][r] = v.x;
            AsT[kk + 1][r] = v.y;
            AsT[kk + 2][r] = v.z;
            AsT[kk + 3][r] = v.w;
        }
        // load B tile (16 x 64)
        {
            int r  = tid >> 4;                 // 0..15
            int c4 = (tid & 15) * 4;
            *(float4*)&Bs[r][c4] = *(const float4*)(Bm + (size_t)(k0 + r) * N + n0 + c4);
        }
        __syncthreads();

#pragma unroll
        for (int kk = 0; kk < BK; ++kk) {
            float4 a0 = *(float4*)&AsT[kk][ty * 8];
            float4 a1 = *(float4*)&AsT[kk][ty * 8 + 4];
            float4 b4 = *(float4*)&Bs[kk][tx * 4];
            float av[8] = {a0.x, a0.y, a0.z, a0.w, a1.x, a1.y, a1.z, a1.w};
            float bv[4] = {b4.x, b4.y, b4.z, b4.w};
#pragma unroll
            for (int i = 0; i < 8; ++i)
#pragma unroll
                for (int j = 0; j < 4; ++j) acc[i][j] += av[i] * bv[j];
        }
        __syncthreads();
    }

    float4 bb = *(const float4*)(bias + n0 + tx * 4);
#pragma unroll
    for (int i = 0; i < 8; ++i) {
        float4 o;
        o.x = acc[i][0] + bb.x;
        o.y = acc[i][1] + bb.y;
        o.z = acc[i][2] + bb.z;
        o.w = acc[i][3] + bb.w;
        *(float4*)(C + (size_t)(m0 + ty * 8 + i) * N + n0 + tx * 4) = o;
    }
}

// ---------------- relative-position bias: bias[h][q][k] = sum_c rel[c][h]*Qb[q][k][c]
__global__ void __launch_bounds__(256)
bias_kernel(const float* __restrict__ Qb, const float* __restrict__ rel,
            float* __restrict__ bias)
{
    __shared__ float srel[128];  // [c*16 + h]
    if (threadIdx.x < 128) srel[threadIdx.x] = rel[threadIdx.x];
    __syncthreads();

    size_t p = (size_t)blockIdx.x * blockDim.x + threadIdx.x;  // 0 .. S*S-1
    float qb[8];
    *(float4*)qb       = *(const float4*)(Qb + p * 8);
    *(float4*)(qb + 4) = *(const float4*)(Qb + p * 8 + 4);

#pragma unroll
    for (int h = 0; h < 16; ++h) {
        float a = 0.f;
#pragma unroll
        for (int c = 0; c < 8; ++c) a += srel[c * 16 + h] * qb[c];
        bias[(size_t)h * SS * SS + p] = a;
    }
}

// ---------------- LayerNorm over HD=64 for q and k (one warp per vector) -------
__global__ void __launch_bounds__(256)
qk_ln_kernel(float* __restrict__ q, float* __restrict__ k,
             const float* __restrict__ qs, const float* __restrict__ ks)
{
    int gwarp = (blockIdx.x * blockDim.x + threadIdx.x) >> 5;
    int lane = threadIdx.x & 31;
    // 65536 vectors per tensor (B*S*H), 2 tensors
    int tensor = gwarp >> 16;
    int vec = gwarp & 65535;
    float* base = (tensor == 0 ? q : k) + (size_t)vec * 64;
    const float* sc = (tensor == 0 ? qs : ks);

    float2 v = *(float2*)(base + lane * 2);
    float s = v.x + v.y;
    float s2 = v.x * v.x + v.y * v.y;
#pragma unroll
    for (int d = 16; d > 0; d >>= 1) {
        s  += __shfl_xor_sync(0xffffffffu, s, d);
        s2 += __shfl_xor_sync(0xffffffffu, s2, d);
    }
    float mu = s * (1.f / 64.f);
    float var = s2 * (1.f / 64.f) - mu * mu;
    float r = rsqrtf(var + 1e-6f);
    float2 o;
    o.x = (v.x - mu) * r * sc[lane * 2];
    o.y = (v.y - mu) * r * sc[lane * 2 + 1];
    *(float2*)(base + lane * 2) = o;
}

// ---------------- flash attention: CTA = (q_tile=64, h, b), 64-wide K tiles ----
__global__ void __launch_bounds__(256)
attn_kernel(const float* __restrict__ gq, const float* __restrict__ gk,
            const float* __restrict__ gv, const float* __restrict__ bias,
            float* __restrict__ gctx)
{
    extern __shared__ float smem_f[];
    float (*sQT)[68] = (float(*)[68])(smem_f);                 // [hd][q]
    float (*sKT)[68] = (float(*)[68])(smem_f + 64 * 68);       // [hd][k]
    float (*sV)[68]  = (float(*)[68])(smem_f + 2 * 64 * 68);   // [k][hd]
    float (*sP)[68]  = (float(*)[68])(smem_f + 3 * 64 * 68);   // [q][k]

    const int tid = threadIdx.x;
    const int tx = tid & 15;     // 4-wide col group (k or hd)
    const int ty = tid >> 4;     // 4-wide row group (q)
    const int q0 = blockIdx.x * 64;
    const int h  = blockIdx.y;
    const int b  = blockIdx.z;
    const float scale = 0.125f;  // 1/sqrt(64)

    // load Q tile transposed, pre-scaled
#pragma unroll
    for (int it = 0; it < 4; ++it) {
        int idx = tid + it * 256;          // 1024 float4s
        int r  = idx >> 4;                 // q row
        int c4 = (idx & 15) * 4;           // hd
        size_t goff = ((((size_t)b * SS + q0 + r) * HH + h) << 6) + c4;
        float4 v = *(const float4*)(gq + goff);
        sQT[c4 + 0][r] = v.x * scale;
        sQT[c4 + 1][r] = v.y * scale;
        sQT[c4 + 2][r] = v.z * scale;
        sQT[c4 + 3][r] = v.w * scale;
    }

    float m_i[4], l_i[4], o[4][4];
#pragma unroll
    for (int i = 0; i < 4; ++i) {
        m_i[i] = -1e30f;
        l_i[i] = 0.f;
#pragma unroll
        for (int j = 0; j < 4; ++j) o[i][j] = 0.f;
    }
    __syncthreads();

    for (int k0 = 0; k0 < SS; k0 += 64) {
        // load K tile (transposed) and V tile
#pragma unroll
        for (int it = 0; it < 4; ++it) {
            int idx = tid + it * 256;
            int r  = idx >> 4;             // k row
            int c4 = (idx & 15) * 4;       // hd
            size_t goff = ((((size_t)b * SS + k0 + r) * HH + h) << 6) + c4;
            float4 kv = *(const float4*)(gk + goff);
            sKT[c4 + 0][r] = kv.x;
            sKT[c4 + 1][r] = kv.y;
            sKT[c4 + 2][r] = kv.z;
            sKT[c4 + 3][r] = kv.w;
            *(float4*)&sV[r][c4] = *(const float4*)(gv + goff);
        }
        __syncthreads();

        // scores: init with bias, accumulate (q*scale) . k
        float s[4][4];
#pragma unroll
        for (int i = 0; i < 4; ++i) {
            float4 bb = *(const float4*)(bias + ((size_t)h * SS + q0 + ty * 4 + i) * SS
                                               + k0 + tx * 4);
            s[i][0] = bb.x; s[i][1] = bb.y; s[i][2] = bb.z; s[i][3] = bb.w;
        }
#pragma unroll 8
        for (int hd = 0; hd < 64; ++hd) {
            float4 a4 = *(float4*)&sQT[hd][ty * 4];
            float4 b4 = *(float4*)&sKT[hd][tx * 4];
            float av[4] = {a4.x, a4.y, a4.z, a4.w};
            float bv[4] = {b4.x, b4.y, b4.z, b4.w};
#pragma unroll
            for (int i = 0; i < 4; ++i)
#pragma unroll
                for (int j = 0; j < 4; ++j) s[i][j] += av[i] * bv[j];
        }

        // online softmax (row groups = 16 lanes sharing ty; xor dist < 16 stays in group)
        float tm[4], ps[4];
#pragma unroll
        for (int i = 0; i < 4; ++i)
            tm[i] = fmaxf(fmaxf(s[i][0], s[i][1]), fmaxf(s[i][2], s[i][3]));
#pragma unroll
        for (int d = 1; d < 16; d <<= 1)
#pragma unroll
            for (int i = 0; i < 4; ++i)
                tm[i] = fmaxf(tm[i], __shfl_xor_sync(0xffffffffu, tm[i], d));
#pragma unroll
        for (int i = 0; i < 4; ++i) {
            float mn = fmaxf(m_i[i], tm[i]);
            float alpha = __expf(m_i[i] - mn);
            m_i[i] = mn;
            float p0 = __expf(s[i][0] - mn);
            float p1 = __expf(s[i][1] - mn);
            float p2 = __expf(s[i][2] - mn);
            float p3 = __expf(s[i][3] - mn);
            s[i][0] = p0; s[i][1] = p1; s[i][2] = p2; s[i][3] = p3;
            ps[i] = (p0 + p1) + (p2 + p3);
            l_i[i] *= alpha;
#pragma unroll
            for (int j = 0; j < 4; ++j) o[i][j] *= alpha;
        }
#pragma unroll
        for (int d = 1; d < 16; d <<= 1)
#pragma unroll
            for (int i = 0; i < 4; ++i)
                ps[i] += __shfl_xor_sync(0xffffffffu, ps[i], d);
#pragma unroll
        for (int i = 0; i < 4; ++i) l_i[i] += ps[i];

        // stage P
        __syncthreads();  // everyone done reading sKT / computing scores
#pragma unroll
        for (int i = 0; i < 4; ++i) {
            float4 pv;
            pv.x = s[i][0]; pv.y = s[i][1]; pv.z = s[i][2]; pv.w = s[i][3];
            *(float4*)&sP[ty * 4 + i][tx * 4] = pv;
        }
        __syncthreads();

        // PV: o[q][hd] += P[q][kk] * V[kk][hd]
#pragma unroll 8
        for (int kk = 0; kk < 64; ++kk) {
            float4 v4 = *(float4*)&sV[kk][tx * 4];
            float vv[4] = {v4.x, v4.y, v4.z, v4.w};
            float pv[4];
#pragma unroll
            for (int i = 0; i < 4; ++i) pv[i] = sP[ty * 4 + i][kk];  // broadcast
#pragma unroll
            for (int i = 0; i < 4; ++i)
#pragma unroll
                for (int j = 0; j < 4; ++j) o[i][j] += pv[i] * vv[j];
        }
        __syncthreads();  // before next tile overwrites sKT/sV/sP
    }

    // epilogue: normalize and store ctx
#pragma unroll
    for (int i = 0; i < 4; ++i) {
        float inv = 1.f / l_i[i];
        size_t off = ((((size_t)b * SS + q0 + ty * 4 + i) * HH + h) << 6) + tx * 4;
        float4 ov;
        ov.x = o[i][0] * inv; ov.y = o[i][1] * inv;
        ov.z = o[i][2] * inv; ov.w = o[i][3] * inv;
        *(float4*)(gctx + off) = ov;
    }
}

// ---------------- launcher ------------------------------------------------------
extern "C" void kernel_launch(void* const* d_in, const int* in_sizes, int n_in,
                              void* d_out, int out_size)
{
    (void)in_sizes; (void)n_in; (void)out_size;
    const float* x   = (const float*)d_in[0];
    const float* Qb  = (const float*)d_in[1];
    const float* Wq  = (const float*)d_in[2];
    const float* bq  = (const float*)d_in[3];
    const float* Wk  = (const float*)d_in[4];
    const float* bk  = (const float*)d_in[5];
    const float* Wv  = (const float*)d_in[6];
    const float* bv  = (const float*)d_in[7];
    const float* qs  = (const float*)d_in[8];
    const float* ks  = (const float*)d_in[9];
    const float* rel = (const float*)d_in[10];
    const float* Wo  = (const float*)d_in[11];
    const float* bo  = (const float*)d_in[12];
    float* out = (float*)d_out;

    float *pq, *pk, *pv, *pctx, *pbias;
    cudaGetSymbolAddress((void**)&pq,    g_q);
    cudaGetSymbolAddress((void**)&pk,    g_k);
    cudaGetSymbolAddress((void**)&pv,    g_v);
    cudaGetSymbolAddress((void**)&pctx,  g_ctx);
    cudaGetSymbolAddress((void**)&pbias, g_bias);

    const int M = BB * SS;   // 4096
    const int N = DD;        // 1024
    const int K = DD;        // 1024
    dim3 gg(N / BN, M / BM); // (16, 32)

    // QKV projections
    gemm_bias_kernel<<<gg, 256>>>(x, Wq, bq, pq, M, N, K);
    gemm_bias_kernel<<<gg, 256>>>(x, Wk, bk, pk, M, N, K);
    gemm_bias_kernel<<<gg, 256>>>(x, Wv, bv, pv, M, N, K);

    // relative-position bias (independent of qkv)
    bias_kernel<<<(SS * SS) / 256, 256>>>(Qb, rel, pbias);

    // QK layernorm
    qk_ln_kernel<<<(2 * BB * SS * HH * 32) / 256, 256>>>(pq, pk, qs, ks);

    // attention
    static const int ATTN_SMEM = 4 * 64 * 68 * (int)sizeof(float);  // 69632 B
    cudaFuncSetAttribute(attn_kernel, cudaFuncAttributeMaxDynamicSharedMemorySize,
                         ATTN_SMEM);
    attn_kernel<<<dim3(SS / 64, HH, BB), 256, ATTN_SMEM>>>(pq, pk, pv, pbias, pctx);

    // output projection
    gemm_bias_kernel<<<gg, 256>>>(pctx, Wo, bo, out, M, N, K);
}

// round 6
// speedup vs baseline: 2.1633x; 2.1633x over previous
#include <cuda_runtime.h>
#include <cuda_fp16.h>
#include <cstdint>

#define BBATCH 2
#define SSEQ 2048
#define DDIM 1024
#define HHEADS 16
#define MROWS (BBATCH * SSEQ)
#define LOG2E 1.4426950408889634f

// ------------------------------ scratch ---------------------------------------
__device__ __align__(16) __half g_xh[MROWS * DDIM];
__device__ __align__(16) __half g_xl[MROWS * DDIM];
__device__ __align__(16) __half g_wth[4 * DDIM * DDIM];
__device__ __align__(16) __half g_wtl[4 * DDIM * DDIM];
__device__ __align__(16) float  g_q[MROWS * DDIM];
__device__ __align__(16) float  g_k[MROWS * DDIM];
__device__ __align__(16) float  g_v[MROWS * DDIM];
__device__ __align__(16) __half g_qh[MROWS * DDIM];
__device__ __align__(16) __half g_ql[MROWS * DDIM];
__device__ __align__(16) __half g_kh[MROWS * DDIM];
__device__ __align__(16) __half g_kl[MROWS * DDIM];
__device__ __align__(16) __half g_vh[MROWS * DDIM];
__device__ __align__(16) __half g_vl[MROWS * DDIM];
__device__ __align__(16) __half g_biasH[(size_t)HHEADS * SSEQ * SSEQ];
__device__ __align__(16) __half g_ch[MROWS * DDIM];
__device__ __align__(16) __half g_cl[MROWS * DDIM];

// ------------------------------ helpers ---------------------------------------
__device__ __forceinline__ void ldsm4(unsigned* r, const void* p) {
    unsigned a = (unsigned)__cvta_generic_to_shared(p);
    asm volatile("ldmatrix.sync.aligned.m8n8.x4.shared.b16 {%0,%1,%2,%3}, [%4];"
                 : "=r"(r[0]), "=r"(r[1]), "=r"(r[2]), "=r"(r[3]) : "r"(a));
}
__device__ __forceinline__ void ldsm4t(unsigned* r, const void* p) {
    unsigned a = (unsigned)__cvta_generic_to_shared(p);
    asm volatile("ldmatrix.sync.aligned.m8n8.x4.trans.shared.b16 {%0,%1,%2,%3}, [%4];"
                 : "=r"(r[0]), "=r"(r[1]), "=r"(r[2]), "=r"(r[3]) : "r"(a));
}
__device__ __forceinline__ void mma16816(float* c, const unsigned* a,
                                         unsigned b0, unsigned b1) {
    asm volatile(
        "mma.sync.aligned.m16n8k16.row.col.f32.f16.f16.f32 "
        "{%0,%1,%2,%3}, {%4,%5,%6,%7}, {%8,%9}, {%0,%1,%2,%3};"
        : "+f"(c[0]), "+f"(c[1]), "+f"(c[2]), "+f"(c[3])
        : "r"(a[0]), "r"(a[1]), "r"(a[2]), "r"(a[3]), "r"(b0), "r"(b1));
}
__device__ __forceinline__ unsigned packh2(float a, float b) {
    __half2 h = __floats2half2_rn(a, b);
    return *reinterpret_cast<unsigned*>(&h);
}
__device__ __forceinline__ void split_f(float v, __half& h, __half& l) {
    h = __float2half_rn(v);
    l = __float2half_rn(v - __half2float(h));
}

// --------------------------- split x ------------------------------------------
__global__ void __launch_bounds__(256)
split_hl_kernel(const float* __restrict__ in, __half* __restrict__ oh,
                __half* __restrict__ ol, int n4)
{
    int i = blockIdx.x * 256 + threadIdx.x;
    if (i >= n4) return;
    float4 v = ((const float4*)in)[i];
    __half hx, lx, hy, ly, hz, lz, hw, lw;
    split_f(v.x, hx, lx); split_f(v.y, hy, ly);
    split_f(v.z, hz, lz); split_f(v.w, hw, lw);
    ((__half2*)oh)[2 * i]     = __halves2half2(hx, hy);
    ((__half2*)oh)[2 * i + 1] = __halves2half2(hz, hw);
    ((__half2*)ol)[2 * i]     = __halves2half2(lx, ly);
    ((__half2*)ol)[2 * i + 1] = __halves2half2(lz, lw);
}

// --------------- transpose + split W: [K,N] -> [N,K] hi/lo ---------------------
__global__ void transpose_split_kernel(const float* __restrict__ W,
                                       __half* __restrict__ th,
                                       __half* __restrict__ tl)
{
    __shared__ float s[32][33];
    int tx = threadIdx.x, ty = threadIdx.y;
#pragma unroll
    for (int i = 0; i < 4; ++i)
        s[ty + i * 8][tx] = W[(size_t)(blockIdx.y * 32 + ty + i * 8) * DDIM
                              + blockIdx.x * 32 + tx];
    __syncthreads();
    int xo = blockIdx.y * 32 + tx;
#pragma unroll
    for (int i = 0; i < 4; ++i) {
        int n = blockIdx.x * 32 + ty + i * 8;
        __half hh, ll;
        split_f(s[tx][ty + i * 8], hh, ll);
        th[(size_t)n * DDIM + xo] = hh;
        tl[(size_t)n * DDIM + xo] = ll;
    }
}

// --------------- relative-position bias, fp16 * log2e --------------------------
__global__ void __launch_bounds__(256)
bias_kernel(const float* __restrict__ Qb, const float* __restrict__ rel,
            __half* __restrict__ bias)
{
    __shared__ float srel[128];
    if (threadIdx.x < 128) srel[threadIdx.x] = rel[threadIdx.x];
    __syncthreads();
    size_t p = (size_t)blockIdx.x * 256 + threadIdx.x;
    float qb[8];
    *(float4*)qb       = *(const float4*)(Qb + p * 8);
    *(float4*)(qb + 4) = *(const float4*)(Qb + p * 8 + 4);
#pragma unroll
    for (int h = 0; h < 16; ++h) {
        float a = 0.f;
#pragma unroll
        for (int c = 0; c < 8; ++c) a += srel[c * 16 + h] * qb[c];
        bias[(size_t)h * SSEQ * SSEQ + p] = __float2half_rn(a * LOG2E);
    }
}

// ---- split-fp16 GEMM: C[M,N] = (Ah+Al)[M,K] x (Bh+Bl)[N,K]^T + bias[N] -------
__global__ void __launch_bounds__(256)
gemm3_kernel(const __half* __restrict__ Ah, const __half* __restrict__ Al,
             const __half* __restrict__ Bh, const __half* __restrict__ Bl,
             const float* __restrict__ bias, float* __restrict__ C,
             int M, int N, int K)
{
    extern __shared__ __half gsm[];
    __half (*sAh)[72] = (__half(*)[72])gsm;
    __half (*sAl)[72] = (__half(*)[72])(gsm + 128 * 72);
    __half (*sBh)[72] = (__half(*)[72])(gsm + 256 * 72);
    __half (*sBl)[72] = (__half(*)[72])(gsm + 384 * 72);

    const int tid = threadIdx.x;
    const int w = tid >> 5, t = tid & 31;
    const int wm = w & 3, wn = w >> 2;
    const int m0 = blockIdx.y * 128, n0 = blockIdx.x * 128;

    float acc[2][8][4];
#pragma unroll
    for (int a = 0; a < 2; ++a)
#pragma unroll
        for (int b = 0; b < 8; ++b)
#pragma unroll
            for (int c = 0; c < 4; ++c) acc[a][b][c] = 0.f;

    for (int kt = 0; kt < K; kt += 64) {
#pragma unroll
        for (int it = 0; it < 4; ++it) {
            int idx = tid + it * 256;
            int r = idx >> 3, c8 = (idx & 7) * 8;
            *(uint4*)&sAh[r][c8] = *(const uint4*)&Ah[(size_t)(m0 + r) * K + kt + c8];
            *(uint4*)&sAl[r][c8] = *(const uint4*)&Al[(size_t)(m0 + r) * K + kt + c8];
            *(uint4*)&sBh[r][c8] = *(const uint4*)&Bh[(size_t)(n0 + r) * K + kt + c8];
            *(uint4*)&sBl[r][c8] = *(const uint4*)&Bl[(size_t)(n0 + r) * K + kt + c8];
        }
        __syncthreads();

        const int ar = t & 15, co = (t >> 4) << 3;
#pragma unroll
        for (int k16 = 0; k16 < 4; ++k16) {
            int ko = k16 * 16 + co;
            unsigned ah[2][4], al[2][4];
            ldsm4(ah[0], &sAh[wm * 32 + ar][ko]);
            ldsm4(ah[1], &sAh[wm * 32 + 16 + ar][ko]);
            ldsm4(al[0], &sAl[wm * 32 + ar][ko]);
            ldsm4(al[1], &sAl[wm * 32 + 16 + ar][ko]);
#pragma unroll
            for (int ni = 0; ni < 4; ++ni) {
                unsigned bh[4], bl[4];
                ldsm4(bh, &sBh[wn * 64 + ni * 16 + ar][ko]);
                ldsm4(bl, &sBl[wn * 64 + ni * 16 + ar][ko]);
#pragma unroll
                for (int mi = 0; mi < 2; ++mi) {
                    mma16816(acc[mi][2 * ni],     ah[mi], bh[0], bh[2]);
                    mma16816(acc[mi][2 * ni],     ah[mi], bl[0], bl[2]);
                    mma16816(acc[mi][2 * ni],     al[mi], bh[0], bh[2]);
                    mma16816(acc[mi][2 * ni + 1], ah[mi], bh[1], bh[3]);
                    mma16816(acc[mi][2 * ni + 1], ah[mi], bl[1], bl[3]);
                    mma16816(acc[mi][2 * ni + 1], al[mi], bh[1], bh[3]);
                }
            }
        }
        __syncthreads();
    }

    const int qr = t >> 2, qc = (t & 3) * 2;
#pragma unroll
    for (int mi = 0; mi < 2; ++mi) {
        int r0 = m0 + wm * 32 + mi * 16 + qr;
#pragma unroll
        for (int j = 0; j < 8; ++j) {
            int col = n0 + wn * 64 + j * 8 + qc;
            float2 bv = *(const float2*)&bias[col];
            float2 o0 = {acc[mi][j][0] + bv.x, acc[mi][j][1] + bv.y};
            float2 o1 = {acc[mi][j][2] + bv.x, acc[mi][j][3] + bv.y};
            *(float2*)&C[(size_t)r0 * N + col] = o0;
            *(float2*)&C[(size_t)(r0 + 8) * N + col] = o1;
        }
    }
}

// ---- LN(optional) + scale + split + relayout [b,s,h,hd] -> [b,h,s,hd] ---------
__global__ void __launch_bounds__(256)
ln_split_kernel(const float* __restrict__ in, const float* __restrict__ sc,
                __half* __restrict__ oh, __half* __restrict__ ol,
                float mult, int do_ln)
{
    int gt = blockIdx.x * 256 + threadIdx.x;
    int g = gt >> 5, lane = gt & 31;
    int h = g & 15, bs = g >> 4;
    int s = bs & 2047, b = bs >> 11;
    float2 v = *(const float2*)&in[(size_t)g * 64 + lane * 2];
    float y0, y1;
    if (do_ln) {
        float sm = v.x + v.y, s2 = v.x * v.x + v.y * v.y;
#pragma unroll
        for (int d = 16; d > 0; d >>= 1) {
            sm += __shfl_xor_sync(0xffffffffu, sm, d);
            s2 += __shfl_xor_sync(0xffffffffu, s2, d);
        }
        float mu = sm * (1.f / 64.f);
        float var = s2 * (1.f / 64.f) - mu * mu;
        float r = rsqrtf(var + 1e-6f);
        y0 = (v.x - mu) * r * sc[lane * 2] * mult;
        y1 = (v.y - mu) * r * sc[lane * 2 + 1] * mult;
    } else {
        y0 = v.x; y1 = v.y;
    }
    size_t o = (((size_t)b * 16 + h) * 2048 + s) * 64 + lane * 2;
    __half h0, l0, h1, l1;
    split_f(y0, h0, l0); split_f(y1, h1, l1);
    *(__half2*)(oh + o) = __halves2half2(h0, h1);
    *(__half2*)(ol + o) = __halves2half2(l0, l1);
}

// ---------------- flash attention, split-fp16 MMA ------------------------------
__global__ void __launch_bounds__(256)
attn_kernel(const __half* __restrict__ qh_, const __half* __restrict__ ql_,
            const __half* __restrict__ kh_, const __half* __restrict__ kl_,
            const __half* __restrict__ vh_, const __half* __restrict__ vl_,
            const __half* __restrict__ biasH,
            __half* __restrict__ ch_, __half* __restrict__ cl_)
{
    __shared__ __align__(16) __half sbuf[18432];
    __half (*sQh)[72] = (__half(*)[72])sbuf;
    __half (*sQl)[72] = (__half(*)[72])(sbuf + 128 * 72);
    __half (*sKh)[72] = (__half(*)[72])sbuf;
    __half (*sKl)[72] = (__half(*)[72])(sbuf + 64 * 72);
    __half (*sVh)[72] = (__half(*)[72])(sbuf + 128 * 72);
    __half (*sVl)[72] = (__half(*)[72])(sbuf + 192 * 72);

    const int tid = threadIdx.x, w = tid >> 5, t = tid & 31;
    const int q0 = blockIdx.x * 128, h = blockIdx.y, b = blockIdx.z;
    const size_t qb = (((size_t)b * HHEADS + h) * SSEQ + q0) * 64;
    const size_t kb = (((size_t)b * HHEADS + h) * SSEQ) * 64;

#pragma unroll
    for (int it = 0; it < 4; ++it) {
        int idx = tid + it * 256;
        int r = idx >> 3, c8 = (idx & 7) * 8;
        *(uint4*)&sQh[r][c8] = *(const uint4*)&qh_[qb + (size_t)r * 64 + c8];
        *(uint4*)&sQl[r][c8] = *(const uint4*)&ql_[qb + (size_t)r * 64 + c8];
    }
    __syncthreads();
    unsigned qfh[4][4], qfl[4][4];
    {
        const int ar = t & 15, co = (t >> 4) << 3;
#pragma unroll
        for (int ki = 0; ki < 4; ++ki) {
            ldsm4(qfh[ki], &sQh[w * 16 + ar][ki * 16 + co]);
            ldsm4(qfl[ki], &sQl[w * 16 + ar][ki * 16 + co]);
        }
    }
    __syncthreads();

    float m0v = -1e30f, m1v = -1e30f, l0 = 0.f, l1 = 0.f;
    float oc[8][4];
#pragma unroll
    for (int j = 0; j < 8; ++j)
#pragma unroll
        for (int c = 0; c < 4; ++c) oc[j][c] = 0.f;

    const int qr = t >> 2, qc = (t & 3) * 2;
    const size_t brow0 = ((size_t)h * SSEQ + (q0 + w * 16 + qr)) * SSEQ;
    const size_t brow1 = brow0 + 8ull * SSEQ;

    for (int kt = 0; kt < SSEQ; kt += 64) {
#pragma unroll
        for (int it = 0; it < 8; ++it) {
            int idx = tid + it * 256;
            int arr = idx >> 9;
            int r = (idx >> 3) & 63, c8 = (idx & 7) * 8;
            const __half* src = (arr == 0) ? kh_ : (arr == 1) ? kl_
                              : (arr == 2) ? vh_ : vl_;
            __half* dst = (arr == 0) ? &sKh[r][c8] : (arr == 1) ? &sKl[r][c8]
                        : (arr == 2) ? &sVh[r][c8] : &sVl[r][c8];
            *(uint4*)dst = *(const uint4*)&src[kb + (size_t)(kt + r) * 64 + c8];
        }
        __syncthreads();

        float s[8][4];
#pragma unroll
        for (int j = 0; j < 8; ++j)
#pragma unroll
            for (int c = 0; c < 4; ++c) s[j][c] = 0.f;
        {
            const int ar = t & 15, co = (t >> 4) << 3;
#pragma unroll
            for (int ki = 0; ki < 4; ++ki) {
#pragma unroll
                for (int ni = 0; ni < 4; ++ni) {
                    unsigned bh[4], bl[4];
                    ldsm4(bh, &sKh[ni * 16 + ar][ki * 16 + co]);
                    ldsm4(bl, &sKl[ni * 16 + ar][ki * 16 + co]);
                    mma16816(s[2 * ni],     qfh[ki], bh[0], bh[2]);
                    mma16816(s[2 * ni],     qfh[ki], bl[0], bl[2]);
                    mma16816(s[2 * ni],     qfl[ki], bh[0], bh[2]);
                    mma16816(s[2 * ni + 1], qfh[ki], bh[1], bh[3]);
                    mma16816(s[2 * ni + 1], qfh[ki], bl[1], bl[3]);
                    mma16816(s[2 * ni + 1], qfl[ki], bh[1], bh[3]);
                }
            }
        }
#pragma unroll
        for (int j = 0; j < 8; ++j) {
            int col = kt + j * 8 + qc;
            float2 f0 = __half22float2(*(const __half2*)&biasH[brow0 + col]);
            float2 f1 = __half22float2(*(const __half2*)&biasH[brow1 + col]);
            s[j][0] += f0.x; s[j][1] += f0.y; s[j][2] += f1.x; s[j][3] += f1.y;
        }

        float mx0 = -1e30f, mx1 = -1e30f;
#pragma unroll
        for (int j = 0; j < 8; ++j) {
            mx0 = fmaxf(mx0, fmaxf(s[j][0], s[j][1]));
            mx1 = fmaxf(mx1, fmaxf(s[j][2], s[j][3]));
        }
        mx0 = fmaxf(mx0, __shfl_xor_sync(0xffffffffu, mx0, 1));
        mx0 = fmaxf(mx0, __shfl_xor_sync(0xffffffffu, mx0, 2));
        mx1 = fmaxf(mx1, __shfl_xor_sync(0xffffffffu, mx1, 1));
        mx1 = fmaxf(mx1, __shfl_xor_sync(0xffffffffu, mx1, 2));
        float mn0 = fmaxf(m0v, mx0), mn1 = fmaxf(m1v, mx1);
        float a0 = exp2f(m0v - mn0), a1 = exp2f(m1v - mn1);
        m0v = mn0; m1v = mn1;

        float rs0 = 0.f, rs1 = 0.f;
        unsigned pa[4][4];
#pragma unroll
        for (int i = 0; i < 4; ++i) {
            int j0 = 2 * i, j1 = 2 * i + 1;
            float p0 = exp2f(s[j0][0] - mn0), p1 = exp2f(s[j0][1] - mn0);
            float p2 = exp2f(s[j0][2] - mn1), p3 = exp2f(s[j0][3] - mn1);
            float u0 = exp2f(s[j1][0] - mn0), u1 = exp2f(s[j1][1] - mn0);
            float u2 = exp2f(s[j1][2] - mn1), u3 = exp2f(s[j1][3] - mn1);
            rs0 += (p0 + p1) + (u0 + u1);
            rs1 += (p2 + p3) + (u2 + u3);
            pa[i][0] = packh2(p0, p1); pa[i][1] = packh2(p2, p3);
            pa[i][2] = packh2(u0, u1); pa[i][3] = packh2(u2, u3);
        }
        rs0 += __shfl_xor_sync(0xffffffffu, rs0, 1);
        rs0 += __shfl_xor_sync(0xffffffffu, rs0, 2);
        rs1 += __shfl_xor_sync(0xffffffffu, rs1, 1);
        rs1 += __shfl_xor_sync(0xffffffffu, rs1, 2);
        l0 = l0 * a0 + rs0;
        l1 = l1 * a1 + rs1;
#pragma unroll
        for (int j = 0; j < 8; ++j) {
            oc[j][0] *= a0; oc[j][1] *= a0; oc[j][2] *= a1; oc[j][3] *= a1;
        }
        {
            int sr0 = ((t >> 4) & 1) * 8 + (t & 7);
            int hco = ((t >> 3) & 1) * 8;
#pragma unroll
            for (int i = 0; i < 4; ++i) {
                int sr = i * 16 + sr0;
#pragma unroll
                for (int ni = 0; ni < 4; ++ni) {
                    unsigned v4h[4], v4l[4];
                    ldsm4t(v4h, &sVh[sr][ni * 16 + hco]);
                    ldsm4t(v4l, &sVl[sr][ni * 16 + hco]);
                    mma16816(oc[2 * ni],     pa[i], v4h[0], v4h[2]);
                    mma16816(oc[2 * ni],     pa[i], v4l[0], v4l[2]);
                    mma16816(oc[2 * ni + 1], pa[i], v4h[1], v4h[3]);
                    mma16816(oc[2 * ni + 1], pa[i], v4l[1], v4l[3]);
                }
            }
        }
        __syncthreads();
    }

    float inv0 = 1.f / l0, inv1 = 1.f / l1;
    int r0 = q0 + w * 16 + qr;
    size_t ob0 = (((size_t)b * SSEQ + r0) * HHEADS + h) * 64;
    size_t ob1 = (((size_t)b * SSEQ + r0 + 8) * HHEADS + h) * 64;
#pragma unroll
    for (int j = 0; j < 8; ++j) {
        int col = j * 8 + qc;
        float f0 = oc[j][0] * inv0, f1 = oc[j][1] * inv0;
        float f2 = oc[j][2] * inv1, f3 = oc[j][3] * inv1;
        __half h0, e0, h1, e1, h2, e2, h3, e3;
        split_f(f0, h0, e0); split_f(f1, h1, e1);
        split_f(f2, h2, e2); split_f(f3, h3, e3);
        *(__half2*)(ch_ + ob0 + col) = __halves2half2(h0, h1);
        *(__half2*)(cl_ + ob0 + col) = __halves2half2(e0, e1);
        *(__half2*)(ch_ + ob1 + col) = __halves2half2(h2, h3);
        *(__half2*)(cl_ + ob1 + col) = __halves2half2(e2, e3);
    }
}

// ------------------------------- launcher --------------------------------------
extern "C" void kernel_launch(void* const* d_in, const int* in_sizes, int n_in,
                              void* d_out, int out_size)
{
    (void)in_sizes; (void)n_in; (void)out_size;
    const float* x   = (const float*)d_in[0];
    const float* Qb  = (const float*)d_in[1];
    const float* Wq  = (const float*)d_in[2];
    const float* bq  = (const float*)d_in[3];
    const float* Wk  = (const float*)d_in[4];
    const float* bk  = (const float*)d_in[5];
    const float* Wv  = (const float*)d_in[6];
    const float* bv  = (const float*)d_in[7];
    const float* qs  = (const float*)d_in[8];
    const float* ks  = (const float*)d_in[9];
    const float* rel = (const float*)d_in[10];
    const float* Wo  = (const float*)d_in[11];
    const float* bo  = (const float*)d_in[12];
    float* out = (float*)d_out;

    __half *xh, *xl, *wth, *wtl, *qh, *ql, *kh, *kl, *vh, *vl, *bH, *ch, *cl;
    float *pq, *pk, *pv;
    cudaGetSymbolAddress((void**)&xh,  g_xh);
    cudaGetSymbolAddress((void**)&xl,  g_xl);
    cudaGetSymbolAddress((void**)&wth, g_wth);
    cudaGetSymbolAddress((void**)&wtl, g_wtl);
    cudaGetSymbolAddress((void**)&pq,  g_q);
    cudaGetSymbolAddress((void**)&pk,  g_k);
    cudaGetSymbolAddress((void**)&pv,  g_v);
    cudaGetSymbolAddress((void**)&qh,  g_qh);
    cudaGetSymbolAddress((void**)&ql,  g_ql);
    cudaGetSymbolAddress((void**)&kh,  g_kh);
    cudaGetSymbolAddress((void**)&kl,  g_kl);
    cudaGetSymbolAddress((void**)&vh,  g_vh);
    cudaGetSymbolAddress((void**)&vl,  g_vl);
    cudaGetSymbolAddress((void**)&bH,  g_biasH);
    cudaGetSymbolAddress((void**)&ch,  g_ch);
    cudaGetSymbolAddress((void**)&cl,  g_cl);

    const int MM = 1024 * 1024;
    const int GS = 4 * 128 * 72 * 2;   // 73728 B dynamic smem for gemm3
    cudaFuncSetAttribute(gemm3_kernel,
                         cudaFuncAttributeMaxDynamicSharedMemorySize, GS);

    // prep: split x, transpose+split weights, bias table
    split_hl_kernel<<<(MROWS * DDIM / 4 + 255) / 256, 256>>>(x, xh, xl,
                                                             MROWS * DDIM / 4);
    dim3 tb(32, 8), tg(32, 32);
    transpose_split_kernel<<<tg, tb>>>(Wq, wth + 0 * MM, wtl + 0 * MM);
    transpose_split_kernel<<<tg, tb>>>(Wk, wth + 1 * MM, wtl + 1 * MM);
    transpose_split_kernel<<<tg, tb>>>(Wv, wth + 2 * MM, wtl + 2 * MM);
    transpose_split_kernel<<<tg, tb>>>(Wo, wth + 3 * MM, wtl + 3 * MM);
    bias_kernel<<<(SSEQ * SSEQ) / 256, 256>>>(Qb, rel, bH);

    // QKV projections
    dim3 gg(DDIM / 128, MROWS / 128);  // (8, 32)
    gemm3_kernel<<<gg, 256, GS>>>(xh, xl, wth + 0 * MM, wtl + 0 * MM, bq, pq,
                                  MROWS, DDIM, DDIM);
    gemm3_kernel<<<gg, 256, GS>>>(xh, xl, wth + 1 * MM, wtl + 1 * MM, bk, pk,
                                  MROWS, DDIM, DDIM);
    gemm3_kernel<<<gg, 256, GS>>>(xh, xl, wth + 2 * MM, wtl + 2 * MM, bv, pv,
                                  MROWS, DDIM, DDIM);

    // LN + scale + split + relayout
    int lnb = (MROWS * HHEADS * 32) / 256;  // 8192 blocks
    ln_split_kernel<<<lnb, 256>>>(pq, qs, qh, ql, 0.125f * LOG2E, 1);
    ln_split_kernel<<<lnb, 256>>>(pk, ks, kh, kl, 1.0f, 1);
    ln_split_kernel<<<lnb, 256>>>(pv, qs, vh, vl, 1.0f, 0);

    // attention
    attn_kernel<<<dim3(SSEQ / 128, HHEADS, BBATCH), 256>>>(qh, ql, kh, kl,
                                                           vh, vl, bH, ch, cl);

    // output projection
    gemm3_kernel<<<gg, 256, GS>>>(ch, cl, wth + 3 * MM, wtl + 3 * MM, bo, out,
                                  MROWS, DDIM, DDIM);
}

// round 8
// speedup vs baseline: 2.2697x; 1.0492x over previous
#include <cuda_runtime.h>
#include <cuda_fp16.h>
#include <cstdint>

#define BBATCH 2
#define SSEQ 2048
#define DDIM 1024
#define HHEADS 16
#define MROWS (BBATCH * SSEQ)
#define LOG2E 1.4426950408889634f

// ------------------------------ scratch ---------------------------------------
__device__ __align__(16) __half g_xh[MROWS * DDIM];
__device__ __align__(16) __half g_xl[MROWS * DDIM];
__device__ __align__(16) __half g_wth[4 * DDIM * DDIM];
__device__ __align__(16) __half g_wtl[4 * DDIM * DDIM];
__device__ __align__(16) float  g_q[MROWS * DDIM];
__device__ __align__(16) float  g_k[MROWS * DDIM];
__device__ __align__(16) float  g_v[MROWS * DDIM];
__device__ __align__(16) __half g_qh[MROWS * DDIM];
__device__ __align__(16) __half g_ql[MROWS * DDIM];
__device__ __align__(16) __half g_kh[MROWS * DDIM];
__device__ __align__(16) __half g_kl[MROWS * DDIM];
__device__ __align__(16) __half g_vh[MROWS * DDIM];
__device__ __align__(16) __half g_vl[MROWS * DDIM];
__device__ __align__(16) __half g_biasH[(size_t)HHEADS * SSEQ * SSEQ];
__device__ __align__(16) __half g_ch[MROWS * DDIM];
__device__ __align__(16) __half g_cl[MROWS * DDIM];

// ------------------------------ helpers ---------------------------------------
__device__ __forceinline__ void ldsm4(unsigned* r, const void* p) {
    unsigned a = (unsigned)__cvta_generic_to_shared(p);
    asm volatile("ldmatrix.sync.aligned.m8n8.x4.shared.b16 {%0,%1,%2,%3}, [%4];"
                 : "=r"(r[0]), "=r"(r[1]), "=r"(r[2]), "=r"(r[3]) : "r"(a));
}
__device__ __forceinline__ void ldsm4t(unsigned* r, const void* p) {
    unsigned a = (unsigned)__cvta_generic_to_shared(p);
    asm volatile("ldmatrix.sync.aligned.m8n8.x4.trans.shared.b16 {%0,%1,%2,%3}, [%4];"
                 : "=r"(r[0]), "=r"(r[1]), "=r"(r[2]), "=r"(r[3]) : "r"(a));
}
__device__ __forceinline__ void mma16816(float* c, const unsigned* a,
                                         unsigned b0, unsigned b1) {
    asm volatile(
        "mma.sync.aligned.m16n8k16.row.col.f32.f16.f16.f32 "
        "{%0,%1,%2,%3}, {%4,%5,%6,%7}, {%8,%9}, {%0,%1,%2,%3};"
        : "+f"(c[0]), "+f"(c[1]), "+f"(c[2]), "+f"(c[3])
        : "r"(a[0]), "r"(a[1]), "r"(a[2]), "r"(a[3]), "r"(b0), "r"(b1));
}
__device__ __forceinline__ void cp16(void* smem, const void* gmem) {
    unsigned s = (unsigned)__cvta_generic_to_shared(smem);
    asm volatile("cp.async.cg.shared.global [%0], [%1], 16;" :: "r"(s), "l"(gmem));
}
__device__ __forceinline__ void cp_commit() {
    asm volatile("cp.async.commit_group;");
}
__device__ __forceinline__ void cp_wait0() {
    asm volatile("cp.async.wait_group 0;");
}
__device__ __forceinline__ void cp_wait1() {
    asm volatile("cp.async.wait_group 1;");
}
__device__ __forceinline__ unsigned packh2(float a, float b) {
    __half2 h = __floats2half2_rn(a, b);
    return *reinterpret_cast<unsigned*>(&h);
}
__device__ __forceinline__ void split_f(float v, __half& h, __half& l) {
    h = __float2half_rn(v);
    l = __float2half_rn(v - __half2float(h));
}

// --------------------------- split x ------------------------------------------
__global__ void __launch_bounds__(256)
split_hl_kernel(const float* __restrict__ in, __half* __restrict__ oh,
                __half* __restrict__ ol, int n4)
{
    int i = blockIdx.x * 256 + threadIdx.x;
    if (i >= n4) return;
    float4 v = ((const float4*)in)[i];
    __half hx, lx, hy, ly, hz, lz, hw, lw;
    split_f(v.x, hx, lx); split_f(v.y, hy, ly);
    split_f(v.z, hz, lz); split_f(v.w, hw, lw);
    ((__half2*)oh)[2 * i]     = __halves2half2(hx, hy);
    ((__half2*)oh)[2 * i + 1] = __halves2half2(hz, hw);
    ((__half2*)ol)[2 * i]     = __halves2half2(lx, ly);
    ((__half2*)ol)[2 * i + 1] = __halves2half2(lz, lw);
}

// --------------- transpose + split 4 weights: [K,N] -> [N,K] hi/lo -------------
__global__ void transpose_split_kernel(const float* __restrict__ W0,
                                       const float* __restrict__ W1,
                                       const float* __restrict__ W2,
                                       const float* __restrict__ W3,
                                       __half* __restrict__ th_base,
                                       __half* __restrict__ tl_base)
{
    __shared__ float s[32][33];
    const int z = blockIdx.z;
    const float* W = (z == 0) ? W0 : (z == 1) ? W1 : (z == 2) ? W2 : W3;
    __half* th = th_base + (size_t)z * DDIM * DDIM;
    __half* tl = tl_base + (size_t)z * DDIM * DDIM;
    int tx = threadIdx.x, ty = threadIdx.y;
#pragma unroll
    for (int i = 0; i < 4; ++i)
        s[ty + i * 8][tx] = W[(size_t)(blockIdx.y * 32 + ty + i * 8) * DDIM
                              + blockIdx.x * 32 + tx];
    __syncthreads();
    int xo = blockIdx.y * 32 + tx;
#pragma unroll
    for (int i = 0; i < 4; ++i) {
        int n = blockIdx.x * 32 + ty + i * 8;
        __half hh, ll;
        split_f(s[tx][ty + i * 8], hh, ll);
        th[(size_t)n * DDIM + xo] = hh;
        tl[(size_t)n * DDIM + xo] = ll;
    }
}

// --------------- relative-position bias, fp16 * log2e --------------------------
__global__ void __launch_bounds__(256)
bias_kernel(const float* __restrict__ Qb, const float* __restrict__ rel,
            __half* __restrict__ bias)
{
    __shared__ float srel[128];
    if (threadIdx.x < 128) srel[threadIdx.x] = rel[threadIdx.x];
    __syncthreads();
    size_t p = (size_t)blockIdx.x * 256 + threadIdx.x;
    float qb[8];
    *(float4*)qb       = *(const float4*)(Qb + p * 8);
    *(float4*)(qb + 4) = *(const float4*)(Qb + p * 8 + 4);
#pragma unroll
    for (int h = 0; h < 16; ++h) {
        float a = 0.f;
#pragma unroll
        for (int c = 0; c < 8; ++c) a += srel[c * 16 + h] * qb[c];
        bias[(size_t)h * SSEQ * SSEQ + p] = __float2half_rn(a * LOG2E);
    }
}

// ---- split-fp16 GEMM, 2-stage cp.async pipeline, BK=32 ------------------------
// C[M,N] = (Ah+Al)[M,K] x (Bh+Bl)[N,K]^T + bias[N]; 3 MMA terms (hh+hl+lh).
#define GRS 40                      // row stride in halves (32 + 8 pad)
#define GARR (128 * GRS)            // halves per array
#define GSTG (4 * GARR)             // halves per stage

__global__ void __launch_bounds__(256, 2)
gemm3_kernel(const __half* __restrict__ Ah, const __half* __restrict__ Al,
             const __half* __restrict__ Bh, const __half* __restrict__ Bl,
             const float* __restrict__ bias, float* __restrict__ C,
             int M, int N, int K)
{
    extern __shared__ __half gsm[];

    const int tid = threadIdx.x;
    const int w = tid >> 5, t = tid & 31;
    const int wm = w & 3, wn = w >> 2;
    const int m0 = blockIdx.y * 128, n0 = blockIdx.x * 128;

    float acc[2][8][4];
#pragma unroll
    for (int a = 0; a < 2; ++a)
#pragma unroll
        for (int b = 0; b < 8; ++b)
#pragma unroll
            for (int c = 0; c < 4; ++c) acc[a][b][c] = 0.f;

    const int lr = tid >> 2, lc8 = (tid & 3) * 8;   // loader: 128 rows x 4 c8 groups

    auto load_stage = [&](int s, int kt) {
        __half* p = gsm + s * GSTG;
#pragma unroll
        for (int it = 0; it < 2; ++it) {
            int r = lr;  // same row both its? no: 128 rows x 4 groups = 512 / 256 = 2
            int idx = tid + it * 256;
            r = idx >> 2; int c8 = (idx & 3) * 8;
            cp16(p + 0 * GARR + r * GRS + c8, Ah + (size_t)(m0 + r) * K + kt + c8);
            cp16(p + 1 * GARR + r * GRS + c8, Al + (size_t)(m0 + r) * K + kt + c8);
            cp16(p + 2 * GARR + r * GRS + c8, Bh + (size_t)(n0 + r) * K + kt + c8);
            cp16(p + 3 * GARR + r * GRS + c8, Bl + (size_t)(n0 + r) * K + kt + c8);
        }
        cp_commit();
    };

    const int ar = t & 15, co = (t >> 4) << 3;
    const int ntiles = K / 32;

    load_stage(0, 0);
    for (int ti = 0; ti < ntiles; ++ti) {
        int s = ti & 1;
        if (ti + 1 < ntiles) { load_stage(s ^ 1, (ti + 1) * 32); cp_wait1(); }
        else                 { cp_wait0(); }
        __syncthreads();

        __half* pAh = gsm + s * GSTG;
        __half* pAl = pAh + GARR;
        __half* pBh = pAh + 2 * GARR;
        __half* pBl = pAh + 3 * GARR;
#pragma unroll
        for (int k16 = 0; k16 < 2; ++k16) {
            int ko = k16 * 16 + co;
            unsigned ah[2][4], al[2][4];
            ldsm4(ah[0], pAh + (wm * 32 + ar) * GRS + ko);
            ldsm4(ah[1], pAh + (wm * 32 + 16 + ar) * GRS + ko);
            ldsm4(al[0], pAl + (wm * 32 + ar) * GRS + ko);
            ldsm4(al[1], pAl + (wm * 32 + 16 + ar) * GRS + ko);
#pragma unroll
            for (int ni = 0; ni < 4; ++ni) {
                unsigned bh[4], bl[4];
                ldsm4(bh, pBh + (wn * 64 + ni * 16 + ar) * GRS + ko);
                ldsm4(bl, pBl + (wn * 64 + ni * 16 + ar) * GRS + ko);
#pragma unroll
                for (int mi = 0; mi < 2; ++mi) {
                    mma16816(acc[mi][2 * ni],     ah[mi], bh[0], bh[2]);
                    mma16816(acc[mi][2 * ni],     ah[mi], bl[0], bl[2]);
                    mma16816(acc[mi][2 * ni],     al[mi], bh[0], bh[2]);
                    mma16816(acc[mi][2 * ni + 1], ah[mi], bh[1], bh[3]);
                    mma16816(acc[mi][2 * ni + 1], ah[mi], bl[1], bl[3]);
                    mma16816(acc[mi][2 * ni + 1], al[mi], bh[1], bh[3]);
                }
            }
        }
        __syncthreads();
    }

    const int qr = t >> 2, qc = (t & 3) * 2;
#pragma unroll
    for (int mi = 0; mi < 2; ++mi) {
        int r0 = m0 + wm * 32 + mi * 16 + qr;
#pragma unroll
        for (int j = 0; j < 8; ++j) {
            int col = n0 + wn * 64 + j * 8 + qc;
            float2 bv = *(const float2*)&bias[col];
            float2 o0 = {acc[mi][j][0] + bv.x, acc[mi][j][1] + bv.y};
            float2 o1 = {acc[mi][j][2] + bv.x, acc[mi][j][3] + bv.y};
            *(float2*)&C[(size_t)r0 * N + col] = o0;
            *(float2*)&C[(size_t)(r0 + 8) * N + col] = o1;
        }
    }
}

// ---- LN(optional) + scale + split + relayout [b,s,h,hd] -> [b,h,s,hd] ---------
__global__ void __launch_bounds__(256)
ln_split_kernel(const float* __restrict__ in, const float* __restrict__ sc,
                __half* __restrict__ oh, __half* __restrict__ ol,
                float mult, int do_ln)
{
    int gt = blockIdx.x * 256 + threadIdx.x;
    int g = gt >> 5, lane = gt & 31;
    int h = g & 15, bs = g >> 4;
    int s = bs & 2047, b = bs >> 11;
    float2 v = *(const float2*)&in[(size_t)g * 64 + lane * 2];
    float y0, y1;
    if (do_ln) {
        float sm = v.x + v.y, s2 = v.x * v.x + v.y * v.y;
#pragma unroll
        for (int d = 16; d > 0; d >>= 1) {
            sm += __shfl_xor_sync(0xffffffffu, sm, d);
            s2 += __shfl_xor_sync(0xffffffffu, s2, d);
        }
        float mu = sm * (1.f / 64.f);
        float var = s2 * (1.f / 64.f) - mu * mu;
        float r = rsqrtf(var + 1e-6f);
        y0 = (v.x - mu) * r * sc[lane * 2] * mult;
        y1 = (v.y - mu) * r * sc[lane * 2 + 1] * mult;
    } else {
        y0 = v.x; y1 = v.y;
    }
    size_t o = (((size_t)b * 16 + h) * 2048 + s) * 64 + lane * 2;
    __half h0, l0, h1, l1;
    split_f(y0, h0, l0); split_f(y1, h1, l1);
    *(__half2*)(oh + o) = __halves2half2(h0, h1);
    *(__half2*)(ol + o) = __halves2half2(l0, l1);
}

// ---------------- flash attention, split-fp16 MMA, 2-stage pipeline ------------
#define ARS 72                      // attn row stride (halves)
#define AKV (64 * ARS)              // one K/V array (halves)
#define ASTG (4 * AKV)              // one stage: Kh,Kl,Vh,Vl

__global__ void __launch_bounds__(256)
attn_kernel(const __half* __restrict__ qh_, const __half* __restrict__ ql_,
            const __half* __restrict__ kh_, const __half* __restrict__ kl_,
            const __half* __restrict__ vh_, const __half* __restrict__ vl_,
            const __half* __restrict__ biasH,
            __half* __restrict__ ch_, __half* __restrict__ cl_)
{
    extern __shared__ __half smha[];

    const int tid = threadIdx.x, w = tid >> 5, t = tid & 31;
    const int q0 = blockIdx.x * 128, h = blockIdx.y, b = blockIdx.z;
    const size_t qb = (((size_t)b * HHEADS + h) * SSEQ + q0) * 64;
    const size_t kb = (((size_t)b * HHEADS + h) * SSEQ) * 64;

    auto load_kv = [&](int s, int kt) {
        __half* p = smha + s * ASTG;
        int r0 = tid >> 3, c8 = (tid & 7) * 8;
#pragma unroll
        for (int it = 0; it < 8; ++it) {
            const __half* src = (it < 2) ? kh_ : (it < 4) ? kl_
                              : (it < 6) ? vh_ : vl_;
            int arr = it >> 1;
            int r = ((it & 1) << 5) + r0;
            cp16(p + arr * AKV + r * ARS + c8,
                 src + kb + (size_t)(kt + r) * 64 + c8);
        }
        cp_commit();
    };

    // start fetching K/V tile 0 into stage 0
    load_kv(0, 0);

    // stage Q into stage-1 region, consume to registers
    __half* sQh = smha + ASTG;
    __half* sQl = sQh + 2 * AKV;
#pragma unroll
    for (int it = 0; it < 4; ++it) {
        int idx = tid + it * 256;
        int r = idx >> 3, c8 = (idx & 7) * 8;
        *(uint4*)(sQh + r * ARS + c8) = *(const uint4*)&qh_[qb + (size_t)r * 64 + c8];
        *(uint4*)(sQl + r * ARS + c8) = *(const uint4*)&ql_[qb + (size_t)r * 64 + c8];
    }
    __syncthreads();
    unsigned qfh[4][4], qfl[4][4];
    const int ar = t & 15, co = (t >> 4) << 3;
#pragma unroll
    for (int ki = 0; ki < 4; ++ki) {
        ldsm4(qfh[ki], sQh + (w * 16 + ar) * ARS + ki * 16 + co);
        ldsm4(qfl[ki], sQl + (w * 16 + ar) * ARS + ki * 16 + co);
    }
    __syncthreads();   // Q consumed; stage 1 free for tile 1

    float m0v = -1e30f, m1v = -1e30f, l0 = 0.f, l1 = 0.f;
    float oc[8][4];
#pragma unroll
    for (int j = 0; j < 8; ++j)
#pragma unroll
        for (int c = 0; c < 4; ++c) oc[j][c] = 0.f;

    const int qr = t >> 2, qc = (t & 3) * 2;
    const size_t brow0 = ((size_t)h * SSEQ + (q0 + w * 16 + qr)) * SSEQ;
    const size_t brow1 = brow0 + 8ull * SSEQ;

    const int ntiles = SSEQ / 64;   // 32
    for (int ti = 0; ti < ntiles; ++ti) {
        int s = ti & 1;
        if (ti + 1 < ntiles) { load_kv(s ^ 1, (ti + 1) * 64); cp_wait1(); }
        else                 { cp_wait0(); }
        __syncthreads();

        __half* pKh = smha + s * ASTG;
        __half* pKl = pKh + AKV;
        __half* pVh = pKh + 2 * AKV;
        __half* pVl = pKh + 3 * AKV;
        const int kt = ti * 64;

        float sc[8][4];
#pragma unroll
        for (int j = 0; j < 8; ++j)
#pragma unroll
            for (int c = 0; c < 4; ++c) sc[j][c] = 0.f;
#pragma unroll
        for (int ki = 0; ki < 4; ++ki) {
#pragma unroll
            for (int ni = 0; ni < 4; ++ni) {
                unsigned bh[4], bl[4];
                ldsm4(bh, pKh + (ni * 16 + ar) * ARS + ki * 16 + co);
                ldsm4(bl, pKl + (ni * 16 + ar) * ARS + ki * 16 + co);
                mma16816(sc[2 * ni],     qfh[ki], bh[0], bh[2]);
                mma16816(sc[2 * ni],     qfh[ki], bl[0], bl[2]);
                mma16816(sc[2 * ni],     qfl[ki], bh[0], bh[2]);
                mma16816(sc[2 * ni + 1], qfh[ki], bh[1], bh[3]);
                mma16816(sc[2 * ni + 1], qfh[ki], bl[1], bl[3]);
                mma16816(sc[2 * ni + 1], qfl[ki], bh[1], bh[3]);
            }
        }
#pragma unroll
        for (int j = 0; j < 8; ++j) {
            int col = kt + j * 8 + qc;
            float2 f0 = __half22float2(*(const __half2*)&biasH[brow0 + col]);
            float2 f1 = __half22float2(*(const __half2*)&biasH[brow1 + col]);
            sc[j][0] += f0.x; sc[j][1] += f0.y; sc[j][2] += f1.x; sc[j][3] += f1.y;
        }

        float mx0 = -1e30f, mx1 = -1e30f;
#pragma unroll
        for (int j = 0; j < 8; ++j) {
            mx0 = fmaxf(mx0, fmaxf(sc[j][0], sc[j][1]));
            mx1 = fmaxf(mx1, fmaxf(sc[j][2], sc[j][3]));
        }
        mx0 = fmaxf(mx0, __shfl_xor_sync(0xffffffffu, mx0, 1));
        mx0 = fmaxf(mx0, __shfl_xor_sync(0xffffffffu, mx0, 2));
        mx1 = fmaxf(mx1, __shfl_xor_sync(0xffffffffu, mx1, 1));
        mx1 = fmaxf(mx1, __shfl_xor_sync(0xffffffffu, mx1, 2));
        float mn0 = fmaxf(m0v, mx0), mn1 = fmaxf(m1v, mx1);
        float a0 = exp2f(m0v - mn0), a1 = exp2f(m1v - mn1);
        m0v = mn0; m1v = mn1;

        float rs0 = 0.f, rs1 = 0.f;
        unsigned pa[4][4];
#pragma unroll
        for (int i = 0; i < 4; ++i) {
            int j0 = 2 * i, j1 = 2 * i + 1;
            float p0 = exp2f(sc[j0][0] - mn0), p1 = exp2f(sc[j0][1] - mn0);
            float p2 = exp2f(sc[j0][2] - mn1), p3 = exp2f(sc[j0][3] - mn1);
            float u0 = exp2f(sc[j1][0] - mn0), u1 = exp2f(sc[j1][1] - mn0);
            float u2 = exp2f(sc[j1][2] - mn1), u3 = exp2f(sc[j1][3] - mn1);
            rs0 += (p0 + p1) + (u0 + u1);
            rs1 += (p2 + p3) + (u2 + u3);
            pa[i][0] = packh2(p0, p1); pa[i][1] = packh2(p2, p3);
            pa[i][2] = packh2(u0, u1); pa[i][3] = packh2(u2, u3);
        }
        rs0 += __shfl_xor_sync(0xffffffffu, rs0, 1);
        rs0 += __shfl_xor_sync(0xffffffffu, rs0, 2);
        rs1 += __shfl_xor_sync(0xffffffffu, rs1, 1);
        rs1 += __shfl_xor_sync(0xffffffffu, rs1, 2);
        l0 = l0 * a0 + rs0;
        l1 = l1 * a1 + rs1;
#pragma unroll
        for (int j = 0; j < 8; ++j) {
            oc[j][0] *= a0; oc[j][1] *= a0; oc[j][2] *= a1; oc[j][3] *= a1;
        }
        {
            int sr0 = ((t >> 4) & 1) * 8 + (t & 7);
            int hco = ((t >> 3) & 1) * 8;
#pragma unroll
            for (int i = 0; i < 4; ++i) {
                int sr = i * 16 + sr0;
#pragma unroll
                for (int ni = 0; ni < 4; ++ni) {
                    unsigned v4h[4], v4l[4];
                    ldsm4t(v4h, pVh + sr * ARS + ni * 16 + hco);
                    ldsm4t(v4l, pVl + sr * ARS + ni * 16 + hco);
                    mma16816(oc[2 * ni],     pa[i], v4h[0], v4h[2]);
                    mma16816(oc[2 * ni],     pa[i], v4l[0], v4l[2]);
                    mma16816(oc[2 * ni + 1], pa[i], v4h[1], v4h[3]);
                    mma16816(oc[2 * ni + 1], pa[i], v4l[1], v4l[3]);
                }
            }
        }
        __syncthreads();   // stage s fully consumed; next iter may refill it
    }

    float inv0 = 1.f / l0, inv1 = 1.f / l1;
    int r0 = q0 + w * 16 + qr;
    size_t ob0 = (((size_t)b * SSEQ + r0) * HHEADS + h) * 64;
    size_t ob1 = (((size_t)b * SSEQ + r0 + 8) * HHEADS + h) * 64;
#pragma unroll
    for (int j = 0; j < 8; ++j) {
        int col = j * 8 + qc;
        float f0 = oc[j][0] * inv0, f1 = oc[j][1] * inv0;
        float f2 = oc[j][2] * inv1, f3 = oc[j][3] * inv1;
        __half h0, e0, h1, e1, h2, e2, h3, e3;
        split_f(f0, h0, e0); split_f(f1, h1, e1);
        split_f(f2, h2, e2); split_f(f3, h3, e3);
        *(__half2*)(ch_ + ob0 + col) = __halves2half2(h0, h1);
        *(__half2*)(cl_ + ob0 + col) = __halves2half2(e0, e1);
        *(__half2*)(ch_ + ob1 + col) = __halves2half2(h2, h3);
        *(__half2*)(cl_ + ob1 + col) = __halves2half2(e2, e3);
    }
}

// ------------------------------- launcher --------------------------------------
extern "C" void kernel_launch(void* const* d_in, const int* in_sizes, int n_in,
                              void* d_out, int out_size)
{
    (void)in_sizes; (void)n_in; (void)out_size;
    const float* x   = (const float*)d_in[0];
    const float* Qb  = (const float*)d_in[1];
    const float* Wq  = (const float*)d_in[2];
    const float* bq  = (const float*)d_in[3];
    const float* Wk  = (const float*)d_in[4];
    const float* bk  = (const float*)d_in[5];
    const float* Wv  = (const float*)d_in[6];
    const float* bv  = (const float*)d_in[7];
    const float* qs  = (const float*)d_in[8];
    const float* ks  = (const float*)d_in[9];
    const float* rel = (const float*)d_in[10];
    const float* Wo  = (const float*)d_in[11];
    const float* bo  = (const float*)d_in[12];
    float* out = (float*)d_out;

    __half *xh, *xl, *wth, *wtl, *qh, *ql, *kh, *kl, *vh, *vl, *bH, *ch, *cl;
    float *pq, *pk, *pv;
    cudaGetSymbolAddress((void**)&xh,  g_xh);
    cudaGetSymbolAddress((void**)&xl,  g_xl);
    cudaGetSymbolAddress((void**)&wth, g_wth);
    cudaGetSymbolAddress((void**)&wtl, g_wtl);
    cudaGetSymbolAddress((void**)&pq,  g_q);
    cudaGetSymbolAddress((void**)&pk,  g_k);
    cudaGetSymbolAddress((void**)&pv,  g_v);
    cudaGetSymbolAddress((void**)&qh,  g_qh);
    cudaGetSymbolAddress((void**)&ql,  g_ql);
    cudaGetSymbolAddress((void**)&kh,  g_kh);
    cudaGetSymbolAddress((void**)&kl,  g_kl);
    cudaGetSymbolAddress((void**)&vh,  g_vh);
    cudaGetSymbolAddress((void**)&vl,  g_vl);
    cudaGetSymbolAddress((void**)&bH,  g_biasH);
    cudaGetSymbolAddress((void**)&ch,  g_ch);
    cudaGetSymbolAddress((void**)&cl,  g_cl);

    const int MM = 1024 * 1024;
    const int GS = 2 * GSTG * (int)sizeof(__half);   // 81920 B
    const int AS = 2 * ASTG * (int)sizeof(__half);   // 73728 B
    cudaFuncSetAttribute(gemm3_kernel,
                         cudaFuncAttributeMaxDynamicSharedMemorySize, GS);
    cudaFuncSetAttribute(attn_kernel,
                         cudaFuncAttributeMaxDynamicSharedMemorySize, AS);

    // prep
    split_hl_kernel<<<(MROWS * DDIM / 4 + 255) / 256, 256>>>(x, xh, xl,
                                                             MROWS * DDIM / 4);
    dim3 tb(32, 8), tg(32, 32, 4);
    transpose_split_kernel<<<tg, tb>>>(Wq, Wk, Wv, Wo, wth, wtl);
    bias_kernel<<<(SSEQ * SSEQ) / 256, 256>>>(Qb, rel, bH);

    // QKV projections
    dim3 gg(DDIM / 128, MROWS / 128);
    gemm3_kernel<<<gg, 256, GS>>>(xh, xl, wth + 0 * MM, wtl + 0 * MM, bq, pq,
                                  MROWS, DDIM, DDIM);
    gemm3_kernel<<<gg, 256, GS>>>(xh, xl, wth + 1 * MM, wtl + 1 * MM, bk, pk,
                                  MROWS, DDIM, DDIM);
    gemm3_kernel<<<gg, 256, GS>>>(xh, xl, wth + 2 * MM, wtl + 2 * MM, bv, pv,
                                  MROWS, DDIM, DDIM);

    // LN + scale + split + relayout
    int lnb = (MROWS * HHEADS * 32) / 256;
    ln_split_kernel<<<lnb, 256>>>(pq, qs, qh, ql, 0.125f * LOG2E, 1);
    ln_split_kernel<<<lnb, 256>>>(pk, ks, kh, kl, 1.0f, 1);
    ln_split_kernel<<<lnb, 256>>>(pv, qs, vh, vl, 1.0f, 0);

    // attention
    attn_kernel<<<dim3(SSEQ / 128, HHEADS, BBATCH), 256, AS>>>(qh, ql, kh, kl,
                                                               vh, vl, bH, ch, cl);

    // output projection
    gemm3_kernel<<<gg, 256, GS>>>(ch, cl, wth + 3 * MM, wtl + 3 * MM, bo, out,
                                  MROWS, DDIM, DDIM);
}

// round 9
// speedup vs baseline: 2.3229x; 1.0234x over previous
#include <cuda_runtime.h>
#include <cuda_fp16.h>
#include <cstdint>

#define BBATCH 2
#define SSEQ 2048
#define DDIM 1024
#define HHEADS 16
#define MROWS (BBATCH * SSEQ)
#define LOG2E 1.4426950408889634f

// ------------------------------ scratch ---------------------------------------
__device__ __align__(16) __half g_xh[MROWS * DDIM];
__device__ __align__(16) __half g_xl[MROWS * DDIM];
__device__ __align__(16) __half g_wth[4 * DDIM * DDIM];
__device__ __align__(16) __half g_wtl[4 * DDIM * DDIM];
__device__ __align__(16) __half g_qh[MROWS * DDIM];
__device__ __align__(16) __half g_ql[MROWS * DDIM];
__device__ __align__(16) __half g_kh[MROWS * DDIM];
__device__ __align__(16) __half g_kl[MROWS * DDIM];
__device__ __align__(16) __half g_vh[MROWS * DDIM];
__device__ __align__(16) __half g_vl[MROWS * DDIM];
__device__ __align__(16) __half g_biasH[(size_t)HHEADS * SSEQ * SSEQ];
__device__ __align__(16) __half g_ch[MROWS * DDIM];
__device__ __align__(16) __half g_cl[MROWS * DDIM];

// ------------------------------ helpers ---------------------------------------
__device__ __forceinline__ void ldsm4(unsigned* r, const void* p) {
    unsigned a = (unsigned)__cvta_generic_to_shared(p);
    asm volatile("ldmatrix.sync.aligned.m8n8.x4.shared.b16 {%0,%1,%2,%3}, [%4];"
                 : "=r"(r[0]), "=r"(r[1]), "=r"(r[2]), "=r"(r[3]) : "r"(a));
}
__device__ __forceinline__ void ldsm4t(unsigned* r, const void* p) {
    unsigned a = (unsigned)__cvta_generic_to_shared(p);
    asm volatile("ldmatrix.sync.aligned.m8n8.x4.trans.shared.b16 {%0,%1,%2,%3}, [%4];"
                 : "=r"(r[0]), "=r"(r[1]), "=r"(r[2]), "=r"(r[3]) : "r"(a));
}
// NOT volatile: pure register op; lets ptxas interleave independent MMA chains.
__device__ __forceinline__ void mma16816(float* c, const unsigned* a,
                                         unsigned b0, unsigned b1) {
    asm("mma.sync.aligned.m16n8k16.row.col.f32.f16.f16.f32 "
        "{%0,%1,%2,%3}, {%4,%5,%6,%7}, {%8,%9}, {%0,%1,%2,%3};"
        : "+f"(c[0]), "+f"(c[1]), "+f"(c[2]), "+f"(c[3])
        : "r"(a[0]), "r"(a[1]), "r"(a[2]), "r"(a[3]), "r"(b0), "r"(b1));
}
__device__ __forceinline__ void cp16(void* smem, const void* gmem) {
    unsigned s = (unsigned)__cvta_generic_to_shared(smem);
    asm volatile("cp.async.cg.shared.global [%0], [%1], 16;" :: "r"(s), "l"(gmem));
}
__device__ __forceinline__ void cp_commit() { asm volatile("cp.async.commit_group;"); }
__device__ __forceinline__ void cp_wait0()  { asm volatile("cp.async.wait_group 0;"); }
__device__ __forceinline__ void cp_wait1()  { asm volatile("cp.async.wait_group 1;"); }
__device__ __forceinline__ unsigned packh2(float a, float b) {
    __half2 h = __floats2half2_rn(a, b);
    return *reinterpret_cast<unsigned*>(&h);
}
__device__ __forceinline__ void split_f(float v, __half& h, __half& l) {
    h = __float2half_rn(v);
    l = __float2half_rn(v - __half2float(h));
}

// --------------------------- split x ------------------------------------------
__global__ void __launch_bounds__(256)
split_hl_kernel(const float* __restrict__ in, __half* __restrict__ oh,
                __half* __restrict__ ol, int n4)
{
    int i = blockIdx.x * 256 + threadIdx.x;
    if (i >= n4) return;
    float4 v = ((const float4*)in)[i];
    __half hx, lx, hy, ly, hz, lz, hw, lw;
    split_f(v.x, hx, lx); split_f(v.y, hy, ly);
    split_f(v.z, hz, lz); split_f(v.w, hw, lw);
    ((__half2*)oh)[2 * i]     = __halves2half2(hx, hy);
    ((__half2*)oh)[2 * i + 1] = __halves2half2(hz, hw);
    ((__half2*)ol)[2 * i]     = __halves2half2(lx, ly);
    ((__half2*)ol)[2 * i + 1] = __halves2half2(lz, lw);
}

// --------------- transpose + split 4 weights: [K,N] -> [N,K] hi/lo -------------
__global__ void transpose_split_kernel(const float* __restrict__ W0,
                                       const float* __restrict__ W1,
                                       const float* __restrict__ W2,
                                       const float* __restrict__ W3,
                                       __half* __restrict__ th_base,
                                       __half* __restrict__ tl_base)
{
    __shared__ float s[32][33];
    const int z = blockIdx.z;
    const float* W = (z == 0) ? W0 : (z == 1) ? W1 : (z == 2) ? W2 : W3;
    __half* th = th_base + (size_t)z * DDIM * DDIM;
    __half* tl = tl_base + (size_t)z * DDIM * DDIM;
    int tx = threadIdx.x, ty = threadIdx.y;
#pragma unroll
    for (int i = 0; i < 4; ++i)
        s[ty + i * 8][tx] = W[(size_t)(blockIdx.y * 32 + ty + i * 8) * DDIM
                              + blockIdx.x * 32 + tx];
    __syncthreads();
    int xo = blockIdx.y * 32 + tx;
#pragma unroll
    for (int i = 0; i < 4; ++i) {
        int n = blockIdx.x * 32 + ty + i * 8;
        __half hh, ll;
        split_f(s[tx][ty + i * 8], hh, ll);
        th[(size_t)n * DDIM + xo] = hh;
        tl[(size_t)n * DDIM + xo] = ll;
    }
}

// --------------- relative-position bias, fp16 * log2e --------------------------
__global__ void __launch_bounds__(256)
bias_kernel(const float* __restrict__ Qb, const float* __restrict__ rel,
            __half* __restrict__ bias)
{
    __shared__ float srel[128];
    if (threadIdx.x < 128) srel[threadIdx.x] = rel[threadIdx.x];
    __syncthreads();
    size_t p = (size_t)blockIdx.x * 256 + threadIdx.x;
    float qb[8];
    *(float4*)qb       = *(const float4*)(Qb + p * 8);
    *(float4*)(qb + 4) = *(const float4*)(Qb + p * 8 + 4);
#pragma unroll
    for (int h = 0; h < 16; ++h) {
        float a = 0.f;
#pragma unroll
        for (int c = 0; c < 8; ++c) a += srel[c * 16 + h] * qb[c];
        bias[(size_t)h * SSEQ * SSEQ + p] = __float2half_rn(a * LOG2E);
    }
}

// ------------------ shared GEMM mainloop pieces --------------------------------
#define GRS 40
#define GARR (128 * GRS)
#define GSTG (4 * GARR)

// ---- fused QKV GEMM: [4096,1024] x [3072,1024]^T, epilogue = bias+LN+split ----
__global__ void __launch_bounds__(256, 2)
gemm_qkv_kernel(const __half* __restrict__ Ah, const __half* __restrict__ Al,
                const __half* __restrict__ Bh, const __half* __restrict__ Bl,
                const float* __restrict__ bq, const float* __restrict__ bk,
                const float* __restrict__ bv,
                const float* __restrict__ qs, const float* __restrict__ ks,
                __half* __restrict__ oqh, __half* __restrict__ oql,
                __half* __restrict__ okh, __half* __restrict__ okl,
                __half* __restrict__ ovh, __half* __restrict__ ovl)
{
    extern __shared__ __half gsm[];
    const int K = DDIM;
    const int tid = threadIdx.x;
    const int w = tid >> 5, t = tid & 31;
    const int wm = w & 3, wn = w >> 2;
    const int m0 = blockIdx.y * 128, n0 = blockIdx.x * 128;

    float acc[2][8][4];
#pragma unroll
    for (int a = 0; a < 2; ++a)
#pragma unroll
        for (int b = 0; b < 8; ++b)
#pragma unroll
            for (int c = 0; c < 4; ++c) acc[a][b][c] = 0.f;

    auto load_stage = [&](int s, int kt) {
        __half* p = gsm + s * GSTG;
#pragma unroll
        for (int it = 0; it < 2; ++it) {
            int idx = tid + it * 256;
            int r = idx >> 2, c8 = (idx & 3) * 8;
            cp16(p + 0 * GARR + r * GRS + c8, Ah + (size_t)(m0 + r) * K + kt + c8);
            cp16(p + 1 * GARR + r * GRS + c8, Al + (size_t)(m0 + r) * K + kt + c8);
            cp16(p + 2 * GARR + r * GRS + c8, Bh + (size_t)(n0 + r) * K + kt + c8);
            cp16(p + 3 * GARR + r * GRS + c8, Bl + (size_t)(n0 + r) * K + kt + c8);
        }
        cp_commit();
    };

    const int ar = t & 15, co = (t >> 4) << 3;
    const int ntiles = K / 32;

    load_stage(0, 0);
    for (int ti = 0; ti < ntiles; ++ti) {
        int s = ti & 1;
        if (ti + 1 < ntiles) { load_stage(s ^ 1, (ti + 1) * 32); cp_wait1(); }
        else                 { cp_wait0(); }
        __syncthreads();

        __half* pAh = gsm + s * GSTG;
        __half* pAl = pAh + GARR;
        __half* pBh = pAh + 2 * GARR;
        __half* pBl = pAh + 3 * GARR;
#pragma unroll
        for (int k16 = 0; k16 < 2; ++k16) {
            int ko = k16 * 16 + co;
            unsigned ah[2][4], al[2][4];
            ldsm4(ah[0], pAh + (wm * 32 + ar) * GRS + ko);
            ldsm4(ah[1], pAh + (wm * 32 + 16 + ar) * GRS + ko);
            ldsm4(al[0], pAl + (wm * 32 + ar) * GRS + ko);
            ldsm4(al[1], pAl + (wm * 32 + 16 + ar) * GRS + ko);
#pragma unroll
            for (int ni = 0; ni < 4; ++ni) {
                unsigned bh[4], bl[4];
                ldsm4(bh, pBh + (wn * 64 + ni * 16 + ar) * GRS + ko);
                ldsm4(bl, pBl + (wn * 64 + ni * 16 + ar) * GRS + ko);
#pragma unroll
                for (int mi = 0; mi < 2; ++mi) {  // distance-2 chains
                    mma16816(acc[mi][2 * ni],     ah[mi], bh[0], bh[2]);
                    mma16816(acc[mi][2 * ni + 1], ah[mi], bh[1], bh[3]);
                    mma16816(acc[mi][2 * ni],     ah[mi], bl[0], bl[2]);
                    mma16816(acc[mi][2 * ni + 1], ah[mi], bl[1], bl[3]);
                    mma16816(acc[mi][2 * ni],     al[mi], bh[0], bh[2]);
                    mma16816(acc[mi][2 * ni + 1], al[mi], bh[1], bh[3]);
                }
            }
        }
        __syncthreads();
    }

    // ---------------- epilogue: bias + (LN for q/k) + split + relayout ---------
    const int qr = t >> 2, qc = (t & 3) * 2;
    const int blk = n0 >> 10;                       // 0=q 1=k 2=v
    const int nin = n0 & 1023;
    const int hglob = (nin >> 6) + wn;              // global head
    const float* bias = (blk == 0) ? bq : (blk == 1) ? bk : bv;
    const float* scp  = (blk == 0) ? qs : ks;
    const float mult  = (blk == 0) ? 0.125f * LOG2E : 1.0f;
    __half* oh = (blk == 0) ? oqh : (blk == 1) ? okh : ovh;
    __half* ol = (blk == 0) ? oql : (blk == 1) ? okl : ovl;

    float bvv[8][2], scv[8][2];
#pragma unroll
    for (int j = 0; j < 8; ++j) {
        float2 bb = *(const float2*)&bias[nin + wn * 64 + j * 8 + qc];
        bvv[j][0] = bb.x; bvv[j][1] = bb.y;
        if (blk < 2) {
            float2 ss = *(const float2*)&scp[j * 8 + qc];
            scv[j][0] = ss.x; scv[j][1] = ss.y;
        }
    }

#pragma unroll
    for (int mi = 0; mi < 2; ++mi) {
#pragma unroll
        for (int rh = 0; rh < 2; ++rh) {
            int r0 = m0 + wm * 32 + mi * 16 + rh * 8 + qr;
            int b  = r0 >> 11, s = r0 & 2047;
            size_t obase = (((size_t)b * 16 + hglob) * 2048 + s) * 64;
            if (blk < 2) {
                float sm = 0.f, s2 = 0.f;
#pragma unroll
                for (int j = 0; j < 8; ++j) {
                    float v0 = acc[mi][j][2 * rh]     + bvv[j][0];
                    float v1 = acc[mi][j][2 * rh + 1] + bvv[j][1];
                    sm += v0 + v1; s2 += v0 * v0 + v1 * v1;
                }
                sm += __shfl_xor_sync(0xffffffffu, sm, 1);
                sm += __shfl_xor_sync(0xffffffffu, sm, 2);
                s2 += __shfl_xor_sync(0xffffffffu, s2, 1);
                s2 += __shfl_xor_sync(0xffffffffu, s2, 2);
                float mu = sm * (1.f / 64.f);
                float var = s2 * (1.f / 64.f) - mu * mu;
                float rin = rsqrtf(var + 1e-6f);
#pragma unroll
                for (int j = 0; j < 8; ++j) {
                    float v0 = acc[mi][j][2 * rh]     + bvv[j][0];
                    float v1 = acc[mi][j][2 * rh + 1] + bvv[j][1];
                    float y0 = (v0 - mu) * rin * scv[j][0] * mult;
                    float y1 = (v1 - mu) * rin * scv[j][1] * mult;
                    __half h0, l0, h1, l1;
                    split_f(y0, h0, l0); split_f(y1, h1, l1);
                    *(__half2*)(oh + obase + j * 8 + qc) = __halves2half2(h0, h1);
                    *(__half2*)(ol + obase + j * 8 + qc) = __halves2half2(l0, l1);
                }
            } else {
#pragma unroll
                for (int j = 0; j < 8; ++j) {
                    float y0 = acc[mi][j][2 * rh]     + bvv[j][0];
                    float y1 = acc[mi][j][2 * rh + 1] + bvv[j][1];
                    __half h0, l0, h1, l1;
                    split_f(y0, h0, l0); split_f(y1, h1, l1);
                    *(__half2*)(oh + obase + j * 8 + qc) = __halves2half2(h0, h1);
                    *(__half2*)(ol + obase + j * 8 + qc) = __halves2half2(l0, l1);
                }
            }
        }
    }
}

// ---- output GEMM: C[M,N] = (Ah+Al)(Bh+Bl)^T + bias, fp32 out ------------------
__global__ void __launch_bounds__(256, 2)
gemm3_kernel(const __half* __restrict__ Ah, const __half* __restrict__ Al,
             const __half* __restrict__ Bh, const __half* __restrict__ Bl,
             const float* __restrict__ bias, float* __restrict__ C,
             int M, int N, int K)
{
    extern __shared__ __half gsm[];
    const int tid = threadIdx.x;
    const int w = tid >> 5, t = tid & 31;
    const int wm = w & 3, wn = w >> 2;
    const int m0 = blockIdx.y * 128, n0 = blockIdx.x * 128;

    float acc[2][8][4];
#pragma unroll
    for (int a = 0; a < 2; ++a)
#pragma unroll
        for (int b = 0; b < 8; ++b)
#pragma unroll
            for (int c = 0; c < 4; ++c) acc[a][b][c] = 0.f;

    auto load_stage = [&](int s, int kt) {
        __half* p = gsm + s * GSTG;
#pragma unroll
        for (int it = 0; it < 2; ++it) {
            int idx = tid + it * 256;
            int r = idx >> 2, c8 = (idx & 3) * 8;
            cp16(p + 0 * GARR + r * GRS + c8, Ah + (size_t)(m0 + r) * K + kt + c8);
            cp16(p + 1 * GARR + r * GRS + c8, Al + (size_t)(m0 + r) * K + kt + c8);
            cp16(p + 2 * GARR + r * GRS + c8, Bh + (size_t)(n0 + r) * K + kt + c8);
            cp16(p + 3 * GARR + r * GRS + c8, Bl + (size_t)(n0 + r) * K + kt + c8);
        }
        cp_commit();
    };

    const int ar = t & 15, co = (t >> 4) << 3;
    const int ntiles = K / 32;

    load_stage(0, 0);
    for (int ti = 0; ti < ntiles; ++ti) {
        int s = ti & 1;
        if (ti + 1 < ntiles) { load_stage(s ^ 1, (ti + 1) * 32); cp_wait1(); }
        else                 { cp_wait0(); }
        __syncthreads();

        __half* pAh = gsm + s * GSTG;
        __half* pAl = pAh + GARR;
        __half* pBh = pAh + 2 * GARR;
        __half* pBl = pAh + 3 * GARR;
#pragma unroll
        for (int k16 = 0; k16 < 2; ++k16) {
            int ko = k16 * 16 + co;
            unsigned ah[2][4], al[2][4];
            ldsm4(ah[0], pAh + (wm * 32 + ar) * GRS + ko);
            ldsm4(ah[1], pAh + (wm * 32 + 16 + ar) * GRS + ko);
            ldsm4(al[0], pAl + (wm * 32 + ar) * GRS + ko);
            ldsm4(al[1], pAl + (wm * 32 + 16 + ar) * GRS + ko);
#pragma unroll
            for (int ni = 0; ni < 4; ++ni) {
                unsigned bh[4], bl[4];
                ldsm4(bh, pBh + (wn * 64 + ni * 16 + ar) * GRS + ko);
                ldsm4(bl, pBl + (wn * 64 + ni * 16 + ar) * GRS + ko);
#pragma unroll
                for (int mi = 0; mi < 2; ++mi) {
                    mma16816(acc[mi][2 * ni],     ah[mi], bh[0], bh[2]);
                    mma16816(acc[mi][2 * ni + 1], ah[mi], bh[1], bh[3]);
                    mma16816(acc[mi][2 * ni],     ah[mi], bl[0], bl[2]);
                    mma16816(acc[mi][2 * ni + 1], ah[mi], bl[1], bl[3]);
                    mma16816(acc[mi][2 * ni],     al[mi], bh[0], bh[2]);
                    mma16816(acc[mi][2 * ni + 1], al[mi], bh[1], bh[3]);
                }
            }
        }
        __syncthreads();
    }

    const int qr = t >> 2, qc = (t & 3) * 2;
#pragma unroll
    for (int mi = 0; mi < 2; ++mi) {
        int r0 = m0 + wm * 32 + mi * 16 + qr;
#pragma unroll
        for (int j = 0; j < 8; ++j) {
            int col = n0 + wn * 64 + j * 8 + qc;
            float2 bv = *(const float2*)&bias[col];
            float2 o0 = {acc[mi][j][0] + bv.x, acc[mi][j][1] + bv.y};
            float2 o1 = {acc[mi][j][2] + bv.x, acc[mi][j][3] + bv.y};
            *(float2*)&C[(size_t)r0 * N + col] = o0;
            *(float2*)&C[(size_t)(r0 + 8) * N + col] = o1;
        }
    }
}

// ---------------- flash attention, split-fp16 MMA, 2-stage pipeline ------------
#define ARS 72
#define AKV (64 * ARS)
#define ASTG (4 * AKV)

__global__ void __launch_bounds__(256)
attn_kernel(const __half* __restrict__ qh_, const __half* __restrict__ ql_,
            const __half* __restrict__ kh_, const __half* __restrict__ kl_,
            const __half* __restrict__ vh_, const __half* __restrict__ vl_,
            const __half* __restrict__ biasH,
            __half* __restrict__ ch_, __half* __restrict__ cl_)
{
    extern __shared__ __half smha[];

    const int tid = threadIdx.x, w = tid >> 5, t = tid & 31;
    const int q0 = blockIdx.x * 128, h = blockIdx.y, b = blockIdx.z;
    const size_t qb = (((size_t)b * HHEADS + h) * SSEQ + q0) * 64;
    const size_t kb = (((size_t)b * HHEADS + h) * SSEQ) * 64;

    auto load_kv = [&](int s, int kt) {
        __half* p = smha + s * ASTG;
        int r0 = tid >> 3, c8 = (tid & 7) * 8;
#pragma unroll
        for (int it = 0; it < 8; ++it) {
            const __half* src = (it < 2) ? kh_ : (it < 4) ? kl_
                              : (it < 6) ? vh_ : vl_;
            int arr = it >> 1;
            int r = ((it & 1) << 5) + r0;
            cp16(p + arr * AKV + r * ARS + c8,
                 src + kb + (size_t)(kt + r) * 64 + c8);
        }
        cp_commit();
    };

    load_kv(0, 0);

    __half* sQh = smha + ASTG;
    __half* sQl = sQh + 2 * AKV;
#pragma unroll
    for (int it = 0; it < 4; ++it) {
        int idx = tid + it * 256;
        int r = idx >> 3, c8 = (idx & 7) * 8;
        *(uint4*)(sQh + r * ARS + c8) = *(const uint4*)&qh_[qb + (size_t)r * 64 + c8];
        *(uint4*)(sQl + r * ARS + c8) = *(const uint4*)&ql_[qb + (size_t)r * 64 + c8];
    }
    __syncthreads();
    unsigned qfh[4][4], qfl[4][4];
    const int ar = t & 15, co = (t >> 4) << 3;
#pragma unroll
    for (int ki = 0; ki < 4; ++ki) {
        ldsm4(qfh[ki], sQh + (w * 16 + ar) * ARS + ki * 16 + co);
        ldsm4(qfl[ki], sQl + (w * 16 + ar) * ARS + ki * 16 + co);
    }
    __syncthreads();

    float m0v = -1e30f, m1v = -1e30f, l0 = 0.f, l1 = 0.f;
    float oc[8][4];
#pragma unroll
    for (int j = 0; j < 8; ++j)
#pragma unroll
        for (int c = 0; c < 4; ++c) oc[j][c] = 0.f;

    const int qr = t >> 2, qc = (t & 3) * 2;
    const size_t brow0 = ((size_t)h * SSEQ + (q0 + w * 16 + qr)) * SSEQ;
    const size_t brow1 = brow0 + 8ull * SSEQ;

    const int ntiles = SSEQ / 64;
    for (int ti = 0; ti < ntiles; ++ti) {
        int s = ti & 1;
        const int kt = ti * 64;

        // prefetch this tile's bias early: LDGs retire under cp.wait + MMAs
        unsigned braw0[8], braw1[8];
#pragma unroll
        for (int j = 0; j < 8; ++j) {
            braw0[j] = *(const unsigned*)&biasH[brow0 + kt + j * 8 + qc];
            braw1[j] = *(const unsigned*)&biasH[brow1 + kt + j * 8 + qc];
        }

        if (ti + 1 < ntiles) { load_kv(s ^ 1, (ti + 1) * 64); cp_wait1(); }
        else                 { cp_wait0(); }
        __syncthreads();

        __half* pKh = smha + s * ASTG;
        __half* pKl = pKh + AKV;
        __half* pVh = pKh + 2 * AKV;
        __half* pVl = pKh + 3 * AKV;

        float sc[8][4];
#pragma unroll
        for (int j = 0; j < 8; ++j)
#pragma unroll
            for (int c = 0; c < 4; ++c) sc[j][c] = 0.f;
#pragma unroll
        for (int ki = 0; ki < 4; ++ki) {
#pragma unroll
            for (int ni = 0; ni < 4; ++ni) {
                unsigned bh[4], bl[4];
                ldsm4(bh, pKh + (ni * 16 + ar) * ARS + ki * 16 + co);
                ldsm4(bl, pKl + (ni * 16 + ar) * ARS + ki * 16 + co);
                mma16816(sc[2 * ni],     qfh[ki], bh[0], bh[2]);
                mma16816(sc[2 * ni + 1], qfh[ki], bh[1], bh[3]);
                mma16816(sc[2 * ni],     qfh[ki], bl[0], bl[2]);
                mma16816(sc[2 * ni + 1], qfh[ki], bl[1], bl[3]);
                mma16816(sc[2 * ni],     qfl[ki], bh[0], bh[2]);
                mma16816(sc[2 * ni + 1], qfl[ki], bh[1], bh[3]);
            }
        }
#pragma unroll
        for (int j = 0; j < 8; ++j) {
            float2 f0 = __half22float2(*(__half2*)&braw0[j]);
            float2 f1 = __half22float2(*(__half2*)&braw1[j]);
            sc[j][0] += f0.x; sc[j][1] += f0.y; sc[j][2] += f1.x; sc[j][3] += f1.y;
        }

        float mx0 = -1e30f, mx1 = -1e30f;
#pragma unroll
        for (int j = 0; j < 8; ++j) {
            mx0 = fmaxf(mx0, fmaxf(sc[j][0], sc[j][1]));
            mx1 = fmaxf(mx1, fmaxf(sc[j][2], sc[j][3]));
        }
        mx0 = fmaxf(mx0, __shfl_xor_sync(0xffffffffu, mx0, 1));
        mx0 = fmaxf(mx0, __shfl_xor_sync(0xffffffffu, mx0, 2));
        mx1 = fmaxf(mx1, __shfl_xor_sync(0xffffffffu, mx1, 1));
        mx1 = fmaxf(mx1, __shfl_xor_sync(0xffffffffu, mx1, 2));
        float mn0 = fmaxf(m0v, mx0), mn1 = fmaxf(m1v, mx1);
        float a0 = exp2f(m0v - mn0), a1 = exp2f(m1v - mn1);
        m0v = mn0; m1v = mn1;

        float rs0 = 0.f, rs1 = 0.f;
        unsigned pa[4][4];
#pragma unroll
        for (int i = 0; i < 4; ++i) {
            int j0 = 2 * i, j1 = 2 * i + 1;
            float p0 = exp2f(sc[j0][0] - mn0), p1 = exp2f(sc[j0][1] - mn0);
            float p2 = exp2f(sc[j0][2] - mn1), p3 = exp2f(sc[j0][3] - mn1);
            float u0 = exp2f(sc[j1][0] - mn0), u1 = exp2f(sc[j1][1] - mn0);
            float u2 = exp2f(sc[j1][2] - mn1), u3 = exp2f(sc[j1][3] - mn1);
            rs0 += (p0 + p1) + (u0 + u1);
            rs1 += (p2 + p3) + (u2 + u3);
            pa[i][0] = packh2(p0, p1); pa[i][1] = packh2(p2, p3);
            pa[i][2] = packh2(u0, u1); pa[i][3] = packh2(u2, u3);
        }
        rs0 += __shfl_xor_sync(0xffffffffu, rs0, 1);
        rs0 += __shfl_xor_sync(0xffffffffu, rs0, 2);
        rs1 += __shfl_xor_sync(0xffffffffu, rs1, 1);
        rs1 += __shfl_xor_sync(0xffffffffu, rs1, 2);
        l0 = l0 * a0 + rs0;
        l1 = l1 * a1 + rs1;
#pragma unroll
        for (int j = 0; j < 8; ++j) {
            oc[j][0] *= a0; oc[j][1] *= a0; oc[j][2] *= a1; oc[j][3] *= a1;
        }
        {
            int sr0 = ((t >> 4) & 1) * 8 + (t & 7);
            int hco = ((t >> 3) & 1) * 8;
#pragma unroll
            for (int i = 0; i < 4; ++i) {
                int sr = i * 16 + sr0;
#pragma unroll
                for (int ni = 0; ni < 4; ++ni) {
                    unsigned v4h[4], v4l[4];
                    ldsm4t(v4h, pVh + sr * ARS + ni * 16 + hco);
                    ldsm4t(v4l, pVl + sr * ARS + ni * 16 + hco);
                    mma16816(oc[2 * ni],     pa[i], v4h[0], v4h[2]);
                    mma16816(oc[2 * ni + 1], pa[i], v4h[1], v4h[3]);
                    mma16816(oc[2 * ni],     pa[i], v4l[0], v4l[2]);
                    mma16816(oc[2 * ni + 1], pa[i], v4l[1], v4l[3]);
                }
            }
        }
        __syncthreads();
    }

    float inv0 = 1.f / l0, inv1 = 1.f / l1;
    int r0 = q0 + w * 16 + qr;
    size_t ob0 = (((size_t)b * SSEQ + r0) * HHEADS + h) * 64;
    size_t ob1 = (((size_t)b * SSEQ + r0 + 8) * HHEADS + h) * 64;
#pragma unroll
    for (int j = 0; j < 8; ++j) {
        int col = j * 8 + qc;
        float f0 = oc[j][0] * inv0, f1 = oc[j][1] * inv0;
        float f2 = oc[j][2] * inv1, f3 = oc[j][3] * inv1;
        __half h0, e0, h1, e1, h2, e2, h3, e3;
        split_f(f0, h0, e0); split_f(f1, h1, e1);
        split_f(f2, h2, e2); split_f(f3, h3, e3);
        *(__half2*)(ch_ + ob0 + col) = __halves2half2(h0, h1);
        *(__half2*)(cl_ + ob0 + col) = __halves2half2(e0, e1);
        *(__half2*)(ch_ + ob1 + col) = __halves2half2(h2, h3);
        *(__half2*)(cl_ + ob1 + col) = __halves2half2(e2, e3);
    }
}

// ------------------------------- launcher --------------------------------------
extern "C" void kernel_launch(void* const* d_in, const int* in_sizes, int n_in,
                              void* d_out, int out_size)
{
    (void)in_sizes; (void)n_in; (void)out_size;
    const float* x   = (const float*)d_in[0];
    const float* Qb  = (const float*)d_in[1];
    const float* Wq  = (const float*)d_in[2];
    const float* bq  = (const float*)d_in[3];
    const float* Wk  = (const float*)d_in[4];
    const float* bk  = (const float*)d_in[5];
    const float* Wv  = (const float*)d_in[6];
    const float* bv  = (const float*)d_in[7];
    const float* qs  = (const float*)d_in[8];
    const float* ks  = (const float*)d_in[9];
    const float* rel = (const float*)d_in[10];
    const float* Wo  = (const float*)d_in[11];
    const float* bo  = (const float*)d_in[12];
    float* out = (float*)d_out;

    __half *xh, *xl, *wth, *wtl, *qh, *ql, *kh, *kl, *vh, *vl, *bH, *ch, *cl;
    cudaGetSymbolAddress((void**)&xh,  g_xh);
    cudaGetSymbolAddress((void**)&xl,  g_xl);
    cudaGetSymbolAddress((void**)&wth, g_wth);
    cudaGetSymbolAddress((void**)&wtl, g_wtl);
    cudaGetSymbolAddress((void**)&qh,  g_qh);
    cudaGetSymbolAddress((void**)&ql,  g_ql);
    cudaGetSymbolAddress((void**)&kh,  g_kh);
    cudaGetSymbolAddress((void**)&kl,  g_kl);
    cudaGetSymbolAddress((void**)&vh,  g_vh);
    cudaGetSymbolAddress((void**)&vl,  g_vl);
    cudaGetSymbolAddress((void**)&bH,  g_biasH);
    cudaGetSymbolAddress((void**)&ch,  g_ch);
    cudaGetSymbolAddress((void**)&cl,  g_cl);

    const int MM = 1024 * 1024;
    const int GS = 2 * GSTG * (int)sizeof(__half);   // 81920 B
    const int AS = 2 * ASTG * (int)sizeof(__half);   // 73728 B
    cudaFuncSetAttribute(gemm_qkv_kernel,
                         cudaFuncAttributeMaxDynamicSharedMemorySize, GS);
    cudaFuncSetAttribute(gemm3_kernel,
                         cudaFuncAttributeMaxDynamicSharedMemorySize, GS);
    cudaFuncSetAttribute(attn_kernel,
                         cudaFuncAttributeMaxDynamicSharedMemorySize, AS);

    // prep
    split_hl_kernel<<<(MROWS * DDIM / 4 + 255) / 256, 256>>>(x, xh, xl,
                                                             MROWS * DDIM / 4);
    dim3 tb(32, 8), tg(32, 32, 4);
    transpose_split_kernel<<<tg, tb>>>(Wq, Wk, Wv, Wo, wth, wtl);
    bias_kernel<<<(SSEQ * SSEQ) / 256, 256>>>(Qb, rel, bH);

    // fused QKV projection + LN + split + relayout  (B rows 0..3071 = Wq|Wk|Wv)
    dim3 gqkv(3 * DDIM / 128, MROWS / 128);          // (24, 32)
    gemm_qkv_kernel<<<gqkv, 256, GS>>>(xh, xl, wth, wtl, bq, bk, bv, qs, ks,
                                       qh, ql, kh, kl, vh, vl);

    // attention
    attn_kernel<<<dim3(SSEQ / 128, HHEADS, BBATCH), 256, AS>>>(qh, ql, kh, kl,
                                                               vh, vl, bH, ch, cl);

    // output projection
    dim3 gg(DDIM / 128, MROWS / 128);
    gemm3_kernel<<<gg, 256, GS>>>(ch, cl, wth + 3 * MM, wtl + 3 * MM, bo, out,
                                  MROWS, DDIM, DDIM);
}

// round 12
// speedup vs baseline: 2.5301x; 1.0892x over previous
#include <cuda_runtime.h>
#include <cuda_fp16.h>
#include <cstdint>

#define BBATCH 2
#define SSEQ 2048
#define DDIM 1024
#define HHEADS 16
#define MROWS (BBATCH * SSEQ)
#define LOG2E 1.4426950408889634f

// ------------------------------ scratch ---------------------------------------
__device__ __align__(16) __half g_xh[MROWS * DDIM];
__device__ __align__(16) __half g_xl[MROWS * DDIM];
__device__ __align__(16) __half g_wth[4 * DDIM * DDIM];
__device__ __align__(16) __half g_wtl[4 * DDIM * DDIM];
__device__ __align__(16) __half g_qh[MROWS * DDIM];
__device__ __align__(16) __half g_ql[MROWS * DDIM];
__device__ __align__(16) __half g_kh[MROWS * DDIM];
__device__ __align__(16) __half g_kl[MROWS * DDIM];
__device__ __align__(16) __half g_vh[MROWS * DDIM];
__device__ __align__(16) __half g_vl[MROWS * DDIM];
__device__ __align__(16) __half g_biasH[(size_t)HHEADS * SSEQ * SSEQ];
__device__ __align__(16) __half g_ch[MROWS * DDIM];
__device__ __align__(16) __half g_cl[MROWS * DDIM];

// ------------------------------ helpers ---------------------------------------
__device__ __forceinline__ void ldsm4(unsigned* r, const void* p) {
    unsigned a = (unsigned)__cvta_generic_to_shared(p);
    asm volatile("ldmatrix.sync.aligned.m8n8.x4.shared.b16 {%0,%1,%2,%3}, [%4];"
                 : "=r"(r[0]), "=r"(r[1]), "=r"(r[2]), "=r"(r[3]) : "r"(a));
}
__device__ __forceinline__ void ldsm4t(unsigned* r, const void* p) {
    unsigned a = (unsigned)__cvta_generic_to_shared(p);
    asm volatile("ldmatrix.sync.aligned.m8n8.x4.trans.shared.b16 {%0,%1,%2,%3}, [%4];"
                 : "=r"(r[0]), "=r"(r[1]), "=r"(r[2]), "=r"(r[3]) : "r"(a));
}
// NOT volatile: register-only op; ptxas may interleave independent chains.
__device__ __forceinline__ void mma16816(float* c, const unsigned* a,
                                         unsigned b0, unsigned b1) {
    asm("mma.sync.aligned.m16n8k16.row.col.f32.f16.f16.f32 "
        "{%0,%1,%2,%3}, {%4,%5,%6,%7}, {%8,%9}, {%0,%1,%2,%3};"
        : "+f"(c[0]), "+f"(c[1]), "+f"(c[2]), "+f"(c[3])
        : "r"(a[0]), "r"(a[1]), "r"(a[2]), "r"(a[3]), "r"(b0), "r"(b1));
}
__device__ __forceinline__ void cp16p(void* smem, const void* gmem) {
    unsigned s = (unsigned)__cvta_generic_to_shared(smem);
    asm volatile("cp.async.cg.shared.global [%0], [%1], 16;" :: "r"(s), "l"(gmem));
}
__device__ __forceinline__ void cp_commit() { asm volatile("cp.async.commit_group;"); }
__device__ __forceinline__ void cp_wait0()  { asm volatile("cp.async.wait_group 0;"); }
__device__ __forceinline__ void cp_wait1()  { asm volatile("cp.async.wait_group 1;"); }
__device__ __forceinline__ unsigned packh2(float a, float b) {
    __half2 h = __floats2half2_rn(a, b);
    return *reinterpret_cast<unsigned*>(&h);
}
__device__ __forceinline__ void split_f(float v, __half& h, __half& l) {
    h = __float2half_rn(v);
    l = __float2half_rn(v - __half2float(h));
}

// --------------------------- split x ------------------------------------------
__global__ void __launch_bounds__(256)
split_hl_kernel(const float* __restrict__ in, __half* __restrict__ oh,
                __half* __restrict__ ol, int n4)
{
    int i = blockIdx.x * 256 + threadIdx.x;
    if (i >= n4) return;
    float4 v = ((const float4*)in)[i];
    __half hx, lx, hy, ly, hz, lz, hw, lw;
    split_f(v.x, hx, lx); split_f(v.y, hy, ly);
    split_f(v.z, hz, lz); split_f(v.w, hw, lw);
    ((__half2*)oh)[2 * i]     = __halves2half2(hx, hy);
    ((__half2*)oh)[2 * i + 1] = __halves2half2(hz, hw);
    ((__half2*)ol)[2 * i]     = __halves2half2(lx, ly);
    ((__half2*)ol)[2 * i + 1] = __halves2half2(lz, lw);
}

// --------------- transpose + split 4 weights: [K,N] -> [N,K] hi/lo -------------
__global__ void transpose_split_kernel(const float* __restrict__ W0,
                                       const float* __restrict__ W1,
                                       const float* __restrict__ W2,
                                       const float* __restrict__ W3,
                                       __half* __restrict__ th_base,
                                       __half* __restrict__ tl_base)
{
    __shared__ float s[32][33];
    const int z = blockIdx.z;
    const float* W = (z == 0) ? W0 : (z == 1) ? W1 : (z == 2) ? W2 : W3;
    __half* th = th_base + (size_t)z * DDIM * DDIM;
    __half* tl = tl_base + (size_t)z * DDIM * DDIM;
    int tx = threadIdx.x, ty = threadIdx.y;
#pragma unroll
    for (int i = 0; i < 4; ++i)
        s[ty + i * 8][tx] = W[(size_t)(blockIdx.y * 32 + ty + i * 8) * DDIM
                              + blockIdx.x * 32 + tx];
    __syncthreads();
    int xo = blockIdx.y * 32 + tx;
#pragma unroll
    for (int i = 0; i < 4; ++i) {
        int n = blockIdx.x * 32 + ty + i * 8;
        __half hh, ll;
        split_f(s[tx][ty + i * 8], hh, ll);
        th[(size_t)n * DDIM + xo] = hh;
        tl[(size_t)n * DDIM + xo] = ll;
    }
}

// --------------- relative-position bias, fp16 * log2e --------------------------
__global__ void __launch_bounds__(256)
bias_kernel(const float* __restrict__ Qb, const float* __restrict__ rel,
            __half* __restrict__ bias)
{
    __shared__ float srel[128];
    if (threadIdx.x < 128) srel[threadIdx.x] = rel[threadIdx.x];
    __syncthreads();
    size_t p = (size_t)blockIdx.x * 256 + threadIdx.x;
    float qb[8];
    *(float4*)qb       = *(const float4*)(Qb + p * 8);
    *(float4*)(qb + 4) = *(const float4*)(Qb + p * 8 + 4);
#pragma unroll
    for (int h = 0; h < 16; ++h) {
        float a = 0.f;
#pragma unroll
        for (int c = 0; c < 8; ++c) a += srel[c * 16 + h] * qb[c];
        bias[(size_t)h * SSEQ * SSEQ + p] = __float2half_rn(a * LOG2E);
    }
}

// ------------------ shared GEMM mainloop pieces --------------------------------
#define GRS 40
#define GARR (128 * GRS)
#define GSTG (4 * GARR)

// ---- fused QKV GEMM: [4096,1024] x [3072,1024]^T, epilogue = bias+LN+split ----
__global__ void __launch_bounds__(256, 2)
gemm_qkv_kernel(const __half* __restrict__ Ah, const __half* __restrict__ Al,
                const __half* __restrict__ Bh, const __half* __restrict__ Bl,
                const float* __restrict__ bq, const float* __restrict__ bk,
                const float* __restrict__ bv,
                const float* __restrict__ qs, const float* __restrict__ ks,
                __half* __restrict__ oqh, __half* __restrict__ oql,
                __half* __restrict__ okh, __half* __restrict__ okl,
                __half* __restrict__ ovh, __half* __restrict__ ovl)
{
    extern __shared__ __half gsm[];
    const int K = DDIM;
    const int tid = threadIdx.x;
    const int w = tid >> 5, t = tid & 31;
    const int wm = w & 3, wn = w >> 2;
    const int m0 = blockIdx.y * 128, n0 = blockIdx.x * 128;

    float acc[2][8][4];
#pragma unroll
    for (int a = 0; a < 2; ++a)
#pragma unroll
        for (int b = 0; b < 8; ++b)
#pragma unroll
            for (int c = 0; c < 4; ++c) acc[a][b][c] = 0.f;

    auto load_stage = [&](int s, int kt) {
        __half* p = gsm + s * GSTG;
#pragma unroll
        for (int it = 0; it < 2; ++it) {
            int idx = tid + it * 256;
            int r = idx >> 2, c8 = (idx & 3) * 8;
            cp16p(p + 0 * GARR + r * GRS + c8, Ah + (size_t)(m0 + r) * K + kt + c8);
            cp16p(p + 1 * GARR + r * GRS + c8, Al + (size_t)(m0 + r) * K + kt + c8);
            cp16p(p + 2 * GARR + r * GRS + c8, Bh + (size_t)(n0 + r) * K + kt + c8);
            cp16p(p + 3 * GARR + r * GRS + c8, Bl + (size_t)(n0 + r) * K + kt + c8);
        }
        cp_commit();
    };

    const int ar = t & 15, co = (t >> 4) << 3;
    const int ntiles = K / 32;

    load_stage(0, 0);
    for (int ti = 0; ti < ntiles; ++ti) {
        int s = ti & 1;
        if (ti + 1 < ntiles) { load_stage(s ^ 1, (ti + 1) * 32); cp_wait1(); }
        else                 { cp_wait0(); }
        __syncthreads();

        __half* pAh = gsm + s * GSTG;
        __half* pAl = pAh + GARR;
        __half* pBh = pAh + 2 * GARR;
        __half* pBl = pAh + 3 * GARR;
#pragma unroll
        for (int k16 = 0; k16 < 2; ++k16) {
            int ko = k16 * 16 + co;
            unsigned ah[2][4], al[2][4];
            ldsm4(ah[0], pAh + (wm * 32 + ar) * GRS + ko);
            ldsm4(ah[1], pAh + (wm * 32 + 16 + ar) * GRS + ko);
            ldsm4(al[0], pAl + (wm * 32 + ar) * GRS + ko);
            ldsm4(al[1], pAl + (wm * 32 + 16 + ar) * GRS + ko);
#pragma unroll
            for (int ni = 0; ni < 4; ++ni) {
                unsigned bh[4], bl[4];
                ldsm4(bh, pBh + (wn * 64 + ni * 16 + ar) * GRS + ko);
                ldsm4(bl, pBl + (wn * 64 + ni * 16 + ar) * GRS + ko);
#pragma unroll
                for (int mi = 0; mi < 2; ++mi) {
                    mma16816(acc[mi][2 * ni],     ah[mi], bh[0], bh[2]);
                    mma16816(acc[mi][2 * ni + 1], ah[mi], bh[1], bh[3]);
                    mma16816(acc[mi][2 * ni],     ah[mi], bl[0], bl[2]);
                    mma16816(acc[mi][2 * ni + 1], ah[mi], bl[1], bl[3]);
                    mma16816(acc[mi][2 * ni],     al[mi], bh[0], bh[2]);
                    mma16816(acc[mi][2 * ni + 1], al[mi], bh[1], bh[3]);
                }
            }
        }
        __syncthreads();
    }

    // ---------------- epilogue: bias + (LN for q/k) + split + relayout ---------
    const int qr = t >> 2, qc = (t & 3) * 2;
    const int blk = n0 >> 10;                       // 0=q 1=k 2=v
    const int nin = n0 & 1023;
    const int hglob = (nin >> 6) + wn;              // global head
    const float* bias = (blk == 0) ? bq : (blk == 1) ? bk : bv;
    const float* scp  = (blk == 0) ? qs : ks;
    const float mult  = (blk == 0) ? 0.125f * LOG2E : 1.0f;
    __half* oh = (blk == 0) ? oqh : (blk == 1) ? okh : ovh;
    __half* ol = (blk == 0) ? oql : (blk == 1) ? okl : ovl;

    float bvv[8][2], scv[8][2];
#pragma unroll
    for (int j = 0; j < 8; ++j) {
        float2 bb = *(const float2*)&bias[nin + wn * 64 + j * 8 + qc];
        bvv[j][0] = bb.x; bvv[j][1] = bb.y;
        if (blk < 2) {
            float2 ss = *(const float2*)&scp[j * 8 + qc];
            scv[j][0] = ss.x; scv[j][1] = ss.y;
        }
    }

#pragma unroll
    for (int mi = 0; mi < 2; ++mi) {
#pragma unroll
        for (int rh = 0; rh < 2; ++rh) {
            int r0 = m0 + wm * 32 + mi * 16 + rh * 8 + qr;
            int b  = r0 >> 11, s = r0 & 2047;
            size_t obase = (((size_t)b * 16 + hglob) * 2048 + s) * 64;
            if (blk < 2) {
                float sm = 0.f, s2 = 0.f;
#pragma unroll
                for (int j = 0; j < 8; ++j) {
                    float v0 = acc[mi][j][2 * rh]     + bvv[j][0];
                    float v1 = acc[mi][j][2 * rh + 1] + bvv[j][1];
                    sm += v0 + v1; s2 += v0 * v0 + v1 * v1;
                }
                sm += __shfl_xor_sync(0xffffffffu, sm, 1);
                sm += __shfl_xor_sync(0xffffffffu, sm, 2);
                s2 += __shfl_xor_sync(0xffffffffu, s2, 1);
                s2 += __shfl_xor_sync(0xffffffffu, s2, 2);
                float mu = sm * (1.f / 64.f);
                float var = s2 * (1.f / 64.f) - mu * mu;
                float rin = rsqrtf(var + 1e-6f);
#pragma unroll
                for (int j = 0; j < 8; ++j) {
                    float v0 = acc[mi][j][2 * rh]     + bvv[j][0];
                    float v1 = acc[mi][j][2 * rh + 1] + bvv[j][1];
                    float y0 = (v0 - mu) * rin * scv[j][0] * mult;
                    float y1 = (v1 - mu) * rin * scv[j][1] * mult;
                    __half h0, l0, h1, l1;
                    split_f(y0, h0, l0); split_f(y1, h1, l1);
                    *(__half2*)(oh + obase + j * 8 + qc) = __halves2half2(h0, h1);
                    *(__half2*)(ol + obase + j * 8 + qc) = __halves2half2(l0, l1);
                }
            } else {
#pragma unroll
                for (int j = 0; j < 8; ++j) {
                    float y0 = acc[mi][j][2 * rh]     + bvv[j][0];
                    float y1 = acc[mi][j][2 * rh + 1] + bvv[j][1];
                    __half h0, l0, h1, l1;
                    split_f(y0, h0, l0); split_f(y1, h1, l1);
                    *(__half2*)(oh + obase + j * 8 + qc) = __halves2half2(h0, h1);
                    *(__half2*)(ol + obase + j * 8 + qc) = __halves2half2(l0, l1);
                }
            }
        }
    }
}

// ---- output GEMM: C[M,N] = (Ah+Al)(Bh+Bl)^T + bias, fp32 out ------------------
__global__ void __launch_bounds__(256, 2)
gemm3_kernel(const __half* __restrict__ Ah, const __half* __restrict__ Al,
             const __half* __restrict__ Bh, const __half* __restrict__ Bl,
             const float* __restrict__ bias, float* __restrict__ C,
             int M, int N, int K)
{
    extern __shared__ __half gsm[];
    const int tid = threadIdx.x;
    const int w = tid >> 5, t = tid & 31;
    const int wm = w & 3, wn = w >> 2;
    const int m0 = blockIdx.y * 128, n0 = blockIdx.x * 128;

    float acc[2][8][4];
#pragma unroll
    for (int a = 0; a < 2; ++a)
#pragma unroll
        for (int b = 0; b < 8; ++b)
#pragma unroll
            for (int c = 0; c < 4; ++c) acc[a][b][c] = 0.f;

    auto load_stage = [&](int s, int kt) {
        __half* p = gsm + s * GSTG;
#pragma unroll
        for (int it = 0; it < 2; ++it) {
            int idx = tid + it * 256;
            int r = idx >> 2, c8 = (idx & 3) * 8;
            cp16p(p + 0 * GARR + r * GRS + c8, Ah + (size_t)(m0 + r) * K + kt + c8);
            cp16p(p + 1 * GARR + r * GRS + c8, Al + (size_t)(m0 + r) * K + kt + c8);
            cp16p(p + 2 * GARR + r * GRS + c8, Bh + (size_t)(n0 + r) * K + kt + c8);
            cp16p(p + 3 * GARR + r * GRS + c8, Bl + (size_t)(n0 + r) * K + kt + c8);
        }
        cp_commit();
    };

    const int ar = t & 15, co = (t >> 4) << 3;
    const int ntiles = K / 32;

    load_stage(0, 0);
    for (int ti = 0; ti < ntiles; ++ti) {
        int s = ti & 1;
        if (ti + 1 < ntiles) { load_stage(s ^ 1, (ti + 1) * 32); cp_wait1(); }
        else                 { cp_wait0(); }
        __syncthreads();

        __half* pAh = gsm + s * GSTG;
        __half* pAl = pAh + GARR;
        __half* pBh = pAh + 2 * GARR;
        __half* pBl = pAh + 3 * GARR;
#pragma unroll
        for (int k16 = 0; k16 < 2; ++k16) {
            int ko = k16 * 16 + co;
            unsigned ah[2][4], al[2][4];
            ldsm4(ah[0], pAh + (wm * 32 + ar) * GRS + ko);
            ldsm4(ah[1], pAh + (wm * 32 + 16 + ar) * GRS + ko);
            ldsm4(al[0], pAl + (wm * 32 + ar) * GRS + ko);
            ldsm4(al[1], pAl + (wm * 32 + 16 + ar) * GRS + ko);
#pragma unroll
            for (int ni = 0; ni < 4; ++ni) {
                unsigned bh[4], bl[4];
                ldsm4(bh, pBh + (wn * 64 + ni * 16 + ar) * GRS + ko);
                ldsm4(bl, pBl + (wn * 64 + ni * 16 + ar) * GRS + ko);
#pragma unroll
                for (int mi = 0; mi < 2; ++mi) {
                    mma16816(acc[mi][2 * ni],     ah[mi], bh[0], bh[2]);
                    mma16816(acc[mi][2 * ni + 1], ah[mi], bh[1], bh[3]);
                    mma16816(acc[mi][2 * ni],     ah[mi], bl[0], bl[2]);
                    mma16816(acc[mi][2 * ni + 1], ah[mi], bl[1], bl[3]);
                    mma16816(acc[mi][2 * ni],     al[mi], bh[0], bh[2]);
                    mma16816(acc[mi][2 * ni + 1], al[mi], bh[1], bh[3]);
                }
            }
        }
        __syncthreads();
    }

    const int qr = t >> 2, qc = (t & 3) * 2;
#pragma unroll
    for (int mi = 0; mi < 2; ++mi) {
        int r0 = m0 + wm * 32 + mi * 16 + qr;
#pragma unroll
        for (int j = 0; j < 8; ++j) {
            int col = n0 + wn * 64 + j * 8 + qc;
            float2 bv = *(const float2*)&bias[col];
            float2 o0 = {acc[mi][j][0] + bv.x, acc[mi][j][1] + bv.y};
            float2 o1 = {acc[mi][j][2] + bv.x, acc[mi][j][3] + bv.y};
            *(float2*)&C[(size_t)r0 * N + col] = o0;
            *(float2*)&C[(size_t)(r0 + 8) * N + col] = o1;
        }
    }
}

// ------- flash attention: 512 threads, q-tile 256, split-fp16 MMA --------------
#define ARS 72
#define AKV (64 * ARS)
#define ASTG (4 * AKV)          // one KV stage: 18432 halves = 36864 B

__global__ void __launch_bounds__(512, 1)
attn_kernel(const __half* __restrict__ qh_, const __half* __restrict__ ql_,
            const __half* __restrict__ kh_, const __half* __restrict__ kl_,
            const __half* __restrict__ vh_, const __half* __restrict__ vl_,
            const __half* __restrict__ biasH,
            __half* __restrict__ ch_, __half* __restrict__ cl_)
{
    extern __shared__ __half smha[];

    const int tid = threadIdx.x, w = tid >> 5, t = tid & 31;
    const int q0 = blockIdx.x * 256, h = blockIdx.y, b = blockIdx.z;
    const size_t qb = (((size_t)b * HHEADS + h) * SSEQ + q0) * 64;
    const size_t kb = (((size_t)b * HHEADS + h) * SSEQ) * 64;

    // ---- stage Q (256 rows, hi+lo) into the FULL 2-stage region, consume ------
    {
        __half* sQh = smha;                 // 256*ARS = 18432 halves
        __half* sQl = smha + 256 * ARS;     // next 18432 halves
#pragma unroll
        for (int it = 0; it < 8; ++it) {
            int idx = tid + it * 512;       // 4096 uint4 ops
            int arrQ = idx >> 11;           // 0=hi, 1=lo
            int r = (idx >> 3) & 255, c8 = (idx & 7) * 8;
            const __half* src = arrQ ? ql_ : qh_;
            __half* dst = arrQ ? sQl : sQh;
            *(uint4*)(dst + r * ARS + c8) = *(const uint4*)&src[qb + (size_t)r * 64 + c8];
        }
    }
    __syncthreads();
    unsigned qfh[4][4], qfl[4][4];
    const int ar = t & 15, co = (t >> 4) << 3;
#pragma unroll
    for (int ki = 0; ki < 4; ++ki) {
        ldsm4(qfh[ki], smha + (w * 16 + ar) * ARS + ki * 16 + co);
        ldsm4(qfl[ki], smha + 256 * ARS + (w * 16 + ar) * ARS + ki * 16 + co);
    }
    __syncthreads();   // Q consumed; smem free for KV stages

    auto load_kv = [&](int s, int kt) {
        __half* p = smha + s * ASTG;
#pragma unroll
        for (int it = 0; it < 4; ++it) {
            int idx = tid + it * 512;       // 2048 = 4 arrays x 64 rows x 8 c8
            int arr = idx >> 9;
            int r = (idx >> 3) & 63, c8 = (idx & 7) * 8;
            const __half* src = (arr == 0) ? kh_ : (arr == 1) ? kl_
                              : (arr == 2) ? vh_ : vl_;
            cp16p(p + arr * AKV + r * ARS + c8,
                  src + kb + (size_t)(kt + r) * 64 + c8);
        }
        cp_commit();
    };

    load_kv(0, 0);

    float m0v = -1e30f, m1v = -1e30f, l0 = 0.f, l1 = 0.f;
    float oc[8][4];
#pragma unroll
    for (int j = 0; j < 8; ++j)
#pragma unroll
        for (int c = 0; c < 4; ++c) oc[j][c] = 0.f;

    const int qr = t >> 2, qc = (t & 3) * 2;
    const size_t brow0 = ((size_t)h * SSEQ + (q0 + w * 16 + qr)) * SSEQ;
    const size_t brow1 = brow0 + 8ull * SSEQ;

    const int ntiles = SSEQ / 64;
    for (int ti = 0; ti < ntiles; ++ti) {
        int s = ti & 1;
        const int kt = ti * 64;

        unsigned braw0[8], braw1[8];
#pragma unroll
        for (int j = 0; j < 8; ++j) {
            braw0[j] = *(const unsigned*)&biasH[brow0 + kt + j * 8 + qc];
            braw1[j] = *(const unsigned*)&biasH[brow1 + kt + j * 8 + qc];
        }

        if (ti + 1 < ntiles) { load_kv(s ^ 1, (ti + 1) * 64); cp_wait1(); }
        else                 { cp_wait0(); }
        __syncthreads();

        __half* pKh = smha + s * ASTG;
        __half* pKl = pKh + AKV;
        __half* pVh = pKh + 2 * AKV;
        __half* pVl = pKh + 3 * AKV;

        float sc[8][4];
#pragma unroll
        for (int j = 0; j < 8; ++j)
#pragma unroll
            for (int c = 0; c < 4; ++c) sc[j][c] = 0.f;
#pragma unroll
        for (int ki = 0; ki < 4; ++ki) {
#pragma unroll
            for (int ni = 0; ni < 4; ++ni) {
                unsigned bh[4], bl[4];
                ldsm4(bh, pKh + (ni * 16 + ar) * ARS + ki * 16 + co);
                ldsm4(bl, pKl + (ni * 16 + ar) * ARS + ki * 16 + co);
                mma16816(sc[2 * ni],     qfh[ki], bh[0], bh[2]);
                mma16816(sc[2 * ni + 1], qfh[ki], bh[1], bh[3]);
                mma16816(sc[2 * ni],     qfh[ki], bl[0], bl[2]);
                mma16816(sc[2 * ni + 1], qfh[ki], bl[1], bl[3]);
                mma16816(sc[2 * ni],     qfl[ki], bh[0], bh[2]);
                mma16816(sc[2 * ni + 1], qfl[ki], bh[1], bh[3]);
            }
        }
#pragma unroll
        for (int j = 0; j < 8; ++j) {
            float2 f0 = __half22float2(*(__half2*)&braw0[j]);
            float2 f1 = __half22float2(*(__half2*)&braw1[j]);
            sc[j][0] += f0.x; sc[j][1] += f0.y; sc[j][2] += f1.x; sc[j][3] += f1.y;
        }

        float mx0 = -1e30f, mx1 = -1e30f;
#pragma unroll
        for (int j = 0; j < 8; ++j) {
            mx0 = fmaxf(mx0, fmaxf(sc[j][0], sc[j][1]));
            mx1 = fmaxf(mx1, fmaxf(sc[j][2], sc[j][3]));
        }
        mx0 = fmaxf(mx0, __shfl_xor_sync(0xffffffffu, mx0, 1));
        mx0 = fmaxf(mx0, __shfl_xor_sync(0xffffffffu, mx0, 2));
        mx1 = fmaxf(mx1, __shfl_xor_sync(0xffffffffu, mx1, 1));
        mx1 = fmaxf(mx1, __shfl_xor_sync(0xffffffffu, mx1, 2));
        float mn0 = fmaxf(m0v, mx0), mn1 = fmaxf(m1v, mx1);
        float a0 = exp2f(m0v - mn0), a1 = exp2f(m1v - mn1);
        m0v = mn0; m1v = mn1;

        float rs0 = 0.f, rs1 = 0.f;
        unsigned pa[4][4];
#pragma unroll
        for (int i = 0; i < 4; ++i) {
            int j0 = 2 * i, j1 = 2 * i + 1;
            float p0 = exp2f(sc[j0][0] - mn0), p1 = exp2f(sc[j0][1] - mn0);
            float p2 = exp2f(sc[j0][2] - mn1), p3 = exp2f(sc[j0][3] - mn1);
            float u0 = exp2f(sc[j1][0] - mn0), u1 = exp2f(sc[j1][1] - mn0);
            float u2 = exp2f(sc[j1][2] - mn1), u3 = exp2f(sc[j1][3] - mn1);
            rs0 += (p0 + p1) + (u0 + u1);
            rs1 += (p2 + p3) + (u2 + u3);
            pa[i][0] = packh2(p0, p1); pa[i][1] = packh2(p2, p3);
            pa[i][2] = packh2(u0, u1); pa[i][3] = packh2(u2, u3);
        }
        rs0 += __shfl_xor_sync(0xffffffffu, rs0, 1);
        rs0 += __shfl_xor_sync(0xffffffffu, rs0, 2);
        rs1 += __shfl_xor_sync(0xffffffffu, rs1, 1);
        rs1 += __shfl_xor_sync(0xffffffffu, rs1, 2);
        l0 = l0 * a0 + rs0;
        l1 = l1 * a1 + rs1;
#pragma unroll
        for (int j = 0; j < 8; ++j) {
            oc[j][0] *= a0; oc[j][1] *= a0; oc[j][2] *= a1; oc[j][3] *= a1;
        }
        {
            int sr0 = ((t >> 4) & 1) * 8 + (t & 7);
            int hco = ((t >> 3) & 1) * 8;
#pragma unroll
            for (int i = 0; i < 4; ++i) {
                int sr = i * 16 + sr0;
#pragma unroll
                for (int ni = 0; ni < 4; ++ni) {
                    unsigned v4h[4], v4l[4];
                    ldsm4t(v4h, pVh + sr * ARS + ni * 16 + hco);
                    ldsm4t(v4l, pVl + sr * ARS + ni * 16 + hco);
                    mma16816(oc[2 * ni],     pa[i], v4h[0], v4h[2]);
                    mma16816(oc[2 * ni + 1], pa[i], v4h[1], v4h[3]);
                    mma16816(oc[2 * ni],     pa[i], v4l[0], v4l[2]);
                    mma16816(oc[2 * ni + 1], pa[i], v4l[1], v4l[3]);
                }
            }
        }
        __syncthreads();
    }

    float inv0 = 1.f / l0, inv1 = 1.f / l1;
    int r0 = q0 + w * 16 + qr;
    size_t ob0 = (((size_t)b * SSEQ + r0) * HHEADS + h) * 64;
    size_t ob1 = (((size_t)b * SSEQ + r0 + 8) * HHEADS + h) * 64;
#pragma unroll
    for (int j = 0; j < 8; ++j) {
        int col = j * 8 + qc;
        float f0 = oc[j][0] * inv0, f1 = oc[j][1] * inv0;
        float f2 = oc[j][2] * inv1, f3 = oc[j][3] * inv1;
        __half h0, e0, h1, e1, h2, e2, h3, e3;
        split_f(f0, h0, e0); split_f(f1, h1, e1);
        split_f(f2, h2, e2); split_f(f3, h3, e3);
        *(__half2*)(ch_ + ob0 + col) = __halves2half2(h0, h1);
        *(__half2*)(cl_ + ob0 + col) = __halves2half2(e0, e1);
        *(__half2*)(ch_ + ob1 + col) = __halves2half2(h2, h3);
        *(__half2*)(cl_ + ob1 + col) = __halves2half2(e2, e3);
    }
}

// ------------------------------- launcher --------------------------------------
extern "C" void kernel_launch(void* const* d_in, const int* in_sizes, int n_in,
                              void* d_out, int out_size)
{
    (void)in_sizes; (void)n_in; (void)out_size;
    const float* x   = (const float*)d_in[0];
    const float* Qb  = (const float*)d_in[1];
    const float* Wq  = (const float*)d_in[2];
    const float* bq  = (const float*)d_in[3];
    const float* Wk  = (const float*)d_in[4];
    const float* bk  = (const float*)d_in[5];
    const float* Wv  = (const float*)d_in[6];
    const float* bv  = (const float*)d_in[7];
    const float* qs  = (const float*)d_in[8];
    const float* ks  = (const float*)d_in[9];
    const float* rel = (const float*)d_in[10];
    const float* Wo  = (const float*)d_in[11];
    const float* bo  = (const float*)d_in[12];
    float* out = (float*)d_out;

    __half *xh, *xl, *wth, *wtl, *qh, *ql, *kh, *kl, *vh, *vl, *bH, *ch, *cl;
    cudaGetSymbolAddress((void**)&xh,  g_xh);
    cudaGetSymbolAddress((void**)&xl,  g_xl);
    cudaGetSymbolAddress((void**)&wth, g_wth);
    cudaGetSymbolAddress((void**)&wtl, g_wtl);
    cudaGetSymbolAddress((void**)&qh,  g_qh);
    cudaGetSymbolAddress((void**)&ql,  g_ql);
    cudaGetSymbolAddress((void**)&kh,  g_kh);
    cudaGetSymbolAddress((void**)&kl,  g_kl);
    cudaGetSymbolAddress((void**)&vh,  g_vh);
    cudaGetSymbolAddress((void**)&vl,  g_vl);
    cudaGetSymbolAddress((void**)&bH,  g_biasH);
    cudaGetSymbolAddress((void**)&ch,  g_ch);
    cudaGetSymbolAddress((void**)&cl,  g_cl);

    const int MM = 1024 * 1024;
    const int GS = 2 * GSTG * (int)sizeof(__half);   // 81920 B
    const int AS = 2 * ASTG * (int)sizeof(__half);   // 73728 B
    cudaFuncSetAttribute(gemm_qkv_kernel,
                         cudaFuncAttributeMaxDynamicSharedMemorySize, GS);
    cudaFuncSetAttribute(gemm3_kernel,
                         cudaFuncAttributeMaxDynamicSharedMemorySize, GS);
    cudaFuncSetAttribute(attn_kernel,
                         cudaFuncAttributeMaxDynamicSharedMemorySize, AS);

    // prep
    split_hl_kernel<<<(MROWS * DDIM / 4 + 255) / 256, 256>>>(x, xh, xl,
                                                             MROWS * DDIM / 4);
    dim3 tb(32, 8), tg(32, 32, 4);
    transpose_split_kernel<<<tg, tb>>>(Wq, Wk, Wv, Wo, wth, wtl);
    bias_kernel<<<(SSEQ * SSEQ) / 256, 256>>>(Qb, rel, bH);

    // fused QKV projection + LN + split + relayout
    dim3 gqkv(3 * DDIM / 128, MROWS / 128);          // (24, 32)
    gemm_qkv_kernel<<<gqkv, 256, GS>>>(xh, xl, wth, wtl, bq, bk, bv, qs, ks,
                                       qh, ql, kh, kl, vh, vl);

    // attention: 512 threads, 256-query tiles
    attn_kernel<<<dim3(SSEQ / 256, HHEADS, BBATCH), 512, AS>>>(qh, ql, kh, kl,
                                                               vh, vl, bH, ch, cl);

    // output projection
    dim3 gg(DDIM / 128, MROWS / 128);
    gemm3_kernel<<<gg, 256, GS>>>(ch, cl, wth + 3 * MM, wtl + 3 * MM, bo, out,
                                  MROWS, DDIM, DDIM);
}

// round 14
// speedup vs baseline: 3.1574x; 1.2479x over previous
#include <cuda_runtime.h>
#include <cuda_fp16.h>
#include <cstdint>

#define BBATCH 2
#define SSEQ 2048
#define DDIM 1024
#define HHEADS 16
#define MROWS (BBATCH * SSEQ)
#define LOG2E 1.4426950408889634f

// ------------------------------ scratch ---------------------------------------
__device__ __align__(16) __half g_xh[MROWS * DDIM];
__device__ __align__(16) __half g_wth[4 * DDIM * DDIM];
__device__ __align__(16) __half g_wtl[4 * DDIM * DDIM];
__device__ __align__(16) __half g_qh[MROWS * DDIM];
__device__ __align__(16) __half g_kh[MROWS * DDIM];
__device__ __align__(16) __half g_kl[MROWS * DDIM];
__device__ __align__(16) __half g_vh[MROWS * DDIM];
__device__ __align__(16) __half g_vl[MROWS * DDIM];
__device__ __align__(16) __half g_biasH[(size_t)HHEADS * SSEQ * SSEQ];
__device__ __align__(16) __half g_ch[MROWS * DDIM];

// ------------------------------ helpers ---------------------------------------
__device__ __forceinline__ void ldsm4(unsigned* r, const void* p) {
    unsigned a = (unsigned)__cvta_generic_to_shared(p);
    asm volatile("ldmatrix.sync.aligned.m8n8.x4.shared.b16 {%0,%1,%2,%3}, [%4];"
                 : "=r"(r[0]), "=r"(r[1]), "=r"(r[2]), "=r"(r[3]) : "r"(a));
}
__device__ __forceinline__ void ldsm4t(unsigned* r, const void* p) {
    unsigned a = (unsigned)__cvta_generic_to_shared(p);
    asm volatile("ldmatrix.sync.aligned.m8n8.x4.trans.shared.b16 {%0,%1,%2,%3}, [%4];"
                 : "=r"(r[0]), "=r"(r[1]), "=r"(r[2]), "=r"(r[3]) : "r"(a));
}
__device__ __forceinline__ void mma16816(float* c, const unsigned* a,
                                         unsigned b0, unsigned b1) {
    asm("mma.sync.aligned.m16n8k16.row.col.f32.f16.f16.f32 "
        "{%0,%1,%2,%3}, {%4,%5,%6,%7}, {%8,%9}, {%0,%1,%2,%3};"
        : "+f"(c[0]), "+f"(c[1]), "+f"(c[2]), "+f"(c[3])
        : "r"(a[0]), "r"(a[1]), "r"(a[2]), "r"(a[3]), "r"(b0), "r"(b1));
}
__device__ __forceinline__ void cp16p(void* smem, const void* gmem) {
    unsigned s = (unsigned)__cvta_generic_to_shared(smem);
    asm volatile("cp.async.cg.shared.global [%0], [%1], 16;" :: "r"(s), "l"(gmem));
}
__device__ __forceinline__ void cp_commit() { asm volatile("cp.async.commit_group;"); }
__device__ __forceinline__ void cp_wait0()  { asm volatile("cp.async.wait_group 0;"); }
__device__ __forceinline__ void cp_wait1()  { asm volatile("cp.async.wait_group 1;"); }
__device__ __forceinline__ unsigned packh2(float a, float b) {
    __half2 h = __floats2half2_rn(a, b);
    return *reinterpret_cast<unsigned*>(&h);
}
__device__ __forceinline__ void split_f(float v, __half& h, __half& l) {
    h = __float2half_rn(v);
    l = __float2half_rn(v - __half2float(h));
}

// --------------------------- x -> fp16 (hi only; low term dropped) -------------
__global__ void __launch_bounds__(256)
tohalf_kernel(const float* __restrict__ in, __half* __restrict__ oh, int n4)
{
    int i = blockIdx.x * 256 + threadIdx.x;
    if (i >= n4) return;
    float4 v = ((const float4*)in)[i];
    ((__half2*)oh)[2 * i]     = __floats2half2_rn(v.x, v.y);
    ((__half2*)oh)[2 * i + 1] = __floats2half2_rn(v.z, v.w);
}

// --------------- transpose + split 4 weights: [K,N] -> [N,K] hi/lo -------------
__global__ void transpose_split_kernel(const float* __restrict__ W0,
                                       const float* __restrict__ W1,
                                       const float* __restrict__ W2,
                                       const float* __restrict__ W3,
                                       __half* __restrict__ th_base,
                                       __half* __restrict__ tl_base)
{
    __shared__ float s[32][33];
    const int z = blockIdx.z;
    const float* W = (z == 0) ? W0 : (z == 1) ? W1 : (z == 2) ? W2 : W3;
    __half* th = th_base + (size_t)z * DDIM * DDIM;
    __half* tl = tl_base + (size_t)z * DDIM * DDIM;
    int tx = threadIdx.x, ty = threadIdx.y;
#pragma unroll
    for (int i = 0; i < 4; ++i)
        s[ty + i * 8][tx] = W[(size_t)(blockIdx.y * 32 + ty + i * 8) * DDIM
                              + blockIdx.x * 32 + tx];
    __syncthreads();
    int xo = blockIdx.y * 32 + tx;
#pragma unroll
    for (int i = 0; i < 4; ++i) {
        int n = blockIdx.x * 32 + ty + i * 8;
        __half hh, ll;
        split_f(s[tx][ty + i * 8], hh, ll);
        th[(size_t)n * DDIM + xo] = hh;
        tl[(size_t)n * DDIM + xo] = ll;
    }
}

// --------------- relative-position bias, fp16 * log2e --------------------------
__global__ void __launch_bounds__(256)
bias_kernel(const float* __restrict__ Qb, const float* __restrict__ rel,
            __half* __restrict__ bias)
{
    __shared__ float srel[128];
    if (threadIdx.x < 128) srel[threadIdx.x] = rel[threadIdx.x];
    __syncthreads();
    size_t p = (size_t)blockIdx.x * 256 + threadIdx.x;
    float qb[8];
    *(float4*)qb       = *(const float4*)(Qb + p * 8);
    *(float4*)(qb + 4) = *(const float4*)(Qb + p * 8 + 4);
#pragma unroll
    for (int h = 0; h < 16; ++h) {
        float a = 0.f;
#pragma unroll
        for (int c = 0; c < 8; ++c) a += srel[c * 16 + h] * qb[c];
        bias[(size_t)h * SSEQ * SSEQ + p] = __float2half_rn(a * LOG2E);
    }
}

// ------------------ shared GEMM constants --------------------------------------
#define GRS 40
#define GARR (128 * GRS)
#define GSTG3 (3 * GARR)            // Ah | Bh | Bl  per stage

// ---- fused QKV GEMM: C = Ah(Bh+Bl)^T, epilogue = bias+LN+split+relayout -------
__global__ void __launch_bounds__(256, 2)
gemm_qkv_kernel(const __half* __restrict__ Ah,
                const __half* __restrict__ Bh, const __half* __restrict__ Bl,
                const float* __restrict__ bq, const float* __restrict__ bk,
                const float* __restrict__ bv,
                const float* __restrict__ qs, const float* __restrict__ ks,
                __half* __restrict__ oqh,
                __half* __restrict__ okh, __half* __restrict__ okl,
                __half* __restrict__ ovh, __half* __restrict__ ovl)
{
    extern __shared__ __half gsm[];
    const int K = DDIM;
    const int tid = threadIdx.x;
    const int w = tid >> 5, t = tid & 31;
    const int wm = w & 3, wn = w >> 2;
    const int m0 = blockIdx.y * 128, n0 = blockIdx.x * 128;

    float acc[2][8][4];
#pragma unroll
    for (int a = 0; a < 2; ++a)
#pragma unroll
        for (int b = 0; b < 8; ++b)
#pragma unroll
            for (int c = 0; c < 4; ++c) acc[a][b][c] = 0.f;

    auto load_stage = [&](int s, int kt) {
        __half* p = gsm + s * GSTG3;
#pragma unroll
        for (int it = 0; it < 6; ++it) {
            int idx = tid + it * 256;          // 1536 = 3 arrays x 128 r x 4 c8
            int arr = idx >> 9;
            int r = (idx >> 2) & 127, c8 = (idx & 3) * 8;
            const __half* src = (arr == 0) ? Ah : (arr == 1) ? Bh : Bl;
            int rbase = (arr == 0) ? m0 : n0;
            cp16p(p + arr * GARR + r * GRS + c8,
                  src + (size_t)(rbase + r) * K + kt + c8);
        }
        cp_commit();
    };

    const int ar = t & 15, co = (t >> 4) << 3;
    const int ntiles = K / 32;

    load_stage(0, 0);
    for (int ti = 0; ti < ntiles; ++ti) {
        int s = ti & 1;
        if (ti + 1 < ntiles) { load_stage(s ^ 1, (ti + 1) * 32); cp_wait1(); }
        else                 { cp_wait0(); }
        __syncthreads();

        __half* pAh = gsm + s * GSTG3;
        __half* pBh = pAh + GARR;
        __half* pBl = pAh + 2 * GARR;
#pragma unroll
        for (int k16 = 0; k16 < 2; ++k16) {
            int ko = k16 * 16 + co;
            unsigned ah[2][4];
            ldsm4(ah[0], pAh + (wm * 32 + ar) * GRS + ko);
            ldsm4(ah[1], pAh + (wm * 32 + 16 + ar) * GRS + ko);
#pragma unroll
            for (int ni = 0; ni < 4; ++ni) {
                unsigned bh[4], bl[4];
                ldsm4(bh, pBh + (wn * 64 + ni * 16 + ar) * GRS + ko);
                ldsm4(bl, pBl + (wn * 64 + ni * 16 + ar) * GRS + ko);
#pragma unroll
                for (int mi = 0; mi < 2; ++mi) {
                    mma16816(acc[mi][2 * ni],     ah[mi], bh[0], bh[2]);
                    mma16816(acc[mi][2 * ni + 1], ah[mi], bh[1], bh[3]);
                    mma16816(acc[mi][2 * ni],     ah[mi], bl[0], bl[2]);
                    mma16816(acc[mi][2 * ni + 1], ah[mi], bl[1], bl[3]);
                }
            }
        }
        __syncthreads();
    }

    // ---------------- epilogue: bias + (LN for q/k) + split + relayout ---------
    const int qr = t >> 2, qc = (t & 3) * 2;
    const int blk = n0 >> 10;                       // 0=q 1=k 2=v
    const int nin = n0 & 1023;
    const int hglob = (nin >> 6) + wn;
    const float* bias = (blk == 0) ? bq : (blk == 1) ? bk : bv;
    const float* scp  = (blk == 0) ? qs : ks;
    const float mult  = (blk == 0) ? 0.125f * LOG2E : 1.0f;

    float bvv[8][2], scv[8][2];
#pragma unroll
    for (int j = 0; j < 8; ++j) {
        float2 bb = *(const float2*)&bias[nin + wn * 64 + j * 8 + qc];
        bvv[j][0] = bb.x; bvv[j][1] = bb.y;
        if (blk < 2) {
            float2 ss = *(const float2*)&scp[j * 8 + qc];
            scv[j][0] = ss.x; scv[j][1] = ss.y;
        }
    }

#pragma unroll
    for (int mi = 0; mi < 2; ++mi) {
#pragma unroll
        for (int rh = 0; rh < 2; ++rh) {
            int r0 = m0 + wm * 32 + mi * 16 + rh * 8 + qr;
            int b  = r0 >> 11, s = r0 & 2047;
            size_t obase = (((size_t)b * 16 + hglob) * 2048 + s) * 64;
            if (blk < 2) {
                float sm = 0.f, s2 = 0.f;
#pragma unroll
                for (int j = 0; j < 8; ++j) {
                    float v0 = acc[mi][j][2 * rh]     + bvv[j][0];
                    float v1 = acc[mi][j][2 * rh + 1] + bvv[j][1];
                    sm += v0 + v1; s2 += v0 * v0 + v1 * v1;
                }
                sm += __shfl_xor_sync(0xffffffffu, sm, 1);
                sm += __shfl_xor_sync(0xffffffffu, sm, 2);
                s2 += __shfl_xor_sync(0xffffffffu, s2, 1);
                s2 += __shfl_xor_sync(0xffffffffu, s2, 2);
                float mu = sm * (1.f / 64.f);
                float var = s2 * (1.f / 64.f) - mu * mu;
                float rin = rsqrtf(var + 1e-6f);
                if (blk == 0) {       // q: hi only
#pragma unroll
                    for (int j = 0; j < 8; ++j) {
                        float y0 = (acc[mi][j][2 * rh]     + bvv[j][0] - mu) * rin
                                   * scv[j][0] * mult;
                        float y1 = (acc[mi][j][2 * rh + 1] + bvv[j][1] - mu) * rin
                                   * scv[j][1] * mult;
                        *(__half2*)(oqh + obase + j * 8 + qc) =
                            __floats2half2_rn(y0, y1);
                    }
                } else {              // k: hi + lo
#pragma unroll
                    for (int j = 0; j < 8; ++j) {
                        float y0 = (acc[mi][j][2 * rh]     + bvv[j][0] - mu) * rin
                                   * scv[j][0];
                        float y1 = (acc[mi][j][2 * rh + 1] + bvv[j][1] - mu) * rin
                                   * scv[j][1];
                        __half h0, l0, h1, l1;
                        split_f(y0, h0, l0); split_f(y1, h1, l1);
                        *(__half2*)(okh + obase + j * 8 + qc) = __halves2half2(h0, h1);
                        *(__half2*)(okl + obase + j * 8 + qc) = __halves2half2(l0, l1);
                    }
                }
            } else {                  // v: hi + lo
#pragma unroll
                for (int j = 0; j < 8; ++j) {
                    float y0 = acc[mi][j][2 * rh]     + bvv[j][0];
                    float y1 = acc[mi][j][2 * rh + 1] + bvv[j][1];
                    __half h0, l0, h1, l1;
                    split_f(y0, h0, l0); split_f(y1, h1, l1);
                    *(__half2*)(ovh + obase + j * 8 + qc) = __halves2half2(h0, h1);
                    *(__half2*)(ovl + obase + j * 8 + qc) = __halves2half2(l0, l1);
                }
            }
        }
    }
}

// ---- output GEMM: C[M,N] = Ah(Bh+Bl)^T + bias, fp32 out -----------------------
__global__ void __launch_bounds__(256, 2)
gemm3_kernel(const __half* __restrict__ Ah,
             const __half* __restrict__ Bh, const __half* __restrict__ Bl,
             const float* __restrict__ bias, float* __restrict__ C,
             int M, int N, int K)
{
    extern __shared__ __half gsm[];
    const int tid = threadIdx.x;
    const int w = tid >> 5, t = tid & 31;
    const int wm = w & 3, wn = w >> 2;
    const int m0 = blockIdx.y * 128, n0 = blockIdx.x * 128;

    float acc[2][8][4];
#pragma unroll
    for (int a = 0; a < 2; ++a)
#pragma unroll
        for (int b = 0; b < 8; ++b)
#pragma unroll
            for (int c = 0; c < 4; ++c) acc[a][b][c] = 0.f;

    auto load_stage = [&](int s, int kt) {
        __half* p = gsm + s * GSTG3;
#pragma unroll
        for (int it = 0; it < 6; ++it) {
            int idx = tid + it * 256;
            int arr = idx >> 9;
            int r = (idx >> 2) & 127, c8 = (idx & 3) * 8;
            const __half* src = (arr == 0) ? Ah : (arr == 1) ? Bh : Bl;
            int rbase = (arr == 0) ? m0 : n0;
            cp16p(p + arr * GARR + r * GRS + c8,
                  src + (size_t)(rbase + r) * K + kt + c8);
        }
        cp_commit();
    };

    const int ar = t & 15, co = (t >> 4) << 3;
    const int ntiles = K / 32;

    load_stage(0, 0);
    for (int ti = 0; ti < ntiles; ++ti) {
        int s = ti & 1;
        if (ti + 1 < ntiles) { load_stage(s ^ 1, (ti + 1) * 32); cp_wait1(); }
        else                 { cp_wait0(); }
        __syncthreads();

        __half* pAh = gsm + s * GSTG3;
        __half* pBh = pAh + GARR;
        __half* pBl = pAh + 2 * GARR;
#pragma unroll
        for (int k16 = 0; k16 < 2; ++k16) {
            int ko = k16 * 16 + co;
            unsigned ah[2][4];
            ldsm4(ah[0], pAh + (wm * 32 + ar) * GRS + ko);
            ldsm4(ah[1], pAh + (wm * 32 + 16 + ar) * GRS + ko);
#pragma unroll
            for (int ni = 0; ni < 4; ++ni) {
                unsigned bh[4], bl[4];
                ldsm4(bh, pBh + (wn * 64 + ni * 16 + ar) * GRS + ko);
                ldsm4(bl, pBl + (wn * 64 + ni * 16 + ar) * GRS + ko);
#pragma unroll
                for (int mi = 0; mi < 2; ++mi) {
                    mma16816(acc[mi][2 * ni],     ah[mi], bh[0], bh[2]);
                    mma16816(acc[mi][2 * ni + 1], ah[mi], bh[1], bh[3]);
                    mma16816(acc[mi][2 * ni],     ah[mi], bl[0], bl[2]);
                    mma16816(acc[mi][2 * ni + 1], ah[mi], bl[1], bl[3]);
                }
            }
        }
        __syncthreads();
    }

    const int qr = t >> 2, qc = (t & 3) * 2;
#pragma unroll
    for (int mi = 0; mi < 2; ++mi) {
        int r0 = m0 + wm * 32 + mi * 16 + qr;
#pragma unroll
        for (int j = 0; j < 8; ++j) {
            int col = n0 + wn * 64 + j * 8 + qc;
            float2 bv = *(const float2*)&bias[col];
            float2 o0 = {acc[mi][j][0] + bv.x, acc[mi][j][1] + bv.y};
            float2 o1 = {acc[mi][j][2] + bv.x, acc[mi][j][3] + bv.y};
            *(float2*)&C[(size_t)r0 * N + col] = o0;
            *(float2*)&C[(size_t)(r0 + 8) * N + col] = o1;
        }
    }
}

// ------- flash attention: 512 threads, q-tile 256 ------------------------------
// QK: qh·(kh+kl)   PV: P·(vh+vl)   ctx out: hi only
#define ARS 72
#define AKV (64 * ARS)
#define ASTG (4 * AKV)

__global__ void __launch_bounds__(512, 1)
attn_kernel(const __half* __restrict__ qh_,
            const __half* __restrict__ kh_, const __half* __restrict__ kl_,
            const __half* __restrict__ vh_, const __half* __restrict__ vl_,
            const __half* __restrict__ biasH, __half* __restrict__ ch_)
{
    extern __shared__ __half smha[];

    const int tid = threadIdx.x, w = tid >> 5, t = tid & 31;
    const int q0 = blockIdx.x * 256, h = blockIdx.y, b = blockIdx.z;
    const size_t qb = (((size_t)b * HHEADS + h) * SSEQ + q0) * 64;
    const size_t kb = (((size_t)b * HHEADS + h) * SSEQ) * 64;

    // ---- stage Q (hi only) and consume to registers ---------------------------
#pragma unroll
    for (int it = 0; it < 4; ++it) {
        int idx = tid + it * 512;           // 2048 uint4: 256 rows x 8 c8
        int r = idx >> 3, c8 = (idx & 7) * 8;
        *(uint4*)(smha + r * ARS + c8) = *(const uint4*)&qh_[qb + (size_t)r * 64 + c8];
    }
    __syncthreads();
    unsigned qf[4][4];
    const int ar = t & 15, co = (t >> 4) << 3;
#pragma unroll
    for (int ki = 0; ki < 4; ++ki)
        ldsm4(qf[ki], smha + (w * 16 + ar) * ARS + ki * 16 + co);
    __syncthreads();

    auto load_kv = [&](int s, int kt) {
        __half* p = smha + s * ASTG;
#pragma unroll
        for (int it = 0; it < 4; ++it) {
            int idx = tid + it * 512;
            int arr = idx >> 9;
            int r = (idx >> 3) & 63, c8 = (idx & 7) * 8;
            const __half* src = (arr == 0) ? kh_ : (arr == 1) ? kl_
                              : (arr == 2) ? vh_ : vl_;
            cp16p(p + arr * AKV + r * ARS + c8,
                  src + kb + (size_t)(kt + r) * 64 + c8);
        }
        cp_commit();
    };

    load_kv(0, 0);

    float m0v = -1e30f, m1v = -1e30f, l0 = 0.f, l1 = 0.f;
    float oc[8][4];
#pragma unroll
    for (int j = 0; j < 8; ++j)
#pragma unroll
        for (int c = 0; c < 4; ++c) oc[j][c] = 0.f;

    const int qr = t >> 2, qc = (t & 3) * 2;
    const size_t brow0 = ((size_t)h * SSEQ + (q0 + w * 16 + qr)) * SSEQ;
    const size_t brow1 = brow0 + 8ull * SSEQ;

    const int ntiles = SSEQ / 64;
    for (int ti = 0; ti < ntiles; ++ti) {
        int s = ti & 1;
        const int kt = ti * 64;

        unsigned braw0[8], braw1[8];
#pragma unroll
        for (int j = 0; j < 8; ++j) {
            braw0[j] = *(const unsigned*)&biasH[brow0 + kt + j * 8 + qc];
            braw1[j] = *(const unsigned*)&biasH[brow1 + kt + j * 8 + qc];
        }

        if (ti + 1 < ntiles) { load_kv(s ^ 1, (ti + 1) * 64); cp_wait1(); }
        else                 { cp_wait0(); }
        __syncthreads();

        __half* pKh = smha + s * ASTG;
        __half* pKl = pKh + AKV;
        __half* pVh = pKh + 2 * AKV;
        __half* pVl = pKh + 3 * AKV;

        float sc[8][4];
#pragma unroll
        for (int j = 0; j < 8; ++j)
#pragma unroll
            for (int c = 0; c < 4; ++c) sc[j][c] = 0.f;
#pragma unroll
        for (int ki = 0; ki < 4; ++ki) {
#pragma unroll
            for (int ni = 0; ni < 4; ++ni) {
                unsigned bh[4], bl[4];
                ldsm4(bh, pKh + (ni * 16 + ar) * ARS + ki * 16 + co);
                ldsm4(bl, pKl + (ni * 16 + ar) * ARS + ki * 16 + co);
                mma16816(sc[2 * ni],     qf[ki], bh[0], bh[2]);
                mma16816(sc[2 * ni + 1], qf[ki], bh[1], bh[3]);
                mma16816(sc[2 * ni],     qf[ki], bl[0], bl[2]);
                mma16816(sc[2 * ni + 1], qf[ki], bl[1], bl[3]);
            }
        }
#pragma unroll
        for (int j = 0; j < 8; ++j) {
            float2 f0 = __half22float2(*(__half2*)&braw0[j]);
            float2 f1 = __half22float2(*(__half2*)&braw1[j]);
            sc[j][0] += f0.x; sc[j][1] += f0.y; sc[j][2] += f1.x; sc[j][3] += f1.y;
        }

        float mx0 = -1e30f, mx1 = -1e30f;
#pragma unroll
        for (int j = 0; j < 8; ++j) {
            mx0 = fmaxf(mx0, fmaxf(sc[j][0], sc[j][1]));
            mx1 = fmaxf(mx1, fmaxf(sc[j][2], sc[j][3]));
        }
        mx0 = fmaxf(mx0, __shfl_xor_sync(0xffffffffu, mx0, 1));
        mx0 = fmaxf(mx0, __shfl_xor_sync(0xffffffffu, mx0, 2));
        mx1 = fmaxf(mx1, __shfl_xor_sync(0xffffffffu, mx1, 1));
        mx1 = fmaxf(mx1, __shfl_xor_sync(0xffffffffu, mx1, 2));
        float mn0 = fmaxf(m0v, mx0), mn1 = fmaxf(m1v, mx1);
        float a0 = exp2f(m0v - mn0), a1 = exp2f(m1v - mn1);
        m0v = mn0; m1v = mn1;

        float rs0 = 0.f, rs1 = 0.f;
        unsigned pa[4][4];
#pragma unroll
        for (int i = 0; i < 4; ++i) {
            int j0 = 2 * i, j1 = 2 * i + 1;
            float p0 = exp2f(sc[j0][0] - mn0), p1 = exp2f(sc[j0][1] - mn0);
            float p2 = exp2f(sc[j0][2] - mn1), p3 = exp2f(sc[j0][3] - mn1);
            float u0 = exp2f(sc[j1][0] - mn0), u1 = exp2f(sc[j1][1] - mn0);
            float u2 = exp2f(sc[j1][2] - mn1), u3 = exp2f(sc[j1][3] - mn1);
            rs0 += (p0 + p1) + (u0 + u1);
            rs1 += (p2 + p3) + (u2 + u3);
            pa[i][0] = packh2(p0, p1); pa[i][1] = packh2(p2, p3);
            pa[i][2] = packh2(u0, u1); pa[i][3] = packh2(u2, u3);
        }
        rs0 += __shfl_xor_sync(0xffffffffu, rs0, 1);
        rs0 += __shfl_xor_sync(0xffffffffu, rs0, 2);
        rs1 += __shfl_xor_sync(0xffffffffu, rs1, 1);
        rs1 += __shfl_xor_sync(0xffffffffu, rs1, 2);
        l0 = l0 * a0 + rs0;
        l1 = l1 * a1 + rs1;
#pragma unroll
        for (int j = 0; j < 8; ++j) {
            oc[j][0] *= a0; oc[j][1] *= a0; oc[j][2] *= a1; oc[j][3] *= a1;
        }
        {
            int sr0 = ((t >> 4) & 1) * 8 + (t & 7);
            int hco = ((t >> 3) & 1) * 8;
#pragma unroll
            for (int i = 0; i < 4; ++i) {
                int sr = i * 16 + sr0;
#pragma unroll
                for (int ni = 0; ni < 4; ++ni) {
                    unsigned v4h[4], v4l[4];
                    ldsm4t(v4h, pVh + sr * ARS + ni * 16 + hco);
                    ldsm4t(v4l, pVl + sr * ARS + ni * 16 + hco);
                    mma16816(oc[2 * ni],     pa[i], v4h[0], v4h[2]);
                    mma16816(oc[2 * ni + 1], pa[i], v4h[1], v4h[3]);
                    mma16816(oc[2 * ni],     pa[i], v4l[0], v4l[2]);
                    mma16816(oc[2 * ni + 1], pa[i], v4l[1], v4l[3]);
                }
            }
        }
        __syncthreads();
    }

    float inv0 = 1.f / l0, inv1 = 1.f / l1;
    int r0 = q0 + w * 16 + qr;
    size_t ob0 = (((size_t)b * SSEQ + r0) * HHEADS + h) * 64;
    size_t ob1 = (((size_t)b * SSEQ + r0 + 8) * HHEADS + h) * 64;
#pragma unroll
    for (int j = 0; j < 8; ++j) {
        int col = j * 8 + qc;
        *(__half2*)(ch_ + ob0 + col) =
            __floats2half2_rn(oc[j][0] * inv0, oc[j][1] * inv0);
        *(__half2*)(ch_ + ob1 + col) =
            __floats2half2_rn(oc[j][2] * inv1, oc[j][3] * inv1);
    }
}

// ------------------------------- launcher --------------------------------------
extern "C" void kernel_launch(void* const* d_in, const int* in_sizes, int n_in,
                              void* d_out, int out_size)
{
    (void)in_sizes; (void)n_in; (void)out_size;
    const float* x   = (const float*)d_in[0];
    const float* Qb  = (const float*)d_in[1];
    const float* Wq  = (const float*)d_in[2];
    const float* bq  = (const float*)d_in[3];
    const float* Wk  = (const float*)d_in[4];
    const float* bk  = (const float*)d_in[5];
    const float* Wv  = (const float*)d_in[6];
    const float* bv  = (const float*)d_in[7];
    const float* qs  = (const float*)d_in[8];
    const float* ks  = (const float*)d_in[9];
    const float* rel = (const float*)d_in[10];
    const float* Wo  = (const float*)d_in[11];
    const float* bo  = (const float*)d_in[12];
    float* out = (float*)d_out;

    __half *xh, *wth, *wtl, *qh, *kh, *kl, *vh, *vl, *bH, *ch;
    cudaGetSymbolAddress((void**)&xh,  g_xh);
    cudaGetSymbolAddress((void**)&wth, g_wth);
    cudaGetSymbolAddress((void**)&wtl, g_wtl);
    cudaGetSymbolAddress((void**)&qh,  g_qh);
    cudaGetSymbolAddress((void**)&kh,  g_kh);
    cudaGetSymbolAddress((void**)&kl,  g_kl);
    cudaGetSymbolAddress((void**)&vh,  g_vh);
    cudaGetSymbolAddress((void**)&vl,  g_vl);
    cudaGetSymbolAddress((void**)&bH,  g_biasH);
    cudaGetSymbolAddress((void**)&ch,  g_ch);

    const int MM = 1024 * 1024;
    const int GS = 2 * GSTG3 * (int)sizeof(__half);  // 61440 B
    const int AS = 2 * ASTG * (int)sizeof(__half);   // 73728 B
    cudaFuncSetAttribute(gemm_qkv_kernel,
                         cudaFuncAttributeMaxDynamicSharedMemorySize, GS);
    cudaFuncSetAttribute(gemm3_kernel,
                         cudaFuncAttributeMaxDynamicSharedMemorySize, GS);
    cudaFuncSetAttribute(attn_kernel,
                         cudaFuncAttributeMaxDynamicSharedMemorySize, AS);

    // prep
    tohalf_kernel<<<(MROWS * DDIM / 4 + 255) / 256, 256>>>(x, xh, MROWS * DDIM / 4);
    dim3 tb(32, 8), tg(32, 32, 4);
    transpose_split_kernel<<<tg, tb>>>(Wq, Wk, Wv, Wo, wth, wtl);
    bias_kernel<<<(SSEQ * SSEQ) / 256, 256>>>(Qb, rel, bH);

    // fused QKV projection + LN + split + relayout
    dim3 gqkv(3 * DDIM / 128, MROWS / 128);          // (24, 32)
    gemm_qkv_kernel<<<gqkv, 256, GS>>>(xh, wth, wtl, bq, bk, bv, qs, ks,
                                       qh, kh, kl, vh, vl);

    // attention
    attn_kernel<<<dim3(SSEQ / 256, HHEADS, BBATCH), 512, AS>>>(qh, kh, kl,
                                                               vh, vl, bH, ch);

    // output projection
    dim3 gg(DDIM / 128, MROWS / 128);
    gemm3_kernel<<<gg, 256, GS>>>(ch, wth + 3 * MM, wtl + 3 * MM, bo, out,
                                  MROWS, DDIM, DDIM);
}

// round 15
// speedup vs baseline: 3.1989x; 1.0131x over previous
#include <cuda_runtime.h>
#include <cuda_fp16.h>
#include <cstdint>

#define BBATCH 2
#define SSEQ 2048
#define DDIM 1024
#define HHEADS 16
#define MROWS (BBATCH * SSEQ)
#define LOG2E 1.4426950408889634f

// ------------------------------ scratch ---------------------------------------
__device__ __align__(16) __half g_xh[MROWS * DDIM];
__device__ __align__(16) __half g_wth[4 * DDIM * DDIM];
__device__ __align__(16) __half g_wtl[4 * DDIM * DDIM];
__device__ __align__(16) __half g_qh[MROWS * DDIM];
__device__ __align__(16) __half g_kh[MROWS * DDIM];
__device__ __align__(16) __half g_kl[MROWS * DDIM];
__device__ __align__(16) __half g_vh[MROWS * DDIM];
__device__ __align__(16) __half g_vl[MROWS * DDIM];
// fragment-contiguous bias: block of 1024 halves per (qg, kt, h);
// within block: lane*32 halves = [row qr: 8x(p0,p1)][row qr+8: 8x(p0,p1)]
__device__ __align__(16) __half g_biasH[(size_t)HHEADS * SSEQ * SSEQ];
__device__ __align__(16) __half g_ch[MROWS * DDIM];

// ------------------------------ helpers ---------------------------------------
__device__ __forceinline__ void ldsm4(unsigned* r, const void* p) {
    unsigned a = (unsigned)__cvta_generic_to_shared(p);
    asm volatile("ldmatrix.sync.aligned.m8n8.x4.shared.b16 {%0,%1,%2,%3}, [%4];"
                 : "=r"(r[0]), "=r"(r[1]), "=r"(r[2]), "=r"(r[3]) : "r"(a));
}
__device__ __forceinline__ void ldsm4t(unsigned* r, const void* p) {
    unsigned a = (unsigned)__cvta_generic_to_shared(p);
    asm volatile("ldmatrix.sync.aligned.m8n8.x4.trans.shared.b16 {%0,%1,%2,%3}, [%4];"
                 : "=r"(r[0]), "=r"(r[1]), "=r"(r[2]), "=r"(r[3]) : "r"(a));
}
__device__ __forceinline__ void mma16816(float* c, const unsigned* a,
                                         unsigned b0, unsigned b1) {
    asm("mma.sync.aligned.m16n8k16.row.col.f32.f16.f16.f32 "
        "{%0,%1,%2,%3}, {%4,%5,%6,%7}, {%8,%9}, {%0,%1,%2,%3};"
        : "+f"(c[0]), "+f"(c[1]), "+f"(c[2]), "+f"(c[3])
        : "r"(a[0]), "r"(a[1]), "r"(a[2]), "r"(a[3]), "r"(b0), "r"(b1));
}
__device__ __forceinline__ void cp16p(void* smem, const void* gmem) {
    unsigned s = (unsigned)__cvta_generic_to_shared(smem);
    asm volatile("cp.async.cg.shared.global [%0], [%1], 16;" :: "r"(s), "l"(gmem));
}
__device__ __forceinline__ void cp_commit() { asm volatile("cp.async.commit_group;"); }
__device__ __forceinline__ void cp_wait0()  { asm volatile("cp.async.wait_group 0;"); }
__device__ __forceinline__ void cp_wait1()  { asm volatile("cp.async.wait_group 1;"); }
__device__ __forceinline__ unsigned packh2(float a, float b) {
    __half2 h = __floats2half2_rn(a, b);
    return *reinterpret_cast<unsigned*>(&h);
}
__device__ __forceinline__ void split_f(float v, __half& h, __half& l) {
    h = __float2half_rn(v);
    l = __float2half_rn(v - __half2float(h));
}

// --------------------------- x -> fp16 (hi only) -------------------------------
__global__ void __launch_bounds__(256)
tohalf_kernel(const float* __restrict__ in, __half* __restrict__ oh, int n4)
{
    int i = blockIdx.x * 256 + threadIdx.x;
    if (i >= n4) return;
    float4 v = ((const float4*)in)[i];
    ((__half2*)oh)[2 * i]     = __floats2half2_rn(v.x, v.y);
    ((__half2*)oh)[2 * i + 1] = __floats2half2_rn(v.z, v.w);
}

// --------------- transpose + split 4 weights: [K,N] -> [N,K] hi/lo -------------
__global__ void transpose_split_kernel(const float* __restrict__ W0,
                                       const float* __restrict__ W1,
                                       const float* __restrict__ W2,
                                       const float* __restrict__ W3,
                                       __half* __restrict__ th_base,
                                       __half* __restrict__ tl_base)
{
    __shared__ float s[32][33];
    const int z = blockIdx.z;
    const float* W = (z == 0) ? W0 : (z == 1) ? W1 : (z == 2) ? W2 : W3;
    __half* th = th_base + (size_t)z * DDIM * DDIM;
    __half* tl = tl_base + (size_t)z * DDIM * DDIM;
    int tx = threadIdx.x, ty = threadIdx.y;
#pragma unroll
    for (int i = 0; i < 4; ++i)
        s[ty + i * 8][tx] = W[(size_t)(blockIdx.y * 32 + ty + i * 8) * DDIM
                              + blockIdx.x * 32 + tx];
    __syncthreads();
    int xo = blockIdx.y * 32 + tx;
#pragma unroll
    for (int i = 0; i < 4; ++i) {
        int n = blockIdx.x * 32 + ty + i * 8;
        __half hh, ll;
        split_f(s[tx][ty + i * 8], hh, ll);
        th[(size_t)n * DDIM + xo] = hh;
        tl[(size_t)n * DDIM + xo] = ll;
    }
}

// ---- rel-pos bias, fragment-contiguous layout, *log2e -------------------------
// CTA = (kt, qg). Stages Qb tile [16 q][64 k][8 c] in smem; thread = (h2, lane),
// computes heads h2 and h2+8 for the lane's 32 (q,k) fragment slots.
__global__ void __launch_bounds__(256)
bias_kernel(const float* __restrict__ Qb, const float* __restrict__ rel,
            __half* __restrict__ bias)
{
    __shared__ float QS[16 * 516];          // row stride 516 (pad 4)
    const int kt = blockIdx.x;              // 0..31
    const int qg = blockIdx.y;              // 0..127
    const int tid = threadIdx.x;

    // cooperative load: rows qg*16..+15, cols (kt*64..+63)x8c = 512 floats/row
    const float* src = Qb + ((size_t)qg * 16 * SSEQ + kt * 64) * 8;
#pragma unroll
    for (int it = 0; it < 8; ++it) {
        int idx = tid + it * 256;           // 2048 float4
        int row = idx >> 7, w4 = (idx & 127) * 4;
        float4 v = *(const float4*)(src + (size_t)row * SSEQ * 8 + w4);
        *(float4*)&QS[row * 516 + w4] = v;
    }

    const int lane = tid & 31, h2 = tid >> 5;        // h2 = 0..7
    const int qr = lane >> 2, qc = (lane & 3) * 2;
    float rA[8], rB[8];
#pragma unroll
    for (int c = 0; c < 8; ++c) {
        rA[c] = rel[c * 16 + h2];
        rB[c] = rel[c * 16 + h2 + 8];
    }
    __syncthreads();

    unsigned wA[16], wB[16];
#pragma unroll
    for (int rh = 0; rh < 2; ++rh) {
        int row = qr + rh * 8;
#pragma unroll
        for (int j = 0; j < 8; ++j) {
            float dA[2], dB[2];
#pragma unroll
            for (int p = 0; p < 2; ++p) {
                int k = j * 8 + qc + p;
                const float* q8 = &QS[row * 516 + k * 8];
                float a = 0.f, b = 0.f;
#pragma unroll
                for (int c = 0; c < 8; ++c) {
                    a += rA[c] * q8[c];
                    b += rB[c] * q8[c];
                }
                dA[p] = a * LOG2E;
                dB[p] = b * LOG2E;
            }
            wA[rh * 8 + j] = packh2(dA[0], dA[1]);
            wB[rh * 8 + j] = packh2(dB[0], dB[1]);
        }
    }

    size_t base = ((size_t)qg * 32 + kt) * 16 * 1024;    // halves
    uint4* oA = (uint4*)(bias + base + (size_t)h2 * 1024) + lane * 4;
    uint4* oB = (uint4*)(bias + base + (size_t)(h2 + 8) * 1024) + lane * 4;
    oA[0] = make_uint4(wA[0], wA[1], wA[2], wA[3]);
    oA[1] = make_uint4(wA[4], wA[5], wA[6], wA[7]);
    oA[2] = make_uint4(wA[8], wA[9], wA[10], wA[11]);
    oA[3] = make_uint4(wA[12], wA[13], wA[14], wA[15]);
    oB[0] = make_uint4(wB[0], wB[1], wB[2], wB[3]);
    oB[1] = make_uint4(wB[4], wB[5], wB[6], wB[7]);
    oB[2] = make_uint4(wB[8], wB[9], wB[10], wB[11]);
    oB[3] = make_uint4(wB[12], wB[13], wB[14], wB[15]);
}

// ------------------ shared GEMM constants --------------------------------------
#define GRS 40
#define GARR (128 * GRS)
#define GSTG3 (3 * GARR)            // Ah | Bh | Bl  per stage

// ---- fused QKV GEMM: C = Ah(Bh+Bl)^T, epilogue = bias+LN+split+relayout -------
__global__ void __launch_bounds__(256, 2)
gemm_qkv_kernel(const __half* __restrict__ Ah,
                const __half* __restrict__ Bh, const __half* __restrict__ Bl,
                const float* __restrict__ bq, const float* __restrict__ bk,
                const float* __restrict__ bv,
                const float* __restrict__ qs, const float* __restrict__ ks,
                __half* __restrict__ oqh,
                __half* __restrict__ okh, __half* __restrict__ okl,
                __half* __restrict__ ovh, __half* __restrict__ ovl)
{
    extern __shared__ __half gsm[];
    const int K = DDIM;
    const int tid = threadIdx.x;
    const int w = tid >> 5, t = tid & 31;
    const int wm = w & 3, wn = w >> 2;
    const int m0 = blockIdx.y * 128, n0 = blockIdx.x * 128;

    float acc[2][8][4];
#pragma unroll
    for (int a = 0; a < 2; ++a)
#pragma unroll
        for (int b = 0; b < 8; ++b)
#pragma unroll
            for (int c = 0; c < 4; ++c) acc[a][b][c] = 0.f;

    auto load_stage = [&](int s, int kt) {
        __half* p = gsm + s * GSTG3;
#pragma unroll
        for (int it = 0; it < 6; ++it) {
            int idx = tid + it * 256;
            int arr = idx >> 9;
            int r = (idx >> 2) & 127, c8 = (idx & 3) * 8;
            const __half* src = (arr == 0) ? Ah : (arr == 1) ? Bh : Bl;
            int rbase = (arr == 0) ? m0 : n0;
            cp16p(p + arr * GARR + r * GRS + c8,
                  src + (size_t)(rbase + r) * K + kt + c8);
        }
        cp_commit();
    };

    const int ar = t & 15, co = (t >> 4) << 3;
    const int ntiles = K / 32;

    load_stage(0, 0);
    for (int ti = 0; ti < ntiles; ++ti) {
        int s = ti & 1;
        if (ti + 1 < ntiles) { load_stage(s ^ 1, (ti + 1) * 32); cp_wait1(); }
        else                 { cp_wait0(); }
        __syncthreads();

        __half* pAh = gsm + s * GSTG3;
        __half* pBh = pAh + GARR;
        __half* pBl = pAh + 2 * GARR;
#pragma unroll
        for (int k16 = 0; k16 < 2; ++k16) {
            int ko = k16 * 16 + co;
            unsigned ah[2][4];
            ldsm4(ah[0], pAh + (wm * 32 + ar) * GRS + ko);
            ldsm4(ah[1], pAh + (wm * 32 + 16 + ar) * GRS + ko);
#pragma unroll
            for (int ni = 0; ni < 4; ++ni) {
                unsigned bh[4], bl[4];
                ldsm4(bh, pBh + (wn * 64 + ni * 16 + ar) * GRS + ko);
                ldsm4(bl, pBl + (wn * 64 + ni * 16 + ar) * GRS + ko);
#pragma unroll
                for (int mi = 0; mi < 2; ++mi) {
                    mma16816(acc[mi][2 * ni],     ah[mi], bh[0], bh[2]);
                    mma16816(acc[mi][2 * ni + 1], ah[mi], bh[1], bh[3]);
                    mma16816(acc[mi][2 * ni],     ah[mi], bl[0], bl[2]);
                    mma16816(acc[mi][2 * ni + 1], ah[mi], bl[1], bl[3]);
                }
            }
        }
        __syncthreads();
    }

    // ---------------- epilogue: bias + (LN for q/k) + split + relayout ---------
    const int qr = t >> 2, qc = (t & 3) * 2;
    const int blk = n0 >> 10;                       // 0=q 1=k 2=v
    const int nin = n0 & 1023;
    const int hglob = (nin >> 6) + wn;
    const float* bias = (blk == 0) ? bq : (blk == 1) ? bk : bv;
    const float* scp  = (blk == 0) ? qs : ks;
    const float mult  = (blk == 0) ? 0.125f * LOG2E : 1.0f;

    float bvv[8][2], scv[8][2];
#pragma unroll
    for (int j = 0; j < 8; ++j) {
        float2 bb = *(const float2*)&bias[nin + wn * 64 + j * 8 + qc];
        bvv[j][0] = bb.x; bvv[j][1] = bb.y;
        if (blk < 2) {
            float2 ss = *(const float2*)&scp[j * 8 + qc];
            scv[j][0] = ss.x; scv[j][1] = ss.y;
        }
    }

#pragma unroll
    for (int mi = 0; mi < 2; ++mi) {
#pragma unroll
        for (int rh = 0; rh < 2; ++rh) {
            int r0 = m0 + wm * 32 + mi * 16 + rh * 8 + qr;
            int b  = r0 >> 11, s = r0 & 2047;
            size_t obase = (((size_t)b * 16 + hglob) * 2048 + s) * 64;
            if (blk < 2) {
                float sm = 0.f, s2 = 0.f;
#pragma unroll
                for (int j = 0; j < 8; ++j) {
                    float v0 = acc[mi][j][2 * rh]     + bvv[j][0];
                    float v1 = acc[mi][j][2 * rh + 1] + bvv[j][1];
                    sm += v0 + v1; s2 += v0 * v0 + v1 * v1;
                }
                sm += __shfl_xor_sync(0xffffffffu, sm, 1);
                sm += __shfl_xor_sync(0xffffffffu, sm, 2);
                s2 += __shfl_xor_sync(0xffffffffu, s2, 1);
                s2 += __shfl_xor_sync(0xffffffffu, s2, 2);
                float mu = sm * (1.f / 64.f);
                float var = s2 * (1.f / 64.f) - mu * mu;
                float rin = rsqrtf(var + 1e-6f);
                if (blk == 0) {
#pragma unroll
                    for (int j = 0; j < 8; ++j) {
                        float y0 = (acc[mi][j][2 * rh]     + bvv[j][0] - mu) * rin
                                   * scv[j][0] * mult;
                        float y1 = (acc[mi][j][2 * rh + 1] + bvv[j][1] - mu) * rin
                                   * scv[j][1] * mult;
                        *(__half2*)(oqh + obase + j * 8 + qc) =
                            __floats2half2_rn(y0, y1);
                    }
                } else {
#pragma unroll
                    for (int j = 0; j < 8; ++j) {
                        float y0 = (acc[mi][j][2 * rh]     + bvv[j][0] - mu) * rin
                                   * scv[j][0];
                        float y1 = (acc[mi][j][2 * rh + 1] + bvv[j][1] - mu) * rin
                                   * scv[j][1];
                        __half h0, l0, h1, l1;
                        split_f(y0, h0, l0); split_f(y1, h1, l1);
                        *(__half2*)(okh + obase + j * 8 + qc) = __halves2half2(h0, h1);
                        *(__half2*)(okl + obase + j * 8 + qc) = __halves2half2(l0, l1);
                    }
                }
            } else {
#pragma unroll
                for (int j = 0; j < 8; ++j) {
                    float y0 = acc[mi][j][2 * rh]     + bvv[j][0];
                    float y1 = acc[mi][j][2 * rh + 1] + bvv[j][1];
                    __half h0, l0, h1, l1;
                    split_f(y0, h0, l0); split_f(y1, h1, l1);
                    *(__half2*)(ovh + obase + j * 8 + qc) = __halves2half2(h0, h1);
                    *(__half2*)(ovl + obase + j * 8 + qc) = __halves2half2(l0, l1);
                }
            }
        }
    }
}

// ---- output GEMM: C[M,N] = Ah(Bh+Bl)^T + bias, fp32 out -----------------------
__global__ void __launch_bounds__(256, 2)
gemm3_kernel(const __half* __restrict__ Ah,
             const __half* __restrict__ Bh, const __half* __restrict__ Bl,
             const float* __restrict__ bias, float* __restrict__ C,
             int M, int N, int K)
{
    extern __shared__ __half gsm[];
    const int tid = threadIdx.x;
    const int w = tid >> 5, t = tid & 31;
    const int wm = w & 3, wn = w >> 2;
    const int m0 = blockIdx.y * 128, n0 = blockIdx.x * 128;

    float acc[2][8][4];
#pragma unroll
    for (int a = 0; a < 2; ++a)
#pragma unroll
        for (int b = 0; b < 8; ++b)
#pragma unroll
            for (int c = 0; c < 4; ++c) acc[a][b][c] = 0.f;

    auto load_stage = [&](int s, int kt) {
        __half* p = gsm + s * GSTG3;
#pragma unroll
        for (int it = 0; it < 6; ++it) {
            int idx = tid + it * 256;
            int arr = idx >> 9;
            int r = (idx >> 2) & 127, c8 = (idx & 3) * 8;
            const __half* src = (arr == 0) ? Ah : (arr == 1) ? Bh : Bl;
            int rbase = (arr == 0) ? m0 : n0;
            cp16p(p + arr * GARR + r * GRS + c8,
                  src + (size_t)(rbase + r) * K + kt + c8);
        }
        cp_commit();
    };

    const int ar = t & 15, co = (t >> 4) << 3;
    const int ntiles = K / 32;

    load_stage(0, 0);
    for (int ti = 0; ti < ntiles; ++ti) {
        int s = ti & 1;
        if (ti + 1 < ntiles) { load_stage(s ^ 1, (ti + 1) * 32); cp_wait1(); }
        else                 { cp_wait0(); }
        __syncthreads();

        __half* pAh = gsm + s * GSTG3;
        __half* pBh = pAh + GARR;
        __half* pBl = pAh + 2 * GARR;
#pragma unroll
        for (int k16 = 0; k16 < 2; ++k16) {
            int ko = k16 * 16 + co;
            unsigned ah[2][4];
            ldsm4(ah[0], pAh + (wm * 32 + ar) * GRS + ko);
            ldsm4(ah[1], pAh + (wm * 32 + 16 + ar) * GRS + ko);
#pragma unroll
            for (int ni = 0; ni < 4; ++ni) {
                unsigned bh[4], bl[4];
                ldsm4(bh, pBh + (wn * 64 + ni * 16 + ar) * GRS + ko);
                ldsm4(bl, pBl + (wn * 64 + ni * 16 + ar) * GRS + ko);
#pragma unroll
                for (int mi = 0; mi < 2; ++mi) {
                    mma16816(acc[mi][2 * ni],     ah[mi], bh[0], bh[2]);
                    mma16816(acc[mi][2 * ni + 1], ah[mi], bh[1], bh[3]);
                    mma16816(acc[mi][2 * ni],     ah[mi], bl[0], bl[2]);
                    mma16816(acc[mi][2 * ni + 1], ah[mi], bl[1], bl[3]);
                }
            }
        }
        __syncthreads();
    }

    const int qr = t >> 2, qc = (t & 3) * 2;
#pragma unroll
    for (int mi = 0; mi < 2; ++mi) {
        int r0 = m0 + wm * 32 + mi * 16 + qr;
#pragma unroll
        for (int j = 0; j < 8; ++j) {
            int col = n0 + wn * 64 + j * 8 + qc;
            float2 bv = *(const float2*)&bias[col];
            float2 o0 = {acc[mi][j][0] + bv.x, acc[mi][j][1] + bv.y};
            float2 o1 = {acc[mi][j][2] + bv.x, acc[mi][j][3] + bv.y};
            *(float2*)&C[(size_t)r0 * N + col] = o0;
            *(float2*)&C[(size_t)(r0 + 8) * N + col] = o1;
        }
    }
}

// ------- flash attention: 512 threads, q-tile 256 ------------------------------
#define ARS 72
#define AKV (64 * ARS)
#define ASTG (4 * AKV)

__global__ void __launch_bounds__(512, 1)
attn_kernel(const __half* __restrict__ qh_,
            const __half* __restrict__ kh_, const __half* __restrict__ kl_,
            const __half* __restrict__ vh_, const __half* __restrict__ vl_,
            const __half* __restrict__ biasH, __half* __restrict__ ch_)
{
    extern __shared__ __half smha[];

    const int tid = threadIdx.x, w = tid >> 5, t = tid & 31;
    const int q0 = blockIdx.x * 256, h = blockIdx.y, b = blockIdx.z;
    const size_t qb = (((size_t)b * HHEADS + h) * SSEQ + q0) * 64;
    const size_t kb = (((size_t)b * HHEADS + h) * SSEQ) * 64;
    // fragment-contiguous bias: warp w owns qg = blockIdx.x*16 + w
    const size_t bwarp = (((size_t)(blockIdx.x * 16 + w) * 32) * 16 + h) * 1024
                         + (size_t)t * 32;

    // ---- stage Q (hi only) and consume to registers ---------------------------
#pragma unroll
    for (int it = 0; it < 4; ++it) {
        int idx = tid + it * 512;
        int r = idx >> 3, c8 = (idx & 7) * 8;
        *(uint4*)(smha + r * ARS + c8) = *(const uint4*)&qh_[qb + (size_t)r * 64 + c8];
    }
    __syncthreads();
    unsigned qf[4][4];
    const int ar = t & 15, co = (t >> 4) << 3;
#pragma unroll
    for (int ki = 0; ki < 4; ++ki)
        ldsm4(qf[ki], smha + (w * 16 + ar) * ARS + ki * 16 + co);
    __syncthreads();

    auto load_kv = [&](int s, int kt) {
        __half* p = smha + s * ASTG;
#pragma unroll
        for (int it = 0; it < 4; ++it) {
            int idx = tid + it * 512;
            int arr = idx >> 9;
            int r = (idx >> 3) & 63, c8 = (idx & 7) * 8;
            const __half* src = (arr == 0) ? kh_ : (arr == 1) ? kl_
                              : (arr == 2) ? vh_ : vl_;
            cp16p(p + arr * AKV + r * ARS + c8,
                  src + kb + (size_t)(kt + r) * 64 + c8);
        }
        cp_commit();
    };

    load_kv(0, 0);

    float m0v = -1e30f, m1v = -1e30f, l0 = 0.f, l1 = 0.f;
    float oc[8][4];
#pragma unroll
    for (int j = 0; j < 8; ++j)
#pragma unroll
        for (int c = 0; c < 4; ++c) oc[j][c] = 0.f;

    const int qr = t >> 2, qc = (t & 3) * 2;

    const int ntiles = SSEQ / 64;
    for (int ti = 0; ti < ntiles; ++ti) {
        int s = ti & 1;

        // coalesced bias fragment fetch: 64 B per lane, issued early
        const uint4* bp = (const uint4*)(biasH + bwarp + (size_t)ti * 16 * 1024);
        uint4 u0 = bp[0], u1 = bp[1], u2 = bp[2], u3 = bp[3];

        if (ti + 1 < ntiles) { load_kv(s ^ 1, (ti + 1) * 64); cp_wait1(); }
        else                 { cp_wait0(); }
        __syncthreads();

        __half* pKh = smha + s * ASTG;
        __half* pKl = pKh + AKV;
        __half* pVh = pKh + 2 * AKV;
        __half* pVl = pKh + 3 * AKV;

        float sc[8][4];
#pragma unroll
        for (int j = 0; j < 8; ++j)
#pragma unroll
            for (int c = 0; c < 4; ++c) sc[j][c] = 0.f;
#pragma unroll
        for (int ki = 0; ki < 4; ++ki) {
#pragma unroll
            for (int ni = 0; ni < 4; ++ni) {
                unsigned bh[4], bl[4];
                ldsm4(bh, pKh + (ni * 16 + ar) * ARS + ki * 16 + co);
                ldsm4(bl, pKl + (ni * 16 + ar) * ARS + ki * 16 + co);
                mma16816(sc[2 * ni],     qf[ki], bh[0], bh[2]);
                mma16816(sc[2 * ni + 1], qf[ki], bh[1], bh[3]);
                mma16816(sc[2 * ni],     qf[ki], bl[0], bl[2]);
                mma16816(sc[2 * ni + 1], qf[ki], bl[1], bl[3]);
            }
        }
        {
            unsigned braw0[8] = {u0.x, u0.y, u0.z, u0.w, u1.x, u1.y, u1.z, u1.w};
            unsigned braw1[8] = {u2.x, u2.y, u2.z, u2.w, u3.x, u3.y, u3.z, u3.w};
#pragma unroll
            for (int j = 0; j < 8; ++j) {
                float2 f0 = __half22float2(*(__half2*)&braw0[j]);
                float2 f1 = __half22float2(*(__half2*)&braw1[j]);
                sc[j][0] += f0.x; sc[j][1] += f0.y; sc[j][2] += f1.x; sc[j][3] += f1.y;
            }
        }

        float mx0 = -1e30f, mx1 = -1e30f;
#pragma unroll
        for (int j = 0; j < 8; ++j) {
            mx0 = fmaxf(mx0, fmaxf(sc[j][0], sc[j][1]));
            mx1 = fmaxf(mx1, fmaxf(sc[j][2], sc[j][3]));
        }
        mx0 = fmaxf(mx0, __shfl_xor_sync(0xffffffffu, mx0, 1));
        mx0 = fmaxf(mx0, __shfl_xor_sync(0xffffffffu, mx0, 2));
        mx1 = fmaxf(mx1, __shfl_xor_sync(0xffffffffu, mx1, 1));
        mx1 = fmaxf(mx1, __shfl_xor_sync(0xffffffffu, mx1, 2));
        float mn0 = fmaxf(m0v, mx0), mn1 = fmaxf(m1v, mx1);
        float a0 = exp2f(m0v - mn0), a1 = exp2f(m1v - mn1);
        m0v = mn0; m1v = mn1;

        float rs0 = 0.f, rs1 = 0.f;
        unsigned pa[4][4];
#pragma unroll
        for (int i = 0; i < 4; ++i) {
            int j0 = 2 * i, j1 = 2 * i + 1;
            float p0 = exp2f(sc[j0][0] - mn0), p1 = exp2f(sc[j0][1] - mn0);
            float p2 = exp2f(sc[j0][2] - mn1), p3 = exp2f(sc[j0][3] - mn1);
            float u0e = exp2f(sc[j1][0] - mn0), u1e = exp2f(sc[j1][1] - mn0);
            float u2e = exp2f(sc[j1][2] - mn1), u3e = exp2f(sc[j1][3] - mn1);
            rs0 += (p0 + p1) + (u0e + u1e);
            rs1 += (p2 + p3) + (u2e + u3e);
            pa[i][0] = packh2(p0, p1); pa[i][1] = packh2(p2, p3);
            pa[i][2] = packh2(u0e, u1e); pa[i][3] = packh2(u2e, u3e);
        }
        rs0 += __shfl_xor_sync(0xffffffffu, rs0, 1);
        rs0 += __shfl_xor_sync(0xffffffffu, rs0, 2);
        rs1 += __shfl_xor_sync(0xffffffffu, rs1, 1);
        rs1 += __shfl_xor_sync(0xffffffffu, rs1, 2);
        l0 = l0 * a0 + rs0;
        l1 = l1 * a1 + rs1;
#pragma unroll
        for (int j = 0; j < 8; ++j) {
            oc[j][0] *= a0; oc[j][1] *= a0; oc[j][2] *= a1; oc[j][3] *= a1;
        }
        {
            int sr0 = ((t >> 4) & 1) * 8 + (t & 7);
            int hco = ((t >> 3) & 1) * 8;
#pragma unroll
            for (int i = 0; i < 4; ++i) {
                int sr = i * 16 + sr0;
#pragma unroll
                for (int ni = 0; ni < 4; ++ni) {
                    unsigned v4h[4], v4l[4];
                    ldsm4t(v4h, pVh + sr * ARS + ni * 16 + hco);
                    ldsm4t(v4l, pVl + sr * ARS + ni * 16 + hco);
                    mma16816(oc[2 * ni],     pa[i], v4h[0], v4h[2]);
                    mma16816(oc[2 * ni + 1], pa[i], v4h[1], v4h[3]);
                    mma16816(oc[2 * ni],     pa[i], v4l[0], v4l[2]);
                    mma16816(oc[2 * ni + 1], pa[i], v4l[1], v4l[3]);
                }
            }
        }
        __syncthreads();
    }

    float inv0 = 1.f / l0, inv1 = 1.f / l1;
    int r0 = q0 + w * 16 + qr;
    size_t ob0 = (((size_t)b * SSEQ + r0) * HHEADS + h) * 64;
    size_t ob1 = (((size_t)b * SSEQ + r0 + 8) * HHEADS + h) * 64;
#pragma unroll
    for (int j = 0; j < 8; ++j) {
        int col = j * 8 + qc;
        *(__half2*)(ch_ + ob0 + col) =
            __floats2half2_rn(oc[j][0] * inv0, oc[j][1] * inv0);
        *(__half2*)(ch_ + ob1 + col) =
            __floats2half2_rn(oc[j][2] * inv1, oc[j][3] * inv1);
    }
}

// ------------------------------- launcher --------------------------------------
extern "C" void kernel_launch(void* const* d_in, const int* in_sizes, int n_in,
                              void* d_out, int out_size)
{
    (void)in_sizes; (void)n_in; (void)out_size;
    const float* x   = (const float*)d_in[0];
    const float* Qb  = (const float*)d_in[1];
    const float* Wq  = (const float*)d_in[2];
    const float* bq  = (const float*)d_in[3];
    const float* Wk  = (const float*)d_in[4];
    const float* bk  = (const float*)d_in[5];
    const float* Wv  = (const float*)d_in[6];
    const float* bv  = (const float*)d_in[7];
    const float* qs  = (const float*)d_in[8];
    const float* ks  = (const float*)d_in[9];
    const float* rel = (const float*)d_in[10];
    const float* Wo  = (const float*)d_in[11];
    const float* bo  = (const float*)d_in[12];
    float* out = (float*)d_out;

    __half *xh, *wth, *wtl, *qh, *kh, *kl, *vh, *vl, *bH, *ch;
    cudaGetSymbolAddress((void**)&xh,  g_xh);
    cudaGetSymbolAddress((void**)&wth, g_wth);
    cudaGetSymbolAddress((void**)&wtl, g_wtl);
    cudaGetSymbolAddress((void**)&qh,  g_qh);
    cudaGetSymbolAddress((void**)&kh,  g_kh);
    cudaGetSymbolAddress((void**)&kl,  g_kl);
    cudaGetSymbolAddress((void**)&vh,  g_vh);
    cudaGetSymbolAddress((void**)&vl,  g_vl);
    cudaGetSymbolAddress((void**)&bH,  g_biasH);
    cudaGetSymbolAddress((void**)&ch,  g_ch);

    const int MM = 1024 * 1024;
    const int GS = 2 * GSTG3 * (int)sizeof(__half);  // 61440 B
    const int AS = 2 * ASTG * (int)sizeof(__half);   // 73728 B
    cudaFuncSetAttribute(gemm_qkv_kernel,
                         cudaFuncAttributeMaxDynamicSharedMemorySize, GS);
    cudaFuncSetAttribute(gemm3_kernel,
                         cudaFuncAttributeMaxDynamicSharedMemorySize, GS);
    cudaFuncSetAttribute(attn_kernel,
                         cudaFuncAttributeMaxDynamicSharedMemorySize, AS);

    // prep
    tohalf_kernel<<<(MROWS * DDIM / 4 + 255) / 256, 256>>>(x, xh, MROWS * DDIM / 4);
    dim3 tb(32, 8), tg(32, 32, 4);
    transpose_split_kernel<<<tg, tb>>>(Wq, Wk, Wv, Wo, wth, wtl);
    bias_kernel<<<dim3(32, 128), 256>>>(Qb, rel, bH);

    // fused QKV projection + LN + split + relayout
    dim3 gqkv(3 * DDIM / 128, MROWS / 128);          // (24, 32)
    gemm_qkv_kernel<<<gqkv, 256, GS>>>(xh, wth, wtl, bq, bk, bv, qs, ks,
                                       qh, kh, kl, vh, vl);

    // attention
    attn_kernel<<<dim3(SSEQ / 256, HHEADS, BBATCH), 512, AS>>>(qh, kh, kl,
                                                               vh, vl, bH, ch);

    // output projection
    dim3 gg(DDIM / 128, MROWS / 128);
    gemm3_kernel<<<gg, 256, GS>>>(ch, wth + 3 * MM, wtl + 3 * MM, bo, out,
                                  MROWS, DDIM, DDIM);
}

// round 16
// speedup vs baseline: 3.3887x; 1.0593x over previous
#include <cuda_runtime.h>
#include <cuda_fp16.h>
#include <cstdint>

#define BBATCH 2
#define SSEQ 2048
#define DDIM 1024
#define HHEADS 16
#define MROWS (BBATCH * SSEQ)
#define LOG2E 1.4426950408889634f

// ------------------------------ scratch ---------------------------------------
__device__ __align__(16) __half g_xh[MROWS * DDIM];
__device__ __align__(16) __half g_wth[4 * DDIM * DDIM];
__device__ __align__(16) __half g_wtl[4 * DDIM * DDIM];
__device__ __align__(16) __half g_qh[MROWS * DDIM];
__device__ __align__(16) __half g_kh[MROWS * DDIM];
__device__ __align__(16) __half g_kl[MROWS * DDIM];
__device__ __align__(16) __half g_vh[MROWS * DDIM];
__device__ __align__(16) __half g_vl[MROWS * DDIM];
// fragment-contiguous bias: 1024 halves per (qg, kt, h)
__device__ __align__(16) __half g_biasH[(size_t)HHEADS * SSEQ * SSEQ];
__device__ __align__(16) __half g_ch[MROWS * DDIM];

// ------------------------------ helpers ---------------------------------------
__device__ __forceinline__ void ldsm4(unsigned* r, const void* p) {
    unsigned a = (unsigned)__cvta_generic_to_shared(p);
    asm volatile("ldmatrix.sync.aligned.m8n8.x4.shared.b16 {%0,%1,%2,%3}, [%4];"
                 : "=r"(r[0]), "=r"(r[1]), "=r"(r[2]), "=r"(r[3]) : "r"(a));
}
__device__ __forceinline__ void ldsm4t(unsigned* r, const void* p) {
    unsigned a = (unsigned)__cvta_generic_to_shared(p);
    asm volatile("ldmatrix.sync.aligned.m8n8.x4.trans.shared.b16 {%0,%1,%2,%3}, [%4];"
                 : "=r"(r[0]), "=r"(r[1]), "=r"(r[2]), "=r"(r[3]) : "r"(a));
}
__device__ __forceinline__ void mma16816(float* c, const unsigned* a,
                                         unsigned b0, unsigned b1) {
    asm("mma.sync.aligned.m16n8k16.row.col.f32.f16.f16.f32 "
        "{%0,%1,%2,%3}, {%4,%5,%6,%7}, {%8,%9}, {%0,%1,%2,%3};"
        : "+f"(c[0]), "+f"(c[1]), "+f"(c[2]), "+f"(c[3])
        : "r"(a[0]), "r"(a[1]), "r"(a[2]), "r"(a[3]), "r"(b0), "r"(b1));
}
__device__ __forceinline__ void cp16p(void* smem, const void* gmem) {
    unsigned s = (unsigned)__cvta_generic_to_shared(smem);
    asm volatile("cp.async.cg.shared.global [%0], [%1], 16;" :: "r"(s), "l"(gmem));
}
__device__ __forceinline__ void cp_commit() { asm volatile("cp.async.commit_group;"); }
__device__ __forceinline__ void cp_wait0()  { asm volatile("cp.async.wait_group 0;"); }
__device__ __forceinline__ void cp_wait1()  { asm volatile("cp.async.wait_group 1;"); }
__device__ __forceinline__ unsigned packh2(float a, float b) {
    __half2 h = __floats2half2_rn(a, b);
    return *reinterpret_cast<unsigned*>(&h);
}
__device__ __forceinline__ void split_f(float v, __half& h, __half& l) {
    h = __float2half_rn(v);
    l = __float2half_rn(v - __half2float(h));
}

// --------------------------- x -> fp16 (hi only) -------------------------------
__global__ void __launch_bounds__(256)
tohalf_kernel(const float* __restrict__ in, __half* __restrict__ oh, int n4)
{
    int i = blockIdx.x * 256 + threadIdx.x;
    if (i >= n4) return;
    float4 v = ((const float4*)in)[i];
    ((__half2*)oh)[2 * i]     = __floats2half2_rn(v.x, v.y);
    ((__half2*)oh)[2 * i + 1] = __floats2half2_rn(v.z, v.w);
}

// --------------- transpose + split 4 weights: [K,N] -> [N,K] hi/lo -------------
__global__ void transpose_split_kernel(const float* __restrict__ W0,
                                       const float* __restrict__ W1,
                                       const float* __restrict__ W2,
                                       const float* __restrict__ W3,
                                       __half* __restrict__ th_base,
                                       __half* __restrict__ tl_base)
{
    __shared__ float s[32][33];
    const int z = blockIdx.z;
    const float* W = (z == 0) ? W0 : (z == 1) ? W1 : (z == 2) ? W2 : W3;
    __half* th = th_base + (size_t)z * DDIM * DDIM;
    __half* tl = tl_base + (size_t)z * DDIM * DDIM;
    int tx = threadIdx.x, ty = threadIdx.y;
#pragma unroll
    for (int i = 0; i < 4; ++i)
        s[ty + i * 8][tx] = W[(size_t)(blockIdx.y * 32 + ty + i * 8) * DDIM
                              + blockIdx.x * 32 + tx];
    __syncthreads();
    int xo = blockIdx.y * 32 + tx;
#pragma unroll
    for (int i = 0; i < 4; ++i) {
        int n = blockIdx.x * 32 + ty + i * 8;
        __half hh, ll;
        split_f(s[tx][ty + i * 8], hh, ll);
        th[(size_t)n * DDIM + xo] = hh;
        tl[(size_t)n * DDIM + xo] = ll;
    }
}

// ------------------ shared GEMM constants --------------------------------------
#define GRS 40
#define GARR (128 * GRS)
#define GSTG3 (3 * GARR)            // Ah | Bh | Bl  per stage
#define QKV_BLOCKS 768              // 24 x 32
#define BIAS_BLOCKS 4096            // 32 kt x 128 qg

// ==== fused launch: blocks [0,768) = QKV GEMM+LN+split; [768,4864) = bias ======
__global__ void __launch_bounds__(256, 2)
qkv_bias_kernel(const __half* __restrict__ Ah,
                const __half* __restrict__ Bh, const __half* __restrict__ Bl,
                const float* __restrict__ bq, const float* __restrict__ bk,
                const float* __restrict__ bv,
                const float* __restrict__ qs, const float* __restrict__ ks,
                __half* __restrict__ oqh,
                __half* __restrict__ okh, __half* __restrict__ okl,
                __half* __restrict__ ovh, __half* __restrict__ ovl,
                const float* __restrict__ Qb, const float* __restrict__ rel,
                __half* __restrict__ biasOut)
{
    extern __shared__ __half gsm[];
    const int tid = threadIdx.x;

    if (blockIdx.x >= QKV_BLOCKS) {
        // ================= bias path (fragment-contiguous, *log2e) =============
        float* QS = (float*)gsm;                 // 16 x 516 floats = 33 KB
        const int idx0 = blockIdx.x - QKV_BLOCKS;
        const int kt = idx0 & 31;                // 0..31
        const int qg = idx0 >> 5;                // 0..127

        const float* src = Qb + ((size_t)qg * 16 * SSEQ + kt * 64) * 8;
#pragma unroll
        for (int it = 0; it < 8; ++it) {
            int idx = tid + it * 256;
            int row = idx >> 7, w4 = (idx & 127) * 4;
            float4 v = *(const float4*)(src + (size_t)row * SSEQ * 8 + w4);
            *(float4*)&QS[row * 516 + w4] = v;
        }

        const int lane = tid & 31, h2 = tid >> 5;
        const int qr = lane >> 2, qc = (lane & 3) * 2;
        float rA[8], rB[8];
#pragma unroll
        for (int c = 0; c < 8; ++c) {
            rA[c] = rel[c * 16 + h2];
            rB[c] = rel[c * 16 + h2 + 8];
        }
        __syncthreads();

        unsigned wA[16], wB[16];
#pragma unroll
        for (int rh = 0; rh < 2; ++rh) {
            int row = qr + rh * 8;
#pragma unroll
            for (int j = 0; j < 8; ++j) {
                float dA[2], dB[2];
#pragma unroll
                for (int p = 0; p < 2; ++p) {
                    int k = j * 8 + qc + p;
                    const float* q8 = &QS[row * 516 + k * 8];
                    float a = 0.f, b = 0.f;
#pragma unroll
                    for (int c = 0; c < 8; ++c) {
                        a += rA[c] * q8[c];
                        b += rB[c] * q8[c];
                    }
                    dA[p] = a * LOG2E;
                    dB[p] = b * LOG2E;
                }
                wA[rh * 8 + j] = packh2(dA[0], dA[1]);
                wB[rh * 8 + j] = packh2(dB[0], dB[1]);
            }
        }

        size_t base = ((size_t)qg * 32 + kt) * 16 * 1024;
        uint4* oA = (uint4*)(biasOut + base + (size_t)h2 * 1024) + lane * 4;
        uint4* oB = (uint4*)(biasOut + base + (size_t)(h2 + 8) * 1024) + lane * 4;
        oA[0] = make_uint4(wA[0], wA[1], wA[2], wA[3]);
        oA[1] = make_uint4(wA[4], wA[5], wA[6], wA[7]);
        oA[2] = make_uint4(wA[8], wA[9], wA[10], wA[11]);
        oA[3] = make_uint4(wA[12], wA[13], wA[14], wA[15]);
        oB[0] = make_uint4(wB[0], wB[1], wB[2], wB[3]);
        oB[1] = make_uint4(wB[4], wB[5], wB[6], wB[7]);
        oB[2] = make_uint4(wB[8], wB[9], wB[10], wB[11]);
        oB[3] = make_uint4(wB[12], wB[13], wB[14], wB[15]);
        return;
    }

    // ================== QKV GEMM path (identical to R15) =======================
    const int K = DDIM;
    const int w = tid >> 5, t = tid & 31;
    const int wm = w & 3, wn = w >> 2;
    const int n0 = (blockIdx.x % 24) * 128;
    const int m0 = (blockIdx.x / 24) * 128;

    float acc[2][8][4];
#pragma unroll
    for (int a = 0; a < 2; ++a)
#pragma unroll
        for (int b = 0; b < 8; ++b)
#pragma unroll
            for (int c = 0; c < 4; ++c) acc[a][b][c] = 0.f;

    auto load_stage = [&](int s, int kt) {
        __half* p = gsm + s * GSTG3;
#pragma unroll
        for (int it = 0; it < 6; ++it) {
            int idx = tid + it * 256;
            int arr = idx >> 9;
            int r = (idx >> 2) & 127, c8 = (idx & 3) * 8;
            const __half* src = (arr == 0) ? Ah : (arr == 1) ? Bh : Bl;
            int rbase = (arr == 0) ? m0 : n0;
            cp16p(p + arr * GARR + r * GRS + c8,
                  src + (size_t)(rbase + r) * K + kt + c8);
        }
        cp_commit();
    };

    const int ar = t & 15, co = (t >> 4) << 3;
    const int ntiles = K / 32;

    load_stage(0, 0);
    for (int ti = 0; ti < ntiles; ++ti) {
        int s = ti & 1;
        if (ti + 1 < ntiles) { load_stage(s ^ 1, (ti + 1) * 32); cp_wait1(); }
        else                 { cp_wait0(); }
        __syncthreads();

        __half* pAh = gsm + s * GSTG3;
        __half* pBh = pAh + GARR;
        __half* pBl = pAh + 2 * GARR;
#pragma unroll
        for (int k16 = 0; k16 < 2; ++k16) {
            int ko = k16 * 16 + co;
            unsigned ah[2][4];
            ldsm4(ah[0], pAh + (wm * 32 + ar) * GRS + ko);
            ldsm4(ah[1], pAh + (wm * 32 + 16 + ar) * GRS + ko);
#pragma unroll
            for (int ni = 0; ni < 4; ++ni) {
                unsigned bh[4], bl[4];
                ldsm4(bh, pBh + (wn * 64 + ni * 16 + ar) * GRS + ko);
                ldsm4(bl, pBl + (wn * 64 + ni * 16 + ar) * GRS + ko);
#pragma unroll
                for (int mi = 0; mi < 2; ++mi) {
                    mma16816(acc[mi][2 * ni],     ah[mi], bh[0], bh[2]);
                    mma16816(acc[mi][2 * ni + 1], ah[mi], bh[1], bh[3]);
                    mma16816(acc[mi][2 * ni],     ah[mi], bl[0], bl[2]);
                    mma16816(acc[mi][2 * ni + 1], ah[mi], bl[1], bl[3]);
                }
            }
        }
        __syncthreads();
    }

    const int qr = t >> 2, qc = (t & 3) * 2;
    const int blk = n0 >> 10;
    const int nin = n0 & 1023;
    const int hglob = (nin >> 6) + wn;
    const float* bias = (blk == 0) ? bq : (blk == 1) ? bk : bv;
    const float* scp  = (blk == 0) ? qs : ks;
    const float mult  = (blk == 0) ? 0.125f * LOG2E : 1.0f;

    float bvv[8][2], scv[8][2];
#pragma unroll
    for (int j = 0; j < 8; ++j) {
        float2 bb = *(const float2*)&bias[nin + wn * 64 + j * 8 + qc];
        bvv[j][0] = bb.x; bvv[j][1] = bb.y;
        if (blk < 2) {
            float2 ss = *(const float2*)&scp[j * 8 + qc];
            scv[j][0] = ss.x; scv[j][1] = ss.y;
        }
    }

#pragma unroll
    for (int mi = 0; mi < 2; ++mi) {
#pragma unroll
        for (int rh = 0; rh < 2; ++rh) {
            int r0 = m0 + wm * 32 + mi * 16 + rh * 8 + qr;
            int b  = r0 >> 11, s = r0 & 2047;
            size_t obase = (((size_t)b * 16 + hglob) * 2048 + s) * 64;
            if (blk < 2) {
                float sm = 0.f, s2 = 0.f;
#pragma unroll
                for (int j = 0; j < 8; ++j) {
                    float v0 = acc[mi][j][2 * rh]     + bvv[j][0];
                    float v1 = acc[mi][j][2 * rh + 1] + bvv[j][1];
                    sm += v0 + v1; s2 += v0 * v0 + v1 * v1;
                }
                sm += __shfl_xor_sync(0xffffffffu, sm, 1);
                sm += __shfl_xor_sync(0xffffffffu, sm, 2);
                s2 += __shfl_xor_sync(0xffffffffu, s2, 1);
                s2 += __shfl_xor_sync(0xffffffffu, s2, 2);
                float mu = sm * (1.f / 64.f);
                float var = s2 * (1.f / 64.f) - mu * mu;
                float rin = rsqrtf(var + 1e-6f);
                if (blk == 0) {
#pragma unroll
                    for (int j = 0; j < 8; ++j) {
                        float y0 = (acc[mi][j][2 * rh]     + bvv[j][0] - mu) * rin
                                   * scv[j][0] * mult;
                        float y1 = (acc[mi][j][2 * rh + 1] + bvv[j][1] - mu) * rin
                                   * scv[j][1] * mult;
                        *(__half2*)(oqh + obase + j * 8 + qc) =
                            __floats2half2_rn(y0, y1);
                    }
                } else {
#pragma unroll
                    for (int j = 0; j < 8; ++j) {
                        float y0 = (acc[mi][j][2 * rh]     + bvv[j][0] - mu) * rin
                                   * scv[j][0];
                        float y1 = (acc[mi][j][2 * rh + 1] + bvv[j][1] - mu) * rin
                                   * scv[j][1];
                        __half h0, l0, h1, l1;
                        split_f(y0, h0, l0); split_f(y1, h1, l1);
                        *(__half2*)(okh + obase + j * 8 + qc) = __halves2half2(h0, h1);
                        *(__half2*)(okl + obase + j * 8 + qc) = __halves2half2(l0, l1);
                    }
                }
            } else {
#pragma unroll
                for (int j = 0; j < 8; ++j) {
                    float y0 = acc[mi][j][2 * rh]     + bvv[j][0];
                    float y1 = acc[mi][j][2 * rh + 1] + bvv[j][1];
                    __half h0, l0, h1, l1;
                    split_f(y0, h0, l0); split_f(y1, h1, l1);
                    *(__half2*)(ovh + obase + j * 8 + qc) = __halves2half2(h0, h1);
                    *(__half2*)(ovl + obase + j * 8 + qc) = __halves2half2(l0, l1);
                }
            }
        }
    }
}

// ---- output GEMM: C[M,N] = Ah(Bh+Bl)^T + bias, fp32 out -----------------------
__global__ void __launch_bounds__(256, 2)
gemm3_kernel(const __half* __restrict__ Ah,
             const __half* __restrict__ Bh, const __half* __restrict__ Bl,
             const float* __restrict__ bias, float* __restrict__ C,
             int M, int N, int K)
{
    extern __shared__ __half gsm[];
    const int tid = threadIdx.x;
    const int w = tid >> 5, t = tid & 31;
    const int wm = w & 3, wn = w >> 2;
    const int m0 = blockIdx.y * 128, n0 = blockIdx.x * 128;

    float acc[2][8][4];
#pragma unroll
    for (int a = 0; a < 2; ++a)
#pragma unroll
        for (int b = 0; b < 8; ++b)
#pragma unroll
            for (int c = 0; c < 4; ++c) acc[a][b][c] = 0.f;

    auto load_stage = [&](int s, int kt) {
        __half* p = gsm + s * GSTG3;
#pragma unroll
        for (int it = 0; it < 6; ++it) {
            int idx = tid + it * 256;
            int arr = idx >> 9;
            int r = (idx >> 2) & 127, c8 = (idx & 3) * 8;
            const __half* src = (arr == 0) ? Ah : (arr == 1) ? Bh : Bl;
            int rbase = (arr == 0) ? m0 : n0;
            cp16p(p + arr * GARR + r * GRS + c8,
                  src + (size_t)(rbase + r) * K + kt + c8);
        }
        cp_commit();
    };

    const int ar = t & 15, co = (t >> 4) << 3;
    const int ntiles = K / 32;

    load_stage(0, 0);
    for (int ti = 0; ti < ntiles; ++ti) {
        int s = ti & 1;
        if (ti + 1 < ntiles) { load_stage(s ^ 1, (ti + 1) * 32); cp_wait1(); }
        else                 { cp_wait0(); }
        __syncthreads();

        __half* pAh = gsm + s * GSTG3;
        __half* pBh = pAh + GARR;
        __half* pBl = pAh + 2 * GARR;
#pragma unroll
        for (int k16 = 0; k16 < 2; ++k16) {
            int ko = k16 * 16 + co;
            unsigned ah[2][4];
            ldsm4(ah[0], pAh + (wm * 32 + ar) * GRS + ko);
            ldsm4(ah[1], pAh + (wm * 32 + 16 + ar) * GRS + ko);
#pragma unroll
            for (int ni = 0; ni < 4; ++ni) {
                unsigned bh[4], bl[4];
                ldsm4(bh, pBh + (wn * 64 + ni * 16 + ar) * GRS + ko);
                ldsm4(bl, pBl + (wn * 64 + ni * 16 + ar) * GRS + ko);
#pragma unroll
                for (int mi = 0; mi < 2; ++mi) {
                    mma16816(acc[mi][2 * ni],     ah[mi], bh[0], bh[2]);
                    mma16816(acc[mi][2 * ni + 1], ah[mi], bh[1], bh[3]);
                    mma16816(acc[mi][2 * ni],     ah[mi], bl[0], bl[2]);
                    mma16816(acc[mi][2 * ni + 1], ah[mi], bl[1], bl[3]);
                }
            }
        }
        __syncthreads();
    }

    const int qr = t >> 2, qc = (t & 3) * 2;
#pragma unroll
    for (int mi = 0; mi < 2; ++mi) {
        int r0 = m0 + wm * 32 + mi * 16 + qr;
#pragma unroll
        for (int j = 0; j < 8; ++j) {
            int col = n0 + wn * 64 + j * 8 + qc;
            float2 bv = *(const float2*)&bias[col];
            float2 o0 = {acc[mi][j][0] + bv.x, acc[mi][j][1] + bv.y};
            float2 o1 = {acc[mi][j][2] + bv.x, acc[mi][j][3] + bv.y};
            *(float2*)&C[(size_t)r0 * N + col] = o0;
            *(float2*)&C[(size_t)(r0 + 8) * N + col] = o1;
        }
    }
}

// ------- flash attention: 512 threads, q-tile 256 ------------------------------
#define ARS 72
#define AKV (64 * ARS)
#define ASTG (4 * AKV)

__global__ void __launch_bounds__(512, 1)
attn_kernel(const __half* __restrict__ qh_,
            const __half* __restrict__ kh_, const __half* __restrict__ kl_,
            const __half* __restrict__ vh_, const __half* __restrict__ vl_,
            const __half* __restrict__ biasH, __half* __restrict__ ch_)
{
    extern __shared__ __half smha[];

    const int tid = threadIdx.x, w = tid >> 5, t = tid & 31;
    const int q0 = blockIdx.x * 256, h = blockIdx.y, b = blockIdx.z;
    const size_t qb = (((size_t)b * HHEADS + h) * SSEQ + q0) * 64;
    const size_t kb = (((size_t)b * HHEADS + h) * SSEQ) * 64;
    const size_t bwarp = (((size_t)(blockIdx.x * 16 + w) * 32) * 16 + h) * 1024
                         + (size_t)t * 32;

#pragma unroll
    for (int it = 0; it < 4; ++it) {
        int idx = tid + it * 512;
        int r = idx >> 3, c8 = (idx & 7) * 8;
        *(uint4*)(smha + r * ARS + c8) = *(const uint4*)&qh_[qb + (size_t)r * 64 + c8];
    }
    __syncthreads();
    unsigned qf[4][4];
    const int ar = t & 15, co = (t >> 4) << 3;
#pragma unroll
    for (int ki = 0; ki < 4; ++ki)
        ldsm4(qf[ki], smha + (w * 16 + ar) * ARS + ki * 16 + co);
    __syncthreads();

    auto load_kv = [&](int s, int kt) {
        __half* p = smha + s * ASTG;
#pragma unroll
        for (int it = 0; it < 4; ++it) {
            int idx = tid + it * 512;
            int arr = idx >> 9;
            int r = (idx >> 3) & 63, c8 = (idx & 7) * 8;
            const __half* src = (arr == 0) ? kh_ : (arr == 1) ? kl_
                              : (arr == 2) ? vh_ : vl_;
            cp16p(p + arr * AKV + r * ARS + c8,
                  src + kb + (size_t)(kt + r) * 64 + c8);
        }
        cp_commit();
    };

    load_kv(0, 0);

    float m0v = -1e30f, m1v = -1e30f, l0 = 0.f, l1 = 0.f;
    float oc[8][4];
#pragma unroll
    for (int j = 0; j < 8; ++j)
#pragma unroll
        for (int c = 0; c < 4; ++c) oc[j][c] = 0.f;

    const int qr = t >> 2, qc = (t & 3) * 2;

    const int ntiles = SSEQ / 64;
    for (int ti = 0; ti < ntiles; ++ti) {
        int s = ti & 1;

        const uint4* bp = (const uint4*)(biasH + bwarp + (size_t)ti * 16 * 1024);
        uint4 u0 = bp[0], u1 = bp[1], u2 = bp[2], u3 = bp[3];

        if (ti + 1 < ntiles) { load_kv(s ^ 1, (ti + 1) * 64); cp_wait1(); }
        else                 { cp_wait0(); }
        __syncthreads();

        __half* pKh = smha + s * ASTG;
        __half* pKl = pKh + AKV;
        __half* pVh = pKh + 2 * AKV;
        __half* pVl = pKh + 3 * AKV;

        float sc[8][4];
#pragma unroll
        for (int j = 0; j < 8; ++j)
#pragma unroll
            for (int c = 0; c < 4; ++c) sc[j][c] = 0.f;
#pragma unroll
        for (int ki = 0; ki < 4; ++ki) {
#pragma unroll
            for (int ni = 0; ni < 4; ++ni) {
                unsigned bh[4], bl[4];
                ldsm4(bh, pKh + (ni * 16 + ar) * ARS + ki * 16 + co);
                ldsm4(bl, pKl + (ni * 16 + ar) * ARS + ki * 16 + co);
                mma16816(sc[2 * ni],     qf[ki], bh[0], bh[2]);
                mma16816(sc[2 * ni + 1], qf[ki], bh[1], bh[3]);
                mma16816(sc[2 * ni],     qf[ki], bl[0], bl[2]);
                mma16816(sc[2 * ni + 1], qf[ki], bl[1], bl[3]);
            }
        }
        {
            unsigned braw0[8] = {u0.x, u0.y, u0.z, u0.w, u1.x, u1.y, u1.z, u1.w};
            unsigned braw1[8] = {u2.x, u2.y, u2.z, u2.w, u3.x, u3.y, u3.z, u3.w};
#pragma unroll
            for (int j = 0; j < 8; ++j) {
                float2 f0 = __half22float2(*(__half2*)&braw0[j]);
                float2 f1 = __half22float2(*(__half2*)&braw1[j]);
                sc[j][0] += f0.x; sc[j][1] += f0.y; sc[j][2] += f1.x; sc[j][3] += f1.y;
            }
        }

        float mx0 = -1e30f, mx1 = -1e30f;
#pragma unroll
        for (int j = 0; j < 8; ++j) {
            mx0 = fmaxf(mx0, fmaxf(sc[j][0], sc[j][1]));
            mx1 = fmaxf(mx1, fmaxf(sc[j][2], sc[j][3]));
        }
        mx0 = fmaxf(mx0, __shfl_xor_sync(0xffffffffu, mx0, 1));
        mx0 = fmaxf(mx0, __shfl_xor_sync(0xffffffffu, mx0, 2));
        mx1 = fmaxf(mx1, __shfl_xor_sync(0xffffffffu, mx1, 1));
        mx1 = fmaxf(mx1, __shfl_xor_sync(0xffffffffu, mx1, 2));
        float mn0 = fmaxf(m0v, mx0), mn1 = fmaxf(m1v, mx1);
        float a0 = exp2f(m0v - mn0), a1 = exp2f(m1v - mn1);
        m0v = mn0; m1v = mn1;

        float rs0 = 0.f, rs1 = 0.f;
        unsigned pa[4][4];
#pragma unroll
        for (int i = 0; i < 4; ++i) {
            int j0 = 2 * i, j1 = 2 * i + 1;
            float p0 = exp2f(sc[j0][0] - mn0), p1 = exp2f(sc[j0][1] - mn0);
            float p2 = exp2f(sc[j0][2] - mn1), p3 = exp2f(sc[j0][3] - mn1);
            float u0e = exp2f(sc[j1][0] - mn0), u1e = exp2f(sc[j1][1] - mn0);
            float u2e = exp2f(sc[j1][2] - mn1), u3e = exp2f(sc[j1][3] - mn1);
            rs0 += (p0 + p1) + (u0e + u1e);
            rs1 += (p2 + p3) + (u2e + u3e);
            pa[i][0] = packh2(p0, p1); pa[i][1] = packh2(p2, p3);
            pa[i][2] = packh2(u0e, u1e); pa[i][3] = packh2(u2e, u3e);
        }
        rs0 += __shfl_xor_sync(0xffffffffu, rs0, 1);
        rs0 += __shfl_xor_sync(0xffffffffu, rs0, 2);
        rs1 += __shfl_xor_sync(0xffffffffu, rs1, 1);
        rs1 += __shfl_xor_sync(0xffffffffu, rs1, 2);
        l0 = l0 * a0 + rs0;
        l1 = l1 * a1 + rs1;
#pragma unroll
        for (int j = 0; j < 8; ++j) {
            oc[j][0] *= a0; oc[j][1] *= a0; oc[j][2] *= a1; oc[j][3] *= a1;
        }
        {
            int sr0 = ((t >> 4) & 1) * 8 + (t & 7);
            int hco = ((t >> 3) & 1) * 8;
#pragma unroll
            for (int i = 0; i < 4; ++i) {
                int sr = i * 16 + sr0;
#pragma unroll
                for (int ni = 0; ni < 4; ++ni) {
                    unsigned v4h[4], v4l[4];
                    ldsm4t(v4h, pVh + sr * ARS + ni * 16 + hco);
                    ldsm4t(v4l, pVl + sr * ARS + ni * 16 + hco);
                    mma16816(oc[2 * ni],     pa[i], v4h[0], v4h[2]);
                    mma16816(oc[2 * ni + 1], pa[i], v4h[1], v4h[3]);
                    mma16816(oc[2 * ni],     pa[i], v4l[0], v4l[2]);
                    mma16816(oc[2 * ni + 1], pa[i], v4l[1], v4l[3]);
                }
            }
        }
        __syncthreads();
    }

    float inv0 = 1.f / l0, inv1 = 1.f / l1;
    int r0 = q0 + w * 16 + qr;
    size_t ob0 = (((size_t)b * SSEQ + r0) * HHEADS + h) * 64;
    size_t ob1 = (((size_t)b * SSEQ + r0 + 8) * HHEADS + h) * 64;
#pragma unroll
    for (int j = 0; j < 8; ++j) {
        int col = j * 8 + qc;
        *(__half2*)(ch_ + ob0 + col) =
            __floats2half2_rn(oc[j][0] * inv0, oc[j][1] * inv0);
        *(__half2*)(ch_ + ob1 + col) =
            __floats2half2_rn(oc[j][2] * inv1, oc[j][3] * inv1);
    }
}

// ------------------------------- launcher --------------------------------------
extern "C" void kernel_launch(void* const* d_in, const int* in_sizes, int n_in,
                              void* d_out, int out_size)
{
    (void)in_sizes; (void)n_in; (void)out_size;
    const float* x   = (const float*)d_in[0];
    const float* Qb  = (const float*)d_in[1];
    const float* Wq  = (const float*)d_in[2];
    const float* bq  = (const float*)d_in[3];
    const float* Wk  = (const float*)d_in[4];
    const float* bk  = (const float*)d_in[5];
    const float* Wv  = (const float*)d_in[6];
    const float* bv  = (const float*)d_in[7];
    const float* qs  = (const float*)d_in[8];
    const float* ks  = (const float*)d_in[9];
    const float* rel = (const float*)d_in[10];
    const float* Wo  = (const float*)d_in[11];
    const float* bo  = (const float*)d_in[12];
    float* out = (float*)d_out;

    __half *xh, *wth, *wtl, *qh, *kh, *kl, *vh, *vl, *bH, *ch;
    cudaGetSymbolAddress((void**)&xh,  g_xh);
    cudaGetSymbolAddress((void**)&wth, g_wth);
    cudaGetSymbolAddress((void**)&wtl, g_wtl);
    cudaGetSymbolAddress((void**)&qh,  g_qh);
    cudaGetSymbolAddress((void**)&kh,  g_kh);
    cudaGetSymbolAddress((void**)&kl,  g_kl);
    cudaGetSymbolAddress((void**)&vh,  g_vh);
    cudaGetSymbolAddress((void**)&vl,  g_vl);
    cudaGetSymbolAddress((void**)&bH,  g_biasH);
    cudaGetSymbolAddress((void**)&ch,  g_ch);

    const int MM = 1024 * 1024;
    const int GS = 2 * GSTG3 * (int)sizeof(__half);  // 61440 B
    const int AS = 2 * ASTG * (int)sizeof(__half);   // 73728 B
    cudaFuncSetAttribute(qkv_bias_kernel,
                         cudaFuncAttributeMaxDynamicSharedMemorySize, GS);
    cudaFuncSetAttribute(gemm3_kernel,
                         cudaFuncAttributeMaxDynamicSharedMemorySize, GS);
    cudaFuncSetAttribute(attn_kernel,
                         cudaFuncAttributeMaxDynamicSharedMemorySize, AS);

    // prep (upstream of the fused launch)
    tohalf_kernel<<<(MROWS * DDIM / 4 + 255) / 256, 256>>>(x, xh, MROWS * DDIM / 4);
    dim3 tb(32, 8), tg(32, 32, 4);
    transpose_split_kernel<<<tg, tb>>>(Wq, Wk, Wv, Wo, wth, wtl);

    // fused QKV GEMM + bias-table launch (gemm blocks first, bias blocks backfill)
    qkv_bias_kernel<<<QKV_BLOCKS + BIAS_BLOCKS, 256, GS>>>(
        xh, wth, wtl, bq, bk, bv, qs, ks,
        qh, kh, kl, vh, vl, Qb, rel, bH);

    // attention
    attn_kernel<<<dim3(SSEQ / 256, HHEADS, BBATCH), 512, AS>>>(qh, kh, kl,
                                                               vh, vl, bH, ch);

    // output projection
    dim3 gg(DDIM / 128, MROWS / 128);
    gemm3_kernel<<<gg, 256, GS>>>(ch, wth + 3 * MM, wtl + 3 * MM, bo, out,
                                  MROWS, DDIM, DDIM);
}

// round 17
// speedup vs baseline: 3.6940x; 1.0901x over previous
#include <cuda_runtime.h>
#include <cuda_fp16.h>
#include <cstdint>

#define BBATCH 2
#define SSEQ 2048
#define DDIM 1024
#define HHEADS 16
#define MROWS (BBATCH * SSEQ)
#define LOG2E 1.4426950408889634f

// ------------------------------ scratch ---------------------------------------
__device__ __align__(16) __half g_xh[MROWS * DDIM];
__device__ __align__(16) __half g_wth[4 * DDIM * DDIM];
__device__ __align__(16) __half g_wtl[4 * DDIM * DDIM];
__device__ __align__(16) __half g_qh[MROWS * DDIM];
__device__ __align__(16) __half g_kh[MROWS * DDIM];
__device__ __align__(16) __half g_vh[MROWS * DDIM];
__device__ __align__(16) __half g_vl[MROWS * DDIM];
// fragment-contiguous bias: 1024 halves per (qg, kt, h)
__device__ __align__(16) __half g_biasH[(size_t)HHEADS * SSEQ * SSEQ];
__device__ __align__(16) __half g_ch[MROWS * DDIM];

// ------------------------------ helpers ---------------------------------------
__device__ __forceinline__ void ldsm4(unsigned* r, const void* p) {
    unsigned a = (unsigned)__cvta_generic_to_shared(p);
    asm volatile("ldmatrix.sync.aligned.m8n8.x4.shared.b16 {%0,%1,%2,%3}, [%4];"
                 : "=r"(r[0]), "=r"(r[1]), "=r"(r[2]), "=r"(r[3]) : "r"(a));
}
__device__ __forceinline__ void ldsm4t(unsigned* r, const void* p) {
    unsigned a = (unsigned)__cvta_generic_to_shared(p);
    asm volatile("ldmatrix.sync.aligned.m8n8.x4.trans.shared.b16 {%0,%1,%2,%3}, [%4];"
                 : "=r"(r[0]), "=r"(r[1]), "=r"(r[2]), "=r"(r[3]) : "r"(a));
}
__device__ __forceinline__ void mma16816(float* c, const unsigned* a,
                                         unsigned b0, unsigned b1) {
    asm("mma.sync.aligned.m16n8k16.row.col.f32.f16.f16.f32 "
        "{%0,%1,%2,%3}, {%4,%5,%6,%7}, {%8,%9}, {%0,%1,%2,%3};"
        : "+f"(c[0]), "+f"(c[1]), "+f"(c[2]), "+f"(c[3])
        : "r"(a[0]), "r"(a[1]), "r"(a[2]), "r"(a[3]), "r"(b0), "r"(b1));
}
__device__ __forceinline__ void cp16p(void* smem, const void* gmem) {
    unsigned s = (unsigned)__cvta_generic_to_shared(smem);
    asm volatile("cp.async.cg.shared.global [%0], [%1], 16;" :: "r"(s), "l"(gmem));
}
__device__ __forceinline__ void cp_commit() { asm volatile("cp.async.commit_group;"); }
__device__ __forceinline__ void cp_wait0()  { asm volatile("cp.async.wait_group 0;"); }
__device__ __forceinline__ void cp_wait1()  { asm volatile("cp.async.wait_group 1;"); }
__device__ __forceinline__ unsigned packh2(float a, float b) {
    __half2 h = __floats2half2_rn(a, b);
    return *reinterpret_cast<unsigned*>(&h);
}
__device__ __forceinline__ void split_f(float v, __half& h, __half& l) {
    h = __float2half_rn(v);
    l = __float2half_rn(v - __half2float(h));
}

// --------------------------- x -> fp16 (hi only) -------------------------------
__global__ void __launch_bounds__(256)
tohalf_kernel(const float* __restrict__ in, __half* __restrict__ oh, int n4)
{
    int i = blockIdx.x * 256 + threadIdx.x;
    if (i >= n4) return;
    float4 v = ((const float4*)in)[i];
    ((__half2*)oh)[2 * i]     = __floats2half2_rn(v.x, v.y);
    ((__half2*)oh)[2 * i + 1] = __floats2half2_rn(v.z, v.w);
}

// --------------- transpose + split 4 weights: [K,N] -> [N,K] hi/lo -------------
__global__ void transpose_split_kernel(const float* __restrict__ W0,
                                       const float* __restrict__ W1,
                                       const float* __restrict__ W2,
                                       const float* __restrict__ W3,
                                       __half* __restrict__ th_base,
                                       __half* __restrict__ tl_base)
{
    __shared__ float s[32][33];
    const int z = blockIdx.z;
    const float* W = (z == 0) ? W0 : (z == 1) ? W1 : (z == 2) ? W2 : W3;
    __half* th = th_base + (size_t)z * DDIM * DDIM;
    __half* tl = tl_base + (size_t)z * DDIM * DDIM;
    int tx = threadIdx.x, ty = threadIdx.y;
#pragma unroll
    for (int i = 0; i < 4; ++i)
        s[ty + i * 8][tx] = W[(size_t)(blockIdx.y * 32 + ty + i * 8) * DDIM
                              + blockIdx.x * 32 + tx];
    __syncthreads();
    int xo = blockIdx.y * 32 + tx;
#pragma unroll
    for (int i = 0; i < 4; ++i) {
        int n = blockIdx.x * 32 + ty + i * 8;
        __half hh, ll;
        split_f(s[tx][ty + i * 8], hh, ll);
        th[(size_t)n * DDIM + xo] = hh;
        tl[(size_t)n * DDIM + xo] = ll;
    }
}

// ------------------ shared GEMM constants --------------------------------------
#define GRS 40
#define GARR (128 * GRS)
#define GSTG3 (3 * GARR)            // Ah | Bh | Bl  per stage
#define QKV_BLOCKS 768              // 24 x 32
#define BIAS_BLOCKS 4096            // 32 kt x 128 qg

// ==== fused launch: blocks [0,768) = QKV GEMM+LN+split; [768,4864) = bias ======
__global__ void __launch_bounds__(256, 2)
qkv_bias_kernel(const __half* __restrict__ Ah,
                const __half* __restrict__ Bh, const __half* __restrict__ Bl,
                const float* __restrict__ bq, const float* __restrict__ bk,
                const float* __restrict__ bv,
                const float* __restrict__ qs, const float* __restrict__ ks,
                __half* __restrict__ oqh, __half* __restrict__ okh,
                __half* __restrict__ ovh, __half* __restrict__ ovl,
                const float* __restrict__ Qb, const float* __restrict__ rel,
                __half* __restrict__ biasOut)
{
    extern __shared__ __half gsm[];
    const int tid = threadIdx.x;

    if (blockIdx.x >= QKV_BLOCKS) {
        // ================= bias path (fragment-contiguous, *log2e) =============
        float* QS = (float*)gsm;                 // 16 x 516 floats = 33 KB
        const int idx0 = blockIdx.x - QKV_BLOCKS;
        const int kt = idx0 & 31;
        const int qg = idx0 >> 5;

        const float* src = Qb + ((size_t)qg * 16 * SSEQ + kt * 64) * 8;
#pragma unroll
        for (int it = 0; it < 8; ++it) {
            int idx = tid + it * 256;
            int row = idx >> 7, w4 = (idx & 127) * 4;
            float4 v = *(const float4*)(src + (size_t)row * SSEQ * 8 + w4);
            *(float4*)&QS[row * 516 + w4] = v;
        }

        const int lane = tid & 31, h2 = tid >> 5;
        const int qr = lane >> 2, qc = (lane & 3) * 2;
        float rA[8], rB[8];
#pragma unroll
        for (int c = 0; c < 8; ++c) {
            rA[c] = rel[c * 16 + h2];
            rB[c] = rel[c * 16 + h2 + 8];
        }
        __syncthreads();

        unsigned wA[16], wB[16];
#pragma unroll
        for (int rh = 0; rh < 2; ++rh) {
            int row = qr + rh * 8;
#pragma unroll
            for (int j = 0; j < 8; ++j) {
                float dA[2], dB[2];
#pragma unroll
                for (int p = 0; p < 2; ++p) {
                    int k = j * 8 + qc + p;
                    const float* q8 = &QS[row * 516 + k * 8];
                    float a = 0.f, b = 0.f;
#pragma unroll
                    for (int c = 0; c < 8; ++c) {
                        a += rA[c] * q8[c];
                        b += rB[c] * q8[c];
                    }
                    dA[p] = a * LOG2E;
                    dB[p] = b * LOG2E;
                }
                wA[rh * 8 + j] = packh2(dA[0], dA[1]);
                wB[rh * 8 + j] = packh2(dB[0], dB[1]);
            }
        }

        size_t base = ((size_t)qg * 32 + kt) * 16 * 1024;
        uint4* oA = (uint4*)(biasOut + base + (size_t)h2 * 1024) + lane * 4;
        uint4* oB = (uint4*)(biasOut + base + (size_t)(h2 + 8) * 1024) + lane * 4;
        oA[0] = make_uint4(wA[0], wA[1], wA[2], wA[3]);
        oA[1] = make_uint4(wA[4], wA[5], wA[6], wA[7]);
        oA[2] = make_uint4(wA[8], wA[9], wA[10], wA[11]);
        oA[3] = make_uint4(wA[12], wA[13], wA[14], wA[15]);
        oB[0] = make_uint4(wB[0], wB[1], wB[2], wB[3]);
        oB[1] = make_uint4(wB[4], wB[5], wB[6], wB[7]);
        oB[2] = make_uint4(wB[8], wB[9], wB[10], wB[11]);
        oB[3] = make_uint4(wB[12], wB[13], wB[14], wB[15]);
        return;
    }

    // ================== QKV GEMM path ==========================================
    const int K = DDIM;
    const int w = tid >> 5, t = tid & 31;
    const int wm = w & 3, wn = w >> 2;
    const int n0 = (blockIdx.x % 24) * 128;
    const int m0 = (blockIdx.x / 24) * 128;

    float acc[2][8][4];
#pragma unroll
    for (int a = 0; a < 2; ++a)
#pragma unroll
        for (int b = 0; b < 8; ++b)
#pragma unroll
            for (int c = 0; c < 4; ++c) acc[a][b][c] = 0.f;

    auto load_stage = [&](int s, int kt) {
        __half* p = gsm + s * GSTG3;
#pragma unroll
        for (int it = 0; it < 6; ++it) {
            int idx = tid + it * 256;
            int arr = idx >> 9;
            int r = (idx >> 2) & 127, c8 = (idx & 3) * 8;
            const __half* src = (arr == 0) ? Ah : (arr == 1) ? Bh : Bl;
            int rbase = (arr == 0) ? m0 : n0;
            cp16p(p + arr * GARR + r * GRS + c8,
                  src + (size_t)(rbase + r) * K + kt + c8);
        }
        cp_commit();
    };

    const int ar = t & 15, co = (t >> 4) << 3;
    const int ntiles = K / 32;

    load_stage(0, 0);
    for (int ti = 0; ti < ntiles; ++ti) {
        int s = ti & 1;
        if (ti + 1 < ntiles) { load_stage(s ^ 1, (ti + 1) * 32); cp_wait1(); }
        else                 { cp_wait0(); }
        __syncthreads();

        __half* pAh = gsm + s * GSTG3;
        __half* pBh = pAh + GARR;
        __half* pBl = pAh + 2 * GARR;
#pragma unroll
        for (int k16 = 0; k16 < 2; ++k16) {
            int ko = k16 * 16 + co;
            unsigned ah[2][4];
            ldsm4(ah[0], pAh + (wm * 32 + ar) * GRS + ko);
            ldsm4(ah[1], pAh + (wm * 32 + 16 + ar) * GRS + ko);
#pragma unroll
            for (int ni = 0; ni < 4; ++ni) {
                unsigned bh[4], bl[4];
                ldsm4(bh, pBh + (wn * 64 + ni * 16 + ar) * GRS + ko);
                ldsm4(bl, pBl + (wn * 64 + ni * 16 + ar) * GRS + ko);
#pragma unroll
                for (int mi = 0; mi < 2; ++mi) {
                    mma16816(acc[mi][2 * ni],     ah[mi], bh[0], bh[2]);
                    mma16816(acc[mi][2 * ni + 1], ah[mi], bh[1], bh[3]);
                    mma16816(acc[mi][2 * ni],     ah[mi], bl[0], bl[2]);
                    mma16816(acc[mi][2 * ni + 1], ah[mi], bl[1], bl[3]);
                }
            }
        }
        __syncthreads();
    }

    const int qr = t >> 2, qc = (t & 3) * 2;
    const int blk = n0 >> 10;
    const int nin = n0 & 1023;
    const int hglob = (nin >> 6) + wn;
    const float* bias = (blk == 0) ? bq : (blk == 1) ? bk : bv;
    const float* scp  = (blk == 0) ? qs : ks;
    const float mult  = (blk == 0) ? 0.125f * LOG2E : 1.0f;

    float bvv[8][2], scv[8][2];
#pragma unroll
    for (int j = 0; j < 8; ++j) {
        float2 bb = *(const float2*)&bias[nin + wn * 64 + j * 8 + qc];
        bvv[j][0] = bb.x; bvv[j][1] = bb.y;
        if (blk < 2) {
            float2 ss = *(const float2*)&scp[j * 8 + qc];
            scv[j][0] = ss.x; scv[j][1] = ss.y;
        }
    }

#pragma unroll
    for (int mi = 0; mi < 2; ++mi) {
#pragma unroll
        for (int rh = 0; rh < 2; ++rh) {
            int r0 = m0 + wm * 32 + mi * 16 + rh * 8 + qr;
            int b  = r0 >> 11, s = r0 & 2047;
            size_t obase = (((size_t)b * 16 + hglob) * 2048 + s) * 64;
            if (blk < 2) {
                float sm = 0.f, s2 = 0.f;
#pragma unroll
                for (int j = 0; j < 8; ++j) {
                    float v0 = acc[mi][j][2 * rh]     + bvv[j][0];
                    float v1 = acc[mi][j][2 * rh + 1] + bvv[j][1];
                    sm += v0 + v1; s2 += v0 * v0 + v1 * v1;
                }
                sm += __shfl_xor_sync(0xffffffffu, sm, 1);
                sm += __shfl_xor_sync(0xffffffffu, sm, 2);
                s2 += __shfl_xor_sync(0xffffffffu, s2, 1);
                s2 += __shfl_xor_sync(0xffffffffu, s2, 2);
                float mu = sm * (1.f / 64.f);
                float var = s2 * (1.f / 64.f) - mu * mu;
                float rin = rsqrtf(var + 1e-6f);
                // q and k: hi-only fp16 outputs (k_l dropped this round)
                __half* dst = (blk == 0) ? oqh : okh;
#pragma unroll
                for (int j = 0; j < 8; ++j) {
                    float y0 = (acc[mi][j][2 * rh]     + bvv[j][0] - mu) * rin
                               * scv[j][0] * mult;
                    float y1 = (acc[mi][j][2 * rh + 1] + bvv[j][1] - mu) * rin
                               * scv[j][1] * mult;
                    *(__half2*)(dst + obase + j * 8 + qc) =
                        __floats2half2_rn(y0, y1);
                }
            } else {
#pragma unroll
                for (int j = 0; j < 8; ++j) {
                    float y0 = acc[mi][j][2 * rh]     + bvv[j][0];
                    float y1 = acc[mi][j][2 * rh + 1] + bvv[j][1];
                    __half h0, l0, h1, l1;
                    split_f(y0, h0, l0); split_f(y1, h1, l1);
                    *(__half2*)(ovh + obase + j * 8 + qc) = __halves2half2(h0, h1);
                    *(__half2*)(ovl + obase + j * 8 + qc) = __halves2half2(l0, l1);
                }
            }
        }
    }
}

// ---- output GEMM: C[M,N] = Ah(Bh+Bl)^T + bias, fp32 out -----------------------
__global__ void __launch_bounds__(256, 2)
gemm3_kernel(const __half* __restrict__ Ah,
             const __half* __restrict__ Bh, const __half* __restrict__ Bl,
             const float* __restrict__ bias, float* __restrict__ C,
             int M, int N, int K)
{
    extern __shared__ __half gsm[];
    const int tid = threadIdx.x;
    const int w = tid >> 5, t = tid & 31;
    const int wm = w & 3, wn = w >> 2;
    const int m0 = blockIdx.y * 128, n0 = blockIdx.x * 128;

    float acc[2][8][4];
#pragma unroll
    for (int a = 0; a < 2; ++a)
#pragma unroll
        for (int b = 0; b < 8; ++b)
#pragma unroll
            for (int c = 0; c < 4; ++c) acc[a][b][c] = 0.f;

    auto load_stage = [&](int s, int kt) {
        __half* p = gsm + s * GSTG3;
#pragma unroll
        for (int it = 0; it < 6; ++it) {
            int idx = tid + it * 256;
            int arr = idx >> 9;
            int r = (idx >> 2) & 127, c8 = (idx & 3) * 8;
            const __half* src = (arr == 0) ? Ah : (arr == 1) ? Bh : Bl;
            int rbase = (arr == 0) ? m0 : n0;
            cp16p(p + arr * GARR + r * GRS + c8,
                  src + (size_t)(rbase + r) * K + kt + c8);
        }
        cp_commit();
    };

    const int ar = t & 15, co = (t >> 4) << 3;
    const int ntiles = K / 32;

    load_stage(0, 0);
    for (int ti = 0; ti < ntiles; ++ti) {
        int s = ti & 1;
        if (ti + 1 < ntiles) { load_stage(s ^ 1, (ti + 1) * 32); cp_wait1(); }
        else                 { cp_wait0(); }
        __syncthreads();

        __half* pAh = gsm + s * GSTG3;
        __half* pBh = pAh + GARR;
        __half* pBl = pAh + 2 * GARR;
#pragma unroll
        for (int k16 = 0; k16 < 2; ++k16) {
            int ko = k16 * 16 + co;
            unsigned ah[2][4];
            ldsm4(ah[0], pAh + (wm * 32 + ar) * GRS + ko);
            ldsm4(ah[1], pAh + (wm * 32 + 16 + ar) * GRS + ko);
#pragma unroll
            for (int ni = 0; ni < 4; ++ni) {
                unsigned bh[4], bl[4];
                ldsm4(bh, pBh + (wn * 64 + ni * 16 + ar) * GRS + ko);
                ldsm4(bl, pBl + (wn * 64 + ni * 16 + ar) * GRS + ko);
#pragma unroll
                for (int mi = 0; mi < 2; ++mi) {
                    mma16816(acc[mi][2 * ni],     ah[mi], bh[0], bh[2]);
                    mma16816(acc[mi][2 * ni + 1], ah[mi], bh[1], bh[3]);
                    mma16816(acc[mi][2 * ni],     ah[mi], bl[0], bl[2]);
                    mma16816(acc[mi][2 * ni + 1], ah[mi], bl[1], bl[3]);
                }
            }
        }
        __syncthreads();
    }

    const int qr = t >> 2, qc = (t & 3) * 2;
#pragma unroll
    for (int mi = 0; mi < 2; ++mi) {
        int r0 = m0 + wm * 32 + mi * 16 + qr;
#pragma unroll
        for (int j = 0; j < 8; ++j) {
            int col = n0 + wn * 64 + j * 8 + qc;
            float2 bv = *(const float2*)&bias[col];
            float2 o0 = {acc[mi][j][0] + bv.x, acc[mi][j][1] + bv.y};
            float2 o1 = {acc[mi][j][2] + bv.x, acc[mi][j][3] + bv.y};
            *(float2*)&C[(size_t)r0 * N + col] = o0;
            *(float2*)&C[(size_t)(r0 + 8) * N + col] = o1;
        }
    }
}

// ------- flash attention: 512 threads, q-tile 256 ------------------------------
// QK: qh·kh (single term)   PV: P·(vh+vl)   ctx out: hi only
#define ARS 72
#define AKV (64 * ARS)
#define ASTG (3 * AKV)          // kh | vh | vl per stage = 27648 B

__global__ void __launch_bounds__(512, 1)
attn_kernel(const __half* __restrict__ qh_, const __half* __restrict__ kh_,
            const __half* __restrict__ vh_, const __half* __restrict__ vl_,
            const __half* __restrict__ biasH, __half* __restrict__ ch_)
{
    extern __shared__ __half smha[];

    const int tid = threadIdx.x, w = tid >> 5, t = tid & 31;
    const int q0 = blockIdx.x * 256, h = blockIdx.y, b = blockIdx.z;
    const size_t qb = (((size_t)b * HHEADS + h) * SSEQ + q0) * 64;
    const size_t kb = (((size_t)b * HHEADS + h) * SSEQ) * 64;
    const size_t bwarp = (((size_t)(blockIdx.x * 16 + w) * 32) * 16 + h) * 1024
                         + (size_t)t * 32;

    // ---- stage Q (hi only), consume to registers ------------------------------
#pragma unroll
    for (int it = 0; it < 4; ++it) {
        int idx = tid + it * 512;
        int r = idx >> 3, c8 = (idx & 7) * 8;
        *(uint4*)(smha + r * ARS + c8) = *(const uint4*)&qh_[qb + (size_t)r * 64 + c8];
    }
    __syncthreads();
    unsigned qf[4][4];
    const int ar = t & 15, co = (t >> 4) << 3;
#pragma unroll
    for (int ki = 0; ki < 4; ++ki)
        ldsm4(qf[ki], smha + (w * 16 + ar) * ARS + ki * 16 + co);
    __syncthreads();

    auto load_kv = [&](int s, int kt) {
        __half* p = smha + s * ASTG;
#pragma unroll
        for (int it = 0; it < 3; ++it) {
            int idx = tid + it * 512;       // 1536 = 3 arrays x 64 rows x 8 c8
            int arr = idx >> 9;
            int r = (idx >> 3) & 63, c8 = (idx & 7) * 8;
            const __half* src = (arr == 0) ? kh_ : (arr == 1) ? vh_ : vl_;
            cp16p(p + arr * AKV + r * ARS + c8,
                  src + kb + (size_t)(kt + r) * 64 + c8);
        }
        cp_commit();
    };

    load_kv(0, 0);

    float m0v = -1e30f, m1v = -1e30f, l0 = 0.f, l1 = 0.f;
    float oc[8][4];
#pragma unroll
    for (int j = 0; j < 8; ++j)
#pragma unroll
        for (int c = 0; c < 4; ++c) oc[j][c] = 0.f;

    const int qr = t >> 2, qc = (t & 3) * 2;

    const int ntiles = SSEQ / 64;
    for (int ti = 0; ti < ntiles; ++ti) {
        int s = ti & 1;

        const uint4* bp = (const uint4*)(biasH + bwarp + (size_t)ti * 16 * 1024);
        uint4 u0 = bp[0], u1 = bp[1], u2 = bp[2], u3 = bp[3];

        if (ti + 1 < ntiles) { load_kv(s ^ 1, (ti + 1) * 64); cp_wait1(); }
        else                 { cp_wait0(); }
        __syncthreads();

        __half* pKh = smha + s * ASTG;
        __half* pVh = pKh + AKV;
        __half* pVl = pKh + 2 * AKV;

        float sc[8][4];
#pragma unroll
        for (int j = 0; j < 8; ++j)
#pragma unroll
            for (int c = 0; c < 4; ++c) sc[j][c] = 0.f;
#pragma unroll
        for (int ki = 0; ki < 4; ++ki) {
#pragma unroll
            for (int ni = 0; ni < 4; ++ni) {
                unsigned bh[4];
                ldsm4(bh, pKh + (ni * 16 + ar) * ARS + ki * 16 + co);
                mma16816(sc[2 * ni],     qf[ki], bh[0], bh[2]);
                mma16816(sc[2 * ni + 1], qf[ki], bh[1], bh[3]);
            }
        }
        {
            unsigned braw0[8] = {u0.x, u0.y, u0.z, u0.w, u1.x, u1.y, u1.z, u1.w};
            unsigned braw1[8] = {u2.x, u2.y, u2.z, u2.w, u3.x, u3.y, u3.z, u3.w};
#pragma unroll
            for (int j = 0; j < 8; ++j) {
                float2 f0 = __half22float2(*(__half2*)&braw0[j]);
                float2 f1 = __half22float2(*(__half2*)&braw1[j]);
                sc[j][0] += f0.x; sc[j][1] += f0.y; sc[j][2] += f1.x; sc[j][3] += f1.y;
            }
        }

        float mx0 = -1e30f, mx1 = -1e30f;
#pragma unroll
        for (int j = 0; j < 8; ++j) {
            mx0 = fmaxf(mx0, fmaxf(sc[j][0], sc[j][1]));
            mx1 = fmaxf(mx1, fmaxf(sc[j][2], sc[j][3]));
        }
        mx0 = fmaxf(mx0, __shfl_xor_sync(0xffffffffu, mx0, 1));
        mx0 = fmaxf(mx0, __shfl_xor_sync(0xffffffffu, mx0, 2));
        mx1 = fmaxf(mx1, __shfl_xor_sync(0xffffffffu, mx1, 1));
        mx1 = fmaxf(mx1, __shfl_xor_sync(0xffffffffu, mx1, 2));
        float mn0 = fmaxf(m0v, mx0), mn1 = fmaxf(m1v, mx1);
        float a0 = exp2f(m0v - mn0), a1 = exp2f(m1v - mn1);
        m0v = mn0; m1v = mn1;

        float rs0 = 0.f, rs1 = 0.f;
        unsigned pa[4][4];
#pragma unroll
        for (int i = 0; i < 4; ++i) {
            int j0 = 2 * i, j1 = 2 * i + 1;
            float p0 = exp2f(sc[j0][0] - mn0), p1 = exp2f(sc[j0][1] - mn0);
            float p2 = exp2f(sc[j0][2] - mn1), p3 = exp2f(sc[j0][3] - mn1);
            float u0e = exp2f(sc[j1][0] - mn0), u1e = exp2f(sc[j1][1] - mn0);
            float u2e = exp2f(sc[j1][2] - mn1), u3e = exp2f(sc[j1][3] - mn1);
            rs0 += (p0 + p1) + (u0e + u1e);
            rs1 += (p2 + p3) + (u2e + u3e);
            pa[i][0] = packh2(p0, p1); pa[i][1] = packh2(p2, p3);
            pa[i][2] = packh2(u0e, u1e); pa[i][3] = packh2(u2e, u3e);
        }
        rs0 += __shfl_xor_sync(0xffffffffu, rs0, 1);
        rs0 += __shfl_xor_sync(0xffffffffu, rs0, 2);
        rs1 += __shfl_xor_sync(0xffffffffu, rs1, 1);
        rs1 += __shfl_xor_sync(0xffffffffu, rs1, 2);
        l0 = l0 * a0 + rs0;
        l1 = l1 * a1 + rs1;
#pragma unroll
        for (int j = 0; j < 8; ++j) {
            oc[j][0] *= a0; oc[j][1] *= a0; oc[j][2] *= a1; oc[j][3] *= a1;
        }
        {
            int sr0 = ((t >> 4) & 1) * 8 + (t & 7);
            int hco = ((t >> 3) & 1) * 8;
#pragma unroll
            for (int i = 0; i < 4; ++i) {
                int sr = i * 16 + sr0;
#pragma unroll
                for (int ni = 0; ni < 4; ++ni) {
                    unsigned v4h[4], v4l[4];
                    ldsm4t(v4h, pVh + sr * ARS + ni * 16 + hco);
                    ldsm4t(v4l, pVl + sr * ARS + ni * 16 + hco);
                    mma16816(oc[2 * ni],     pa[i], v4h[0], v4h[2]);
                    mma16816(oc[2 * ni + 1], pa[i], v4h[1], v4h[3]);
                    mma16816(oc[2 * ni],     pa[i], v4l[0], v4l[2]);
                    mma16816(oc[2 * ni + 1], pa[i], v4l[1], v4l[3]);
                }
            }
        }
        __syncthreads();
    }

    float inv0 = 1.f / l0, inv1 = 1.f / l1;
    int r0 = q0 + w * 16 + qr;
    size_t ob0 = (((size_t)b * SSEQ + r0) * HHEADS + h) * 64;
    size_t ob1 = (((size_t)b * SSEQ + r0 + 8) * HHEADS + h) * 64;
#pragma unroll
    for (int j = 0; j < 8; ++j) {
        int col = j * 8 + qc;
        *(__half2*)(ch_ + ob0 + col) =
            __floats2half2_rn(oc[j][0] * inv0, oc[j][1] * inv0);
        *(__half2*)(ch_ + ob1 + col) =
            __floats2half2_rn(oc[j][2] * inv1, oc[j][3] * inv1);
    }
}

// ------------------------------- launcher --------------------------------------
extern "C" void kernel_launch(void* const* d_in, const int* in_sizes, int n_in,
                              void* d_out, int out_size)
{
    (void)in_sizes; (void)n_in; (void)out_size;
    const float* x   = (const float*)d_in[0];
    const float* Qb  = (const float*)d_in[1];
    const float* Wq  = (const float*)d_in[2];
    const float* bq  = (const float*)d_in[3];
    const float* Wk  = (const float*)d_in[4];
    const float* bk  = (const float*)d_in[5];
    const float* Wv  = (const float*)d_in[6];
    const float* bv  = (const float*)d_in[7];
    const float* qs  = (const float*)d_in[8];
    const float* ks  = (const float*)d_in[9];
    const float* rel = (const float*)d_in[10];
    const float* Wo  = (const float*)d_in[11];
    const float* bo  = (const float*)d_in[12];
    float* out = (float*)d_out;

    __half *xh, *wth, *wtl, *qh, *kh, *vh, *vl, *bH, *ch;
    cudaGetSymbolAddress((void**)&xh,  g_xh);
    cudaGetSymbolAddress((void**)&wth, g_wth);
    cudaGetSymbolAddress((void**)&wtl, g_wtl);
    cudaGetSymbolAddress((void**)&qh,  g_qh);
    cudaGetSymbolAddress((void**)&kh,  g_kh);
    cudaGetSymbolAddress((void**)&vh,  g_vh);
    cudaGetSymbolAddress((void**)&vl,  g_vl);
    cudaGetSymbolAddress((void**)&bH,  g_biasH);
    cudaGetSymbolAddress((void**)&ch,  g_ch);

    const int MM = 1024 * 1024;
    const int GS = 2 * GSTG3 * (int)sizeof(__half);  // 61440 B
    const int AS = 2 * ASTG * (int)sizeof(__half);   // 55296 B
    cudaFuncSetAttribute(qkv_bias_kernel,
                         cudaFuncAttributeMaxDynamicSharedMemorySize, GS);
    cudaFuncSetAttribute(gemm3_kernel,
                         cudaFuncAttributeMaxDynamicSharedMemorySize, GS);
    cudaFuncSetAttribute(attn_kernel,
                         cudaFuncAttributeMaxDynamicSharedMemorySize, AS);

    // prep
    tohalf_kernel<<<(MROWS * DDIM / 4 + 255) / 256, 256>>>(x, xh, MROWS * DDIM / 4);
    dim3 tb(32, 8), tg(32, 32, 4);
    transpose_split_kernel<<<tg, tb>>>(Wq, Wk, Wv, Wo, wth, wtl);

    // fused QKV GEMM + bias-table launch
    qkv_bias_kernel<<<QKV_BLOCKS + BIAS_BLOCKS, 256, GS>>>(
        xh, wth, wtl, bq, bk, bv, qs, ks,
        qh, kh, vh, vl, Qb, rel, bH);

    // attention
    attn_kernel<<<dim3(SSEQ / 256, HHEADS, BBATCH), 512, AS>>>(qh, kh,
                                                               vh, vl, bH, ch);

    // output projection
    dim3 gg(DDIM / 128, MROWS / 128);
    gemm3_kernel<<<gg, 256, GS>>>(ch, wth + 3 * MM, wtl + 3 * MM, bo, out,
                                  MROWS, DDIM, DDIM);
}